// round 7
// baseline (speedup 1.0000x reference)
#include <cuda_runtime.h>
#include <cuda_bf16.h>
#include <math.h>
#include <stddef.h>
#include <stdint.h>

// Problem constants
#define NHEAD 16
#define HDIM  64
#define SEQ   2048
#define BATCH 2
#define EMB   1024
#define MTOT  (BATCH * SEQ)   // 4096
#define HSZ   (BATCH * NHEAD * SEQ * HDIM)   // 4194304

// Scratch (device globals: allocation-free, graph-capturable)
__device__ float g_qkv[3 * HSZ];
__device__ __nv_bfloat16 g_xh[MTOT * EMB], g_xl[MTOT * EMB];
__device__ __nv_bfloat16 g_wh[4 * EMB * EMB], g_wl[4 * EMB * EMB];
__device__ __nv_bfloat16 g_oh[MTOT * EMB], g_ol[MTOT * EMB];

// ===========================================================================
// mma.sync helpers (arch-portable tensor core path; works at compute_103)
// ===========================================================================
__device__ __forceinline__ void mma_bf16(float* d, const uint32_t* a, const uint32_t* b) {
    asm volatile(
        "mma.sync.aligned.m16n8k16.row.col.f32.bf16.bf16.f32 "
        "{%0,%1,%2,%3}, {%4,%5,%6,%7}, {%8,%9}, {%0,%1,%2,%3};"
        : "+f"(d[0]), "+f"(d[1]), "+f"(d[2]), "+f"(d[3])
        : "r"(a[0]), "r"(a[1]), "r"(a[2]), "r"(a[3]), "r"(b[0]), "r"(b[1]));
}

__device__ __forceinline__ void ldsm4(uint32_t* r, uint32_t addr) {
    asm volatile("ldmatrix.sync.aligned.m8n8.x4.shared.b16 {%0,%1,%2,%3}, [%4];"
        : "=r"(r[0]), "=r"(r[1]), "=r"(r[2]), "=r"(r[3]) : "r"(addr));
}

__device__ __forceinline__ void ldsm4t(uint32_t* r, uint32_t addr) {
    asm volatile("ldmatrix.sync.aligned.m8n8.x4.trans.shared.b16 {%0,%1,%2,%3}, [%4];"
        : "=r"(r[0]), "=r"(r[1]), "=r"(r[2]), "=r"(r[3]) : "r"(addr));
}

__device__ __forceinline__ uint32_t smem_u32(const void* p) {
    uint32_t a;
    asm("{ .reg .u64 t; cvta.to.shared.u64 t, %1; cvt.u32.u64 %0, t; }"
        : "=r"(a) : "l"(p));
    return a;
}

// hi/lo bf16 split of 2 floats (packed into u32 each)
__device__ __forceinline__ void split2(float x, float y, uint32_t& hi, uint32_t& lo) {
    __nv_bfloat162 h = __floats2bfloat162_rn(x, y);
    float hx = __bfloat162float(h.x), hy = __bfloat162float(h.y);
    __nv_bfloat162 l = __floats2bfloat162_rn(x - hx, y - hy);
    hi = *(uint32_t*)&h;
    lo = *(uint32_t*)&l;
}

// ===========================================================================
// Pre-split: f32 array -> bf16 hi/lo arrays
// ===========================================================================
__global__ __launch_bounds__(256) void split_kernel(
    const float* __restrict__ in, __nv_bfloat16* __restrict__ hi,
    __nv_bfloat16* __restrict__ lo, int n4)
{
    const int i = blockIdx.x * blockDim.x + threadIdx.x;
    if (i < n4) {
        const float4 v = *(const float4*)(in + (size_t)i * 4);
        uint32_t h0, l0, h1, l1;
        split2(v.x, v.y, h0, l0);
        split2(v.z, v.w, h1, l1);
        *(uint2*)(hi + (size_t)i * 4) = make_uint2(h0, h1);
        *(uint2*)(lo + (size_t)i * 4) = make_uint2(l0, l1);
    }
}

// ===========================================================================
// Tensor-core GEMM v3 (pre-split operands, double-buffered smem):
// C[M,N] = (Ah+Al)[M,K] @ (Bh+Bl)[N,K]^T + bias, 3-term split.
// CTA 128x128, BK=32, 8 warps (4x2). One __syncthreads per chunk; STS of
// chunk k+1 overlaps HMMA of chunk k. 80B row stride (16B-aligned,
// conflict-free LDSM). mode=1: N spans QKV (3072), scatter to g_qkv thirds.
// ===========================================================================
#define GBK 32
#define SROWB 80
#define SROWW (SROWB / 4)
#define TILE_U32 (128 * SROWW)    // 2560 words (10240 B)
#define BUF_U32 (4 * TILE_U32)    // one chunk's 4 tiles (40960 B)
#define GEMM_SMEM_B (2 * BUF_U32 * 4)   // 81920 B

#define NCH (EMB / GBK)           // 32

__global__ __launch_bounds__(256, 1) void gemm_tc3(
    const __nv_bfloat16* __restrict__ Ahg, const __nv_bfloat16* __restrict__ Alg,
    const __nv_bfloat16* __restrict__ Bhg, const __nv_bfloat16* __restrict__ Blg,
    const float* __restrict__ b0, const float* __restrict__ b1,
    const float* __restrict__ b2,
    float* __restrict__ C, float* __restrict__ QKV, int mode)
{
    extern __shared__ uint32_t sh[];

    const int tid = threadIdx.x;
    const int lane = tid & 31;
    const int wid = tid >> 5;
    const int wm = wid & 3;
    const int wn = wid >> 2;
    const int m0 = blockIdx.y * 128;
    const int n0 = blockIdx.x * 128;

    // gmem staging: per buffer, thread copies 2x 16B (8 bf16) chunks
    const int lrow = tid >> 2;          // 0..63 (and +64)
    const int c16 = tid & 3;            // 16B chunk within row

    const int mat = lane >> 3, lr8 = lane & 7;
    const uint32_t sbase = smem_u32(sh);
    const uint32_t a_off = (uint32_t)((wm * 32 + (mat & 1) * 8 + lr8) * SROWB + (mat >> 1) * 16);
    const uint32_t b_off = (uint32_t)((wn * 64 + (mat >> 1) * 8 + lr8) * SROWB + (mat & 1) * 16);

    float acc[2][8][4];
#pragma unroll
    for (int mf = 0; mf < 2; mf++)
#pragma unroll
        for (int nf = 0; nf < 8; nf++)
#pragma unroll
            for (int e = 0; e < 4; e++) acc[mf][nf][e] = 0.f;

    const __nv_bfloat16* Ahp = Ahg + (size_t)m0 * EMB;
    const __nv_bfloat16* Alp = Alg + (size_t)m0 * EMB;
    const __nv_bfloat16* Bhp = Bhg + (size_t)n0 * EMB;
    const __nv_bfloat16* Blp = Blg + (size_t)n0 * EMB;

    uint4 ahr[2], alr[2], bhr[2], blr[2];

    // load chunk 0, store into buf 0
#pragma unroll
    for (int it = 0; it < 2; it++) {
        const size_t g = (size_t)(lrow + it * 64) * EMB + c16 * 8;
        ahr[it] = *(const uint4*)(Ahp + g);
        alr[it] = *(const uint4*)(Alp + g);
        bhr[it] = *(const uint4*)(Bhp + g);
        blr[it] = *(const uint4*)(Blp + g);
    }
#pragma unroll
    for (int it = 0; it < 2; it++) {
        const int w0 = (lrow + it * 64) * SROWW + c16 * 4;
        *(uint4*)(sh + w0) = ahr[it];
        *(uint4*)(sh + TILE_U32 + w0) = alr[it];
        *(uint4*)(sh + 2 * TILE_U32 + w0) = bhr[it];
        *(uint4*)(sh + 3 * TILE_U32 + w0) = blr[it];
    }
    // prefetch chunk 1 into regs
#pragma unroll
    for (int it = 0; it < 2; it++) {
        const size_t g = (size_t)(lrow + it * 64) * EMB + GBK + c16 * 8;
        ahr[it] = *(const uint4*)(Ahp + g);
        alr[it] = *(const uint4*)(Alp + g);
        bhr[it] = *(const uint4*)(Bhp + g);
        blr[it] = *(const uint4*)(Blp + g);
    }
    __syncthreads();

    for (int kk = 0; kk < NCH; kk++) {
        const uint32_t bufw = (uint32_t)((kk & 1) * BUF_U32);
        const uint32_t nbufw = (uint32_t)(((kk + 1) & 1) * BUF_U32);

        // store chunk kk+1 into the other buffer (overlaps MMA below)
        if (kk + 1 < NCH) {
#pragma unroll
            for (int it = 0; it < 2; it++) {
                const int w0 = (lrow + it * 64) * SROWW + c16 * 4;
                *(uint4*)(sh + nbufw + w0) = ahr[it];
                *(uint4*)(sh + nbufw + TILE_U32 + w0) = alr[it];
                *(uint4*)(sh + nbufw + 2 * TILE_U32 + w0) = bhr[it];
                *(uint4*)(sh + nbufw + 3 * TILE_U32 + w0) = blr[it];
            }
        }
        // prefetch chunk kk+2 (long-latency LDG hidden under MMA)
        if (kk + 2 < NCH) {
            const int kcol = (kk + 2) * GBK + c16 * 8;
#pragma unroll
            for (int it = 0; it < 2; it++) {
                const size_t g = (size_t)(lrow + it * 64) * EMB + kcol;
                ahr[it] = *(const uint4*)(Ahp + g);
                alr[it] = *(const uint4*)(Alp + g);
                bhr[it] = *(const uint4*)(Bhp + g);
                blr[it] = *(const uint4*)(Blp + g);
            }
        }

        const uint32_t sAh = sbase + bufw * 4 + a_off;
        const uint32_t sAl = sAh + TILE_U32 * 4;
        const uint32_t sBh = sbase + bufw * 4 + 2 * TILE_U32 * 4 + b_off;
        const uint32_t sBl = sBh + TILE_U32 * 4;

#pragma unroll
        for (int ks = 0; ks < 2; ks++) {
            const uint32_t kadd = ks * 32;
            uint32_t ah[2][4], al[2][4], bh[4][4], bl[4][4];
#pragma unroll
            for (int mf = 0; mf < 2; mf++) {
                ldsm4(ah[mf], sAh + mf * 16 * SROWB + kadd);
                ldsm4(al[mf], sAl + mf * 16 * SROWB + kadd);
            }
#pragma unroll
            for (int np = 0; np < 4; np++) {
                ldsm4(bh[np], sBh + np * 16 * SROWB + kadd);
                ldsm4(bl[np], sBl + np * 16 * SROWB + kadd);
            }
#pragma unroll
            for (int mf = 0; mf < 2; mf++)
#pragma unroll
                for (int nf = 0; nf < 8; nf++) {
                    const int np = nf >> 1;
                    uint32_t* bhp = &bh[np][(nf & 1) * 2];
                    uint32_t* blp = &bl[np][(nf & 1) * 2];
                    mma_bf16(acc[mf][nf], ah[mf], bhp);
                    mma_bf16(acc[mf][nf], ah[mf], blp);
                    mma_bf16(acc[mf][nf], al[mf], bhp);
                }
        }
        __syncthreads();
    }

    // Epilogue
    const int third = n0 >> 10;                      // 0/1/2 (mode 1)
    const float* bp = (third == 0) ? b0 : (third == 1) ? b1 : b2;
    float* Cq = QKV + (size_t)third * HSZ;

#pragma unroll
    for (int mf = 0; mf < 2; mf++) {
#pragma unroll
        for (int half = 0; half < 2; half++) {
            const int m = m0 + wm * 32 + mf * 16 + (lane >> 2) + half * 8;
            const int b = m >> 11;
            const int s = m & (SEQ - 1);
#pragma unroll
            for (int nf = 0; nf < 8; nf++) {
                const int n = n0 + wn * 64 + nf * 8 + ((lane & 3) << 1);
                const int nn = n & (EMB - 1);
                float2 v;
                v.x = acc[mf][nf][half * 2 + 0] + bp[nn];
                v.y = acc[mf][nf][half * 2 + 1] + bp[nn + 1];
                if (mode) {
                    const int h = nn >> 6;
                    const int d = nn & 63;
                    *(float2*)(Cq + (((size_t)(b * NHEAD + h)) * SEQ + s) * HDIM + d) = v;
                } else {
                    *(float2*)(C + (size_t)m * EMB + n) = v;
                }
            }
        }
    }
}

// ===========================================================================
// Tensor-core causal flash attention (unchanged from round 6 passing version)
// ===========================================================================
#define QT 128
#define KT 64
#define AROWW 36            // u32 words per smem row (144 B)
#define ABUF (64 * AROWW)   // words per 64-row buffer

__global__ __launch_bounds__(256) void attn_tc(
    const float* __restrict__ Q, const float* __restrict__ K,
    const float* __restrict__ V,
    __nv_bfloat16* __restrict__ Oh, __nv_bfloat16* __restrict__ Ol)
{
    __shared__ uint32_t sm[4 * ABUF];   // 36864 B
    const int tid = threadIdx.x;
    const int lane = tid & 31;
    const int wid = tid >> 5;
    const int lr8 = lane & 7;
    const int mat = lane >> 3;
    const int qb = blockIdx.x;
    const int bh = blockIdx.y;

    const uint32_t sbase = smem_u32(sm);

    const float* Qg = Q + ((size_t)bh * SEQ + (size_t)qb * QT) * HDIM;
    const float* Kg = K + (size_t)bh * SEQ * HDIM;
    const float* Vg = V + (size_t)bh * SEQ * HDIM;

    const int r16 = tid >> 4;
    const int c4f = (tid & 15) << 2;
    const int kw  = (tid & 15) << 1;

#pragma unroll
    for (int u = 0; u < 8; u++) {
        const int row = r16 + u * 16;
        const float4 q = *(const float4*)(Qg + (size_t)row * HDIM + c4f);
        uint32_t h0, l0, h1, l1;
        split2(q.x * 0.125f, q.y * 0.125f, h0, l0);
        split2(q.z * 0.125f, q.w * 0.125f, h1, l1);
        const int w = row * AROWW + kw;
        *(uint2*)(sm + w) = make_uint2(h0, h1);
        *(uint2*)(sm + 2 * ABUF + w) = make_uint2(l0, l1);
    }
    __syncthreads();

    uint32_t qh[4][4], ql[4][4];
    {
        const uint32_t qa = sbase +
            (uint32_t)((wid * 16 + (mat & 1) * 8 + lr8) * 144 + (mat >> 1) * 16);
#pragma unroll
        for (int ks = 0; ks < 4; ks++) {
            ldsm4(qh[ks], qa + ks * 32);
            ldsm4(ql[ks], qa + 2 * ABUF * 4 + ks * 32);
        }
    }

    float oacc[8][4];
#pragma unroll
    for (int nf = 0; nf < 8; nf++)
#pragma unroll
        for (int e = 0; e < 4; e++) oacc[nf][e] = 0.f;
    float m0r = -INFINITY, m1r = -INFINITY, l0r = 0.f, l1r = 0.f;

    const int jbmax = 2 * qb + 1;
    const int qrow0 = qb * QT + wid * 16 + (lane >> 2);

    float4 kreg[4];
#pragma unroll
    for (int u = 0; u < 4; u++)
        kreg[u] = *(const float4*)(Kg + (size_t)(r16 + u * 16) * HDIM + c4f);

    for (int jb = 0; jb <= jbmax; jb++) {
        __syncthreads();
#pragma unroll
        for (int u = 0; u < 4; u++) {
            uint32_t h0, l0, h1, l1;
            split2(kreg[u].x, kreg[u].y, h0, l0);
            split2(kreg[u].z, kreg[u].w, h1, l1);
            const int w = (r16 + u * 16) * AROWW + kw;
            *(uint2*)(sm + w) = make_uint2(h0, h1);
            *(uint2*)(sm + ABUF + w) = make_uint2(l0, l1);
        }
        __syncthreads();

        float4 vreg[4];
        {
            const float* Vt = Vg + (size_t)jb * KT * HDIM;
#pragma unroll
            for (int u = 0; u < 4; u++)
                vreg[u] = *(const float4*)(Vt + (size_t)(r16 + u * 16) * HDIM + c4f);
        }

        float sacc[8][4];
#pragma unroll
        for (int nf = 0; nf < 8; nf++)
#pragma unroll
            for (int e = 0; e < 4; e++) sacc[nf][e] = 0.f;

#pragma unroll
        for (int ks = 0; ks < 4; ks++) {
#pragma unroll
            for (int np = 0; np < 4; np++) {
                uint32_t kh[4], kl[4];
                const uint32_t ka = sbase +
                    (uint32_t)((np * 16 + (mat >> 1) * 8 + lr8) * 144 + ks * 32 + (mat & 1) * 16);
                ldsm4(kh, ka);
                ldsm4(kl, ka + ABUF * 4);
#pragma unroll
                for (int hh = 0; hh < 2; hh++) {
                    float* d = sacc[np * 2 + hh];
                    mma_bf16(d, qh[ks], &kh[hh * 2]);
                    mma_bf16(d, qh[ks], &kl[hh * 2]);
                    mma_bf16(d, ql[ks], &kh[hh * 2]);
                }
            }
        }

#pragma unroll
        for (int u = 0; u < 4; u++) {
            uint32_t h0, l0, h1, l1;
            split2(vreg[u].x, vreg[u].y, h0, l0);
            split2(vreg[u].z, vreg[u].w, h1, l1);
            const int w = (r16 + u * 16) * AROWW + kw;
            *(uint2*)(sm + 2 * ABUF + w) = make_uint2(h0, h1);
            *(uint2*)(sm + 3 * ABUF + w) = make_uint2(l0, l1);
        }
        __syncthreads();

        if (jb < jbmax) {
            const float* Kt = Kg + (size_t)(jb + 1) * KT * HDIM;
#pragma unroll
            for (int u = 0; u < 4; u++)
                kreg[u] = *(const float4*)(Kt + (size_t)(r16 + u * 16) * HDIM + c4f);
        }

        if (jb * KT + KT - 1 > qrow0) {
#pragma unroll
            for (int nt = 0; nt < 8; nt++) {
                const int c = jb * KT + nt * 8 + ((lane & 3) << 1);
                if (c     > qrow0)     sacc[nt][0] = -INFINITY;
                if (c + 1 > qrow0)     sacc[nt][1] = -INFINITY;
                if (c     > qrow0 + 8) sacc[nt][2] = -INFINITY;
                if (c + 1 > qrow0 + 8) sacc[nt][3] = -INFINITY;
            }
        }

        float mx0 = sacc[0][0], mx1 = sacc[0][2];
#pragma unroll
        for (int nt = 0; nt < 8; nt++) {
            mx0 = fmaxf(mx0, fmaxf(sacc[nt][0], sacc[nt][1]));
            mx1 = fmaxf(mx1, fmaxf(sacc[nt][2], sacc[nt][3]));
        }
        mx0 = fmaxf(mx0, __shfl_xor_sync(~0u, mx0, 1));
        mx0 = fmaxf(mx0, __shfl_xor_sync(~0u, mx0, 2));
        mx1 = fmaxf(mx1, __shfl_xor_sync(~0u, mx1, 1));
        mx1 = fmaxf(mx1, __shfl_xor_sync(~0u, mx1, 2));
        const float mn0 = fmaxf(m0r, mx0), mn1 = fmaxf(m1r, mx1);
        const float cr0 = __expf(m0r - mn0), cr1 = __expf(m1r - mn1);
        m0r = mn0; m1r = mn1;
        float rs0 = 0.f, rs1 = 0.f;
#pragma unroll
        for (int nt = 0; nt < 8; nt++) {
            sacc[nt][0] = __expf(sacc[nt][0] - mn0);
            sacc[nt][1] = __expf(sacc[nt][1] - mn0);
            sacc[nt][2] = __expf(sacc[nt][2] - mn1);
            sacc[nt][3] = __expf(sacc[nt][3] - mn1);
            rs0 += sacc[nt][0] + sacc[nt][1];
            rs1 += sacc[nt][2] + sacc[nt][3];
        }
        rs0 += __shfl_xor_sync(~0u, rs0, 1);
        rs0 += __shfl_xor_sync(~0u, rs0, 2);
        rs1 += __shfl_xor_sync(~0u, rs1, 1);
        rs1 += __shfl_xor_sync(~0u, rs1, 2);
        l0r = l0r * cr0 + rs0;
        l1r = l1r * cr1 + rs1;
#pragma unroll
        for (int nf = 0; nf < 8; nf++) {
            oacc[nf][0] *= cr0; oacc[nf][1] *= cr0;
            oacc[nf][2] *= cr1; oacc[nf][3] *= cr1;
        }

#pragma unroll
        for (int ks = 0; ks < 4; ks++) {
            uint32_t ph[4], pl[4];
            split2(sacc[2 * ks][0],     sacc[2 * ks][1],     ph[0], pl[0]);
            split2(sacc[2 * ks][2],     sacc[2 * ks][3],     ph[1], pl[1]);
            split2(sacc[2 * ks + 1][0], sacc[2 * ks + 1][1], ph[2], pl[2]);
            split2(sacc[2 * ks + 1][2], sacc[2 * ks + 1][3], ph[3], pl[3]);
#pragma unroll
            for (int np = 0; np < 4; np++) {
                uint32_t vh[4], vl[4];
                const uint32_t va = sbase + (uint32_t)(2 * ABUF * 4) +
                    (uint32_t)((ks * 16 + (mat & 1) * 8 + lr8) * 144 + np * 32 + (mat >> 1) * 16);
                ldsm4t(vh, va);
                ldsm4t(vl, va + ABUF * 4);
#pragma unroll
                for (int hh = 0; hh < 2; hh++) {
                    float* d = oacc[np * 2 + hh];
                    mma_bf16(d, ph, &vh[hh * 2]);
                    mma_bf16(d, ph, &vl[hh * 2]);
                    mma_bf16(d, pl, &vh[hh * 2]);
                }
            }
        }
    }

    const int b = bh >> 4, h = bh & 15;
    const float inv0 = 1.f / l0r, inv1 = 1.f / l1r;
#pragma unroll
    for (int nt = 0; nt < 8; nt++) {
        const int col = h * HDIM + nt * 8 + ((lane & 3) << 1);
        const size_t o0 = ((size_t)(b * SEQ) + qrow0) * EMB + col;
        const size_t o1 = ((size_t)(b * SEQ) + qrow0 + 8) * EMB + col;
        uint32_t h0, l0;
        split2(oacc[nt][0] * inv0, oacc[nt][1] * inv0, h0, l0);
        *(uint32_t*)(Oh + o0) = h0;
        *(uint32_t*)(Ol + o0) = l0;
        split2(oacc[nt][2] * inv1, oacc[nt][3] * inv1, h0, l0);
        *(uint32_t*)(Oh + o1) = h0;
        *(uint32_t*)(Ol + o1) = l0;
    }
}

// ---------------------------------------------------------------------------
extern "C" void kernel_launch(void* const* d_in, const int* in_sizes, int n_in,
                              void* d_out, int out_size)
{
    (void)in_sizes; (void)n_in; (void)out_size;
    const float* x  = (const float*)d_in[0];
    // d_in[1] = mask (causal tril, implied — unused)
    const float* Wq = (const float*)d_in[2];
    const float* bq = (const float*)d_in[3];
    const float* Wk = (const float*)d_in[4];
    const float* bk = (const float*)d_in[5];
    const float* Wv = (const float*)d_in[6];
    const float* bv = (const float*)d_in[7];
    const float* Wo = (const float*)d_in[8];
    const float* bo = (const float*)d_in[9];
    float* out = (float*)d_out;

    float *qkv;
    __nv_bfloat16 *xh, *xl, *wh, *wl, *oh, *ol;
    cudaGetSymbolAddress((void**)&qkv, g_qkv);
    cudaGetSymbolAddress((void**)&xh, g_xh);
    cudaGetSymbolAddress((void**)&xl, g_xl);
    cudaGetSymbolAddress((void**)&wh, g_wh);
    cudaGetSymbolAddress((void**)&wl, g_wl);
    cudaGetSymbolAddress((void**)&oh, g_oh);
    cudaGetSymbolAddress((void**)&ol, g_ol);

    cudaFuncSetAttribute(gemm_tc3, cudaFuncAttributeMaxDynamicSharedMemorySize,
                         GEMM_SMEM_B);

    const int WN = EMB * EMB;

    // Pre-split activations and weights into bf16 hi/lo
    split_kernel<<<(MTOT * EMB / 4) / 256, 256>>>(x, xh, xl, MTOT * EMB / 4);
    split_kernel<<<(WN / 4) / 256, 256>>>(Wq, wh + 0 * WN, wl + 0 * WN, WN / 4);
    split_kernel<<<(WN / 4) / 256, 256>>>(Wk, wh + 1 * WN, wl + 1 * WN, WN / 4);
    split_kernel<<<(WN / 4) / 256, 256>>>(Wv, wh + 2 * WN, wl + 2 * WN, WN / 4);
    split_kernel<<<(WN / 4) / 256, 256>>>(Wo, wh + 3 * WN, wl + 3 * WN, WN / 4);

    // Fused QKV projection: C = x @ [Wq;Wk;Wv]^T, N=3072, scatter into g_qkv
    const dim3 qkv_grid(3 * EMB / 128, MTOT / 128);  // (24, 32)
    gemm_tc3<<<qkv_grid, 256, GEMM_SMEM_B>>>(
        xh, xl, wh, wl, bq, bk, bv, nullptr, qkv, 1);

    const dim3 attn_grid(SEQ / QT, BATCH * NHEAD);  // (16, 32)
    attn_tc<<<attn_grid, 256>>>(qkv, qkv + HSZ, qkv + 2 * HSZ, oh, ol);

    // Output projection
    const dim3 out_grid(EMB / 128, MTOT / 128);  // (8, 32)
    gemm_tc3<<<out_grid, 256, GEMM_SMEM_B>>>(
        oh, ol, wh + 3 * WN, wl + 3 * WN, bo, nullptr, nullptr, out, nullptr, 0);
}

// round 8
// speedup vs baseline: 1.0882x; 1.0882x over previous
#include <cuda_runtime.h>
#include <cuda_bf16.h>
#include <math.h>
#include <stddef.h>
#include <stdint.h>

// Problem constants
#define NHEAD 16
#define HDIM  64
#define SEQ   2048
#define BATCH 2
#define EMB   1024
#define MTOT  (BATCH * SEQ)   // 4096

// Scratch (device globals: allocation-free, graph-capturable)
__device__ float g_q[BATCH * NHEAD * SEQ * HDIM];
__device__ float g_k[BATCH * NHEAD * SEQ * HDIM];
__device__ float g_v[BATCH * NHEAD * SEQ * HDIM];
__device__ float g_o[MTOT * EMB];

// ===========================================================================
// mma.sync helpers (arch-portable tensor core path; works at compute_103)
// ===========================================================================
__device__ __forceinline__ void mma_bf16(float* d, const uint32_t* a, const uint32_t* b) {
    asm volatile(
        "mma.sync.aligned.m16n8k16.row.col.f32.bf16.bf16.f32 "
        "{%0,%1,%2,%3}, {%4,%5,%6,%7}, {%8,%9}, {%0,%1,%2,%3};"
        : "+f"(d[0]), "+f"(d[1]), "+f"(d[2]), "+f"(d[3])
        : "r"(a[0]), "r"(a[1]), "r"(a[2]), "r"(a[3]), "r"(b[0]), "r"(b[1]));
}

__device__ __forceinline__ void ldsm4(uint32_t* r, uint32_t addr) {
    asm volatile("ldmatrix.sync.aligned.m8n8.x4.shared.b16 {%0,%1,%2,%3}, [%4];"
        : "=r"(r[0]), "=r"(r[1]), "=r"(r[2]), "=r"(r[3]) : "r"(addr));
}

__device__ __forceinline__ void ldsm4t(uint32_t* r, uint32_t addr) {
    asm volatile("ldmatrix.sync.aligned.m8n8.x4.trans.shared.b16 {%0,%1,%2,%3}, [%4];"
        : "=r"(r[0]), "=r"(r[1]), "=r"(r[2]), "=r"(r[3]) : "r"(addr));
}

__device__ __forceinline__ uint32_t smem_u32(const void* p) {
    uint32_t a;
    asm("{ .reg .u64 t; cvta.to.shared.u64 t, %1; cvt.u32.u64 %0, t; }"
        : "=r"(a) : "l"(p));
    return a;
}

// hi/lo bf16 split of 2 floats (packed into u32 each)
__device__ __forceinline__ void split2(float x, float y, uint32_t& hi, uint32_t& lo) {
    __nv_bfloat162 h = __floats2bfloat162_rn(x, y);
    float hx = __bfloat162float(h.x), hy = __bfloat162float(h.y);
    __nv_bfloat162 l = __floats2bfloat162_rn(x - hx, y - hy);
    hi = *(uint32_t*)&h;
    lo = *(uint32_t*)&l;
}

// ===========================================================================
// Tensor-core GEMM (round-5 version, known-good local optimum):
// C[M,N] = A[M,K] @ W[N,K]^T + bias. CTA 128x128, BK=32, 8 warps (4x2),
// in-loop hi/lo split, 80B smem row stride (16B-aligned, conflict-free LDSM).
// ===========================================================================
#define GBK 32
#define SROWB 80
#define SROWW (SROWB / 4)
#define TILE_U32 (128 * SROWW)

__global__ __launch_bounds__(256, 1) void gemm_tc(
    const float* __restrict__ A, const float* __restrict__ W,
    const float* __restrict__ bias, float* __restrict__ C, int writeQKV)
{
    __shared__ uint32_t sh[4 * TILE_U32];   // 40960 B: Ah, Al, Bh, Bl
    uint32_t* Ah = sh;
    uint32_t* Al = sh + TILE_U32;
    uint32_t* Bh = sh + 2 * TILE_U32;
    uint32_t* Bl = sh + 3 * TILE_U32;

    const int tid = threadIdx.x;
    const int lane = tid & 31;
    const int wid = tid >> 5;
    const int wm = wid & 3;
    const int wn = wid >> 2;
    const int m0 = blockIdx.y * 128;
    const int n0 = blockIdx.x * 128;

    const int grow = tid >> 3;
    const int gc4 = (tid & 7) << 2;
    const int kp = (tid & 7) << 1;

    const int mat = lane >> 3, lr8 = lane & 7;
    const uint32_t sbase = smem_u32(sh);
    const uint32_t a_off = (uint32_t)((wm * 32 + (mat & 1) * 8 + lr8) * SROWB + (mat >> 1) * 16);
    const uint32_t b_off = (uint32_t)((wn * 64 + (mat >> 1) * 8 + lr8) * SROWB + (mat & 1) * 16);

    const uint32_t sAh = sbase + a_off;
    const uint32_t sAl = sAh + TILE_U32 * 4;
    const uint32_t sBh = sbase + 2 * TILE_U32 * 4 + b_off;
    const uint32_t sBl = sBh + TILE_U32 * 4;

    float acc[2][8][4];
#pragma unroll
    for (int mf = 0; mf < 2; mf++)
#pragma unroll
        for (int nf = 0; nf < 8; nf++)
#pragma unroll
            for (int e = 0; e < 4; e++) acc[mf][nf][e] = 0.f;

    const float* Ag = A + (size_t)m0 * EMB;
    const float* Wg = W + (size_t)n0 * EMB;

    float4 avr[4], wvr[4];
#pragma unroll
    for (int u = 0; u < 4; u++) {
        avr[u] = *(const float4*)(Ag + (size_t)(grow + u * 32) * EMB + gc4);
        wvr[u] = *(const float4*)(Wg + (size_t)(grow + u * 32) * EMB + gc4);
    }

    for (int kk = 0; kk < EMB / GBK; kk++) {
        __syncthreads();
#pragma unroll
        for (int u = 0; u < 4; u++) {
            const int row = grow + u * 32;
            const int w0 = row * SROWW + kp;
            uint32_t h0, l0, h1, l1;
            split2(avr[u].x, avr[u].y, h0, l0);
            split2(avr[u].z, avr[u].w, h1, l1);
            *(uint2*)(Ah + w0) = make_uint2(h0, h1);
            *(uint2*)(Al + w0) = make_uint2(l0, l1);
            split2(wvr[u].x, wvr[u].y, h0, l0);
            split2(wvr[u].z, wvr[u].w, h1, l1);
            *(uint2*)(Bh + w0) = make_uint2(h0, h1);
            *(uint2*)(Bl + w0) = make_uint2(l0, l1);
        }
        __syncthreads();

        if (kk + 1 < EMB / GBK) {
            const int kcol = (kk + 1) * GBK + gc4;
#pragma unroll
            for (int u = 0; u < 4; u++) {
                avr[u] = *(const float4*)(Ag + (size_t)(grow + u * 32) * EMB + kcol);
                wvr[u] = *(const float4*)(Wg + (size_t)(grow + u * 32) * EMB + kcol);
            }
        }

#pragma unroll
        for (int ks = 0; ks < 2; ks++) {
            const uint32_t kadd = ks * 32;
            uint32_t ah[2][4], al[2][4], bh[4][4], bl[4][4];
#pragma unroll
            for (int mf = 0; mf < 2; mf++) {
                ldsm4(ah[mf], sAh + mf * 16 * SROWB + kadd);
                ldsm4(al[mf], sAl + mf * 16 * SROWB + kadd);
            }
#pragma unroll
            for (int np = 0; np < 4; np++) {
                ldsm4(bh[np], sBh + np * 16 * SROWB + kadd);
                ldsm4(bl[np], sBl + np * 16 * SROWB + kadd);
            }
#pragma unroll
            for (int mf = 0; mf < 2; mf++)
#pragma unroll
                for (int nf = 0; nf < 8; nf++) {
                    const int np = nf >> 1;
                    uint32_t* bhp = &bh[np][(nf & 1) * 2];
                    uint32_t* blp = &bl[np][(nf & 1) * 2];
                    mma_bf16(acc[mf][nf], ah[mf], bhp);
                    mma_bf16(acc[mf][nf], ah[mf], blp);
                    mma_bf16(acc[mf][nf], al[mf], bhp);
                }
        }
    }

#pragma unroll
    for (int mf = 0; mf < 2; mf++) {
#pragma unroll
        for (int half = 0; half < 2; half++) {
            const int m = m0 + wm * 32 + mf * 16 + (lane >> 2) + half * 8;
            const int b = m >> 11;
            const int s = m & (SEQ - 1);
#pragma unroll
            for (int nf = 0; nf < 8; nf++) {
                const int n = n0 + wn * 64 + nf * 8 + ((lane & 3) << 1);
                float2 v;
                v.x = acc[mf][nf][half * 2 + 0] + bias[n];
                v.y = acc[mf][nf][half * 2 + 1] + bias[n + 1];
                if (writeQKV) {
                    const int h = n >> 6;
                    const int d = n & 63;
                    *(float2*)(C + (((size_t)(b * NHEAD + h)) * SEQ + s) * HDIM + d) = v;
                } else {
                    *(float2*)(C + (size_t)m * EMB + n) = v;
                }
            }
        }
    }
}

// ===========================================================================
// Tensor-core causal flash attention (round-5 core) with longest-first
// scheduling: qb = gridDim.x-1-blockIdx.x so heavy (late-row) tiles launch
// in the first wave, removing the load-imbalance tail.
// ===========================================================================
#define QT 128
#define KT 64
#define AROWW 36            // u32 words per smem row (144 B)
#define ABUF (64 * AROWW)   // words per 64-row buffer

__global__ __launch_bounds__(256) void attn_tc(
    const float* __restrict__ Q, const float* __restrict__ K,
    const float* __restrict__ V, float* __restrict__ O)
{
    __shared__ uint32_t sm[4 * ABUF];   // 36864 B
    const int tid = threadIdx.x;
    const int lane = tid & 31;
    const int wid = tid >> 5;
    const int lr8 = lane & 7;
    const int mat = lane >> 3;
    const int qb = gridDim.x - 1 - blockIdx.x;   // heavy tiles first
    const int bh = blockIdx.y;

    const uint32_t sbase = smem_u32(sm);

    const float* Qg = Q + ((size_t)bh * SEQ + (size_t)qb * QT) * HDIM;
    const float* Kg = K + (size_t)bh * SEQ * HDIM;
    const float* Vg = V + (size_t)bh * SEQ * HDIM;

    const int r16 = tid >> 4;
    const int c4f = (tid & 15) << 2;
    const int kw  = (tid & 15) << 1;

    // ---- stage Q (x 1/8), split hi/lo into smem, ldsm into registers ----
#pragma unroll
    for (int u = 0; u < 8; u++) {
        const int row = r16 + u * 16;
        const float4 q = *(const float4*)(Qg + (size_t)row * HDIM + c4f);
        uint32_t h0, l0, h1, l1;
        split2(q.x * 0.125f, q.y * 0.125f, h0, l0);
        split2(q.z * 0.125f, q.w * 0.125f, h1, l1);
        const int w = row * AROWW + kw;
        *(uint2*)(sm + w) = make_uint2(h0, h1);
        *(uint2*)(sm + 2 * ABUF + w) = make_uint2(l0, l1);
    }
    __syncthreads();

    uint32_t qh[4][4], ql[4][4];
    {
        const uint32_t qa = sbase +
            (uint32_t)((wid * 16 + (mat & 1) * 8 + lr8) * 144 + (mat >> 1) * 16);
#pragma unroll
        for (int ks = 0; ks < 4; ks++) {
            ldsm4(qh[ks], qa + ks * 32);
            ldsm4(ql[ks], qa + 2 * ABUF * 4 + ks * 32);
        }
    }

    float oacc[8][4];
#pragma unroll
    for (int nf = 0; nf < 8; nf++)
#pragma unroll
        for (int e = 0; e < 4; e++) oacc[nf][e] = 0.f;
    float m0r = -INFINITY, m1r = -INFINITY, l0r = 0.f, l1r = 0.f;

    const int jbmax = 2 * qb + 1;
    const int qrow0 = qb * QT + wid * 16 + (lane >> 2);

    float4 kreg[4];
#pragma unroll
    for (int u = 0; u < 4; u++)
        kreg[u] = *(const float4*)(Kg + (size_t)(r16 + u * 16) * HDIM + c4f);

    for (int jb = 0; jb <= jbmax; jb++) {
        __syncthreads();
#pragma unroll
        for (int u = 0; u < 4; u++) {
            uint32_t h0, l0, h1, l1;
            split2(kreg[u].x, kreg[u].y, h0, l0);
            split2(kreg[u].z, kreg[u].w, h1, l1);
            const int w = (r16 + u * 16) * AROWW + kw;
            *(uint2*)(sm + w) = make_uint2(h0, h1);
            *(uint2*)(sm + ABUF + w) = make_uint2(l0, l1);
        }
        __syncthreads();

        float4 vreg[4];
        {
            const float* Vt = Vg + (size_t)jb * KT * HDIM;
#pragma unroll
            for (int u = 0; u < 4; u++)
                vreg[u] = *(const float4*)(Vt + (size_t)(r16 + u * 16) * HDIM + c4f);
        }

        float sacc[8][4];
#pragma unroll
        for (int nf = 0; nf < 8; nf++)
#pragma unroll
            for (int e = 0; e < 4; e++) sacc[nf][e] = 0.f;

#pragma unroll
        for (int ks = 0; ks < 4; ks++) {
#pragma unroll
            for (int np = 0; np < 4; np++) {
                uint32_t kh[4], kl[4];
                const uint32_t ka = sbase +
                    (uint32_t)((np * 16 + (mat >> 1) * 8 + lr8) * 144 + ks * 32 + (mat & 1) * 16);
                ldsm4(kh, ka);
                ldsm4(kl, ka + ABUF * 4);
#pragma unroll
                for (int hh = 0; hh < 2; hh++) {
                    float* d = sacc[np * 2 + hh];
                    mma_bf16(d, qh[ks], &kh[hh * 2]);
                    mma_bf16(d, qh[ks], &kl[hh * 2]);
                    mma_bf16(d, ql[ks], &kh[hh * 2]);
                }
            }
        }

#pragma unroll
        for (int u = 0; u < 4; u++) {
            uint32_t h0, l0, h1, l1;
            split2(vreg[u].x, vreg[u].y, h0, l0);
            split2(vreg[u].z, vreg[u].w, h1, l1);
            const int w = (r16 + u * 16) * AROWW + kw;
            *(uint2*)(sm + 2 * ABUF + w) = make_uint2(h0, h1);
            *(uint2*)(sm + 3 * ABUF + w) = make_uint2(l0, l1);
        }
        __syncthreads();

        if (jb < jbmax) {
            const float* Kt = Kg + (size_t)(jb + 1) * KT * HDIM;
#pragma unroll
            for (int u = 0; u < 4; u++)
                kreg[u] = *(const float4*)(Kt + (size_t)(r16 + u * 16) * HDIM + c4f);
        }

        if (jb * KT + KT - 1 > qrow0) {
#pragma unroll
            for (int nt = 0; nt < 8; nt++) {
                const int c = jb * KT + nt * 8 + ((lane & 3) << 1);
                if (c     > qrow0)     sacc[nt][0] = -INFINITY;
                if (c + 1 > qrow0)     sacc[nt][1] = -INFINITY;
                if (c     > qrow0 + 8) sacc[nt][2] = -INFINITY;
                if (c + 1 > qrow0 + 8) sacc[nt][3] = -INFINITY;
            }
        }

        float mx0 = sacc[0][0], mx1 = sacc[0][2];
#pragma unroll
        for (int nt = 0; nt < 8; nt++) {
            mx0 = fmaxf(mx0, fmaxf(sacc[nt][0], sacc[nt][1]));
            mx1 = fmaxf(mx1, fmaxf(sacc[nt][2], sacc[nt][3]));
        }
        mx0 = fmaxf(mx0, __shfl_xor_sync(~0u, mx0, 1));
        mx0 = fmaxf(mx0, __shfl_xor_sync(~0u, mx0, 2));
        mx1 = fmaxf(mx1, __shfl_xor_sync(~0u, mx1, 1));
        mx1 = fmaxf(mx1, __shfl_xor_sync(~0u, mx1, 2));
        const float mn0 = fmaxf(m0r, mx0), mn1 = fmaxf(m1r, mx1);
        const float cr0 = __expf(m0r - mn0), cr1 = __expf(m1r - mn1);
        m0r = mn0; m1r = mn1;
        float rs0 = 0.f, rs1 = 0.f;
#pragma unroll
        for (int nt = 0; nt < 8; nt++) {
            sacc[nt][0] = __expf(sacc[nt][0] - mn0);
            sacc[nt][1] = __expf(sacc[nt][1] - mn0);
            sacc[nt][2] = __expf(sacc[nt][2] - mn1);
            sacc[nt][3] = __expf(sacc[nt][3] - mn1);
            rs0 += sacc[nt][0] + sacc[nt][1];
            rs1 += sacc[nt][2] + sacc[nt][3];
        }
        rs0 += __shfl_xor_sync(~0u, rs0, 1);
        rs0 += __shfl_xor_sync(~0u, rs0, 2);
        rs1 += __shfl_xor_sync(~0u, rs1, 1);
        rs1 += __shfl_xor_sync(~0u, rs1, 2);
        l0r = l0r * cr0 + rs0;
        l1r = l1r * cr1 + rs1;
#pragma unroll
        for (int nf = 0; nf < 8; nf++) {
            oacc[nf][0] *= cr0; oacc[nf][1] *= cr0;
            oacc[nf][2] *= cr1; oacc[nf][3] *= cr1;
        }

#pragma unroll
        for (int ks = 0; ks < 4; ks++) {
            uint32_t ph[4], pl[4];
            split2(sacc[2 * ks][0],     sacc[2 * ks][1],     ph[0], pl[0]);
            split2(sacc[2 * ks][2],     sacc[2 * ks][3],     ph[1], pl[1]);
            split2(sacc[2 * ks + 1][0], sacc[2 * ks + 1][1], ph[2], pl[2]);
            split2(sacc[2 * ks + 1][2], sacc[2 * ks + 1][3], ph[3], pl[3]);
#pragma unroll
            for (int np = 0; np < 4; np++) {
                uint32_t vh[4], vl[4];
                const uint32_t va = sbase + (uint32_t)(2 * ABUF * 4) +
                    (uint32_t)((ks * 16 + (mat & 1) * 8 + lr8) * 144 + np * 32 + (mat >> 1) * 16);
                ldsm4t(vh, va);
                ldsm4t(vl, va + ABUF * 4);
#pragma unroll
                for (int hh = 0; hh < 2; hh++) {
                    float* d = oacc[np * 2 + hh];
                    mma_bf16(d, ph, &vh[hh * 2]);
                    mma_bf16(d, ph, &vl[hh * 2]);
                    mma_bf16(d, pl, &vh[hh * 2]);
                }
            }
        }
    }

    // epilogue: normalize, write [b, s, h*64 + d]
    const int b = bh >> 4, h = bh & 15;
    const float inv0 = 1.f / l0r, inv1 = 1.f / l1r;
#pragma unroll
    for (int nt = 0; nt < 8; nt++) {
        const int col = h * HDIM + nt * 8 + ((lane & 3) << 1);
        *(float2*)(O + ((size_t)(b * SEQ) + qrow0) * EMB + col) =
            make_float2(oacc[nt][0] * inv0, oacc[nt][1] * inv0);
        *(float2*)(O + ((size_t)(b * SEQ) + qrow0 + 8) * EMB + col) =
            make_float2(oacc[nt][2] * inv1, oacc[nt][3] * inv1);
    }
}

// ---------------------------------------------------------------------------
extern "C" void kernel_launch(void* const* d_in, const int* in_sizes, int n_in,
                              void* d_out, int out_size)
{
    (void)in_sizes; (void)n_in; (void)out_size;
    const float* x  = (const float*)d_in[0];
    // d_in[1] = mask (causal tril, implied — unused)
    const float* Wq = (const float*)d_in[2];
    const float* bq = (const float*)d_in[3];
    const float* Wk = (const float*)d_in[4];
    const float* bk = (const float*)d_in[5];
    const float* Wv = (const float*)d_in[6];
    const float* bv = (const float*)d_in[7];
    const float* Wo = (const float*)d_in[8];
    const float* bo = (const float*)d_in[9];
    float* out = (float*)d_out;

    float *gq, *gk, *gv, *go;
    cudaGetSymbolAddress((void**)&gq, g_q);
    cudaGetSymbolAddress((void**)&gk, g_k);
    cudaGetSymbolAddress((void**)&gv, g_v);
    cudaGetSymbolAddress((void**)&go, g_o);

    const dim3 gemm_grid(EMB / 128, MTOT / 128);  // (8, 32)
    gemm_tc<<<gemm_grid, 256>>>(x, Wq, bq, gq, 1);
    gemm_tc<<<gemm_grid, 256>>>(x, Wk, bk, gk, 1);
    gemm_tc<<<gemm_grid, 256>>>(x, Wv, bv, gv, 1);

    const dim3 attn_grid(SEQ / QT, BATCH * NHEAD);  // (16, 32)
    attn_tc<<<attn_grid, 256>>>(gq, gk, gv, go);

    const dim3 out_grid(EMB / 128, MTOT / 128);
    gemm_tc<<<out_grid, 256>>>(go, Wo, bo, out, 0);
}

// round 9
// speedup vs baseline: 1.1349x; 1.0429x over previous
#include <cuda_runtime.h>
#include <cuda_bf16.h>
#include <math.h>
#include <stddef.h>
#include <stdint.h>

// Problem constants
#define NHEAD 16
#define HDIM  64
#define SEQ   2048
#define BATCH 2
#define EMB   1024
#define MTOT  (BATCH * SEQ)   // 4096

// Scratch (device globals: allocation-free, graph-capturable)
__device__ float g_q[BATCH * NHEAD * SEQ * HDIM];
__device__ float g_k[BATCH * NHEAD * SEQ * HDIM];
__device__ float g_v[BATCH * NHEAD * SEQ * HDIM];
__device__ float g_o[MTOT * EMB];

// ===========================================================================
// mma.sync helpers (arch-portable tensor core path; works at compute_103)
// ===========================================================================
__device__ __forceinline__ void mma_bf16(float* d, const uint32_t* a, const uint32_t* b) {
    asm volatile(
        "mma.sync.aligned.m16n8k16.row.col.f32.bf16.bf16.f32 "
        "{%0,%1,%2,%3}, {%4,%5,%6,%7}, {%8,%9}, {%0,%1,%2,%3};"
        : "+f"(d[0]), "+f"(d[1]), "+f"(d[2]), "+f"(d[3])
        : "r"(a[0]), "r"(a[1]), "r"(a[2]), "r"(a[3]), "r"(b[0]), "r"(b[1]));
}

__device__ __forceinline__ void ldsm4(uint32_t* r, uint32_t addr) {
    asm volatile("ldmatrix.sync.aligned.m8n8.x4.shared.b16 {%0,%1,%2,%3}, [%4];"
        : "=r"(r[0]), "=r"(r[1]), "=r"(r[2]), "=r"(r[3]) : "r"(addr));
}

__device__ __forceinline__ void ldsm4t(uint32_t* r, uint32_t addr) {
    asm volatile("ldmatrix.sync.aligned.m8n8.x4.trans.shared.b16 {%0,%1,%2,%3}, [%4];"
        : "=r"(r[0]), "=r"(r[1]), "=r"(r[2]), "=r"(r[3]) : "r"(addr));
}

__device__ __forceinline__ uint32_t smem_u32(const void* p) {
    uint32_t a;
    asm("{ .reg .u64 t; cvta.to.shared.u64 t, %1; cvt.u32.u64 %0, t; }"
        : "=r"(a) : "l"(p));
    return a;
}

// hi/lo bf16 split of 2 floats (packed into u32 each)
__device__ __forceinline__ void split2(float x, float y, uint32_t& hi, uint32_t& lo) {
    __nv_bfloat162 h = __floats2bfloat162_rn(x, y);
    float hx = __bfloat162float(h.x), hy = __bfloat162float(h.y);
    __nv_bfloat162 l = __floats2bfloat162_rn(x - hx, y - hy);
    hi = *(uint32_t*)&h;
    lo = *(uint32_t*)&l;
}

// ===========================================================================
// Tensor-core GEMM (round-5 local optimum, hot loop unchanged).
// grid.z selects W/bias/C so Q,K,V projections run in ONE launch (one tail).
// ===========================================================================
#define GBK 32
#define SROWB 80
#define SROWW (SROWB / 4)
#define TILE_U32 (128 * SROWW)

__global__ __launch_bounds__(256, 1) void gemm_tc(
    const float* __restrict__ A,
    const float* __restrict__ W0, const float* __restrict__ W1,
    const float* __restrict__ W2,
    const float* __restrict__ bias0, const float* __restrict__ bias1,
    const float* __restrict__ bias2,
    float* __restrict__ C0, float* __restrict__ C1, float* __restrict__ C2,
    int writeQKV)
{
    __shared__ uint32_t sh[4 * TILE_U32];   // 40960 B: Ah, Al, Bh, Bl
    uint32_t* Ah = sh;
    uint32_t* Al = sh + TILE_U32;
    uint32_t* Bh = sh + 2 * TILE_U32;
    uint32_t* Bl = sh + 3 * TILE_U32;

    const int z = blockIdx.z;
    const float* W = (z == 0) ? W0 : (z == 1) ? W1 : W2;
    const float* bias = (z == 0) ? bias0 : (z == 1) ? bias1 : bias2;
    float* C = (z == 0) ? C0 : (z == 1) ? C1 : C2;

    const int tid = threadIdx.x;
    const int lane = tid & 31;
    const int wid = tid >> 5;
    const int wm = wid & 3;
    const int wn = wid >> 2;
    const int m0 = blockIdx.y * 128;
    const int n0 = blockIdx.x * 128;

    const int grow = tid >> 3;
    const int gc4 = (tid & 7) << 2;
    const int kp = (tid & 7) << 1;

    const int mat = lane >> 3, lr8 = lane & 7;
    const uint32_t sbase = smem_u32(sh);
    const uint32_t a_off = (uint32_t)((wm * 32 + (mat & 1) * 8 + lr8) * SROWB + (mat >> 1) * 16);
    const uint32_t b_off = (uint32_t)((wn * 64 + (mat >> 1) * 8 + lr8) * SROWB + (mat & 1) * 16);

    const uint32_t sAh = sbase + a_off;
    const uint32_t sAl = sAh + TILE_U32 * 4;
    const uint32_t sBh = sbase + 2 * TILE_U32 * 4 + b_off;
    const uint32_t sBl = sBh + TILE_U32 * 4;

    float acc[2][8][4];
#pragma unroll
    for (int mf = 0; mf < 2; mf++)
#pragma unroll
        for (int nf = 0; nf < 8; nf++)
#pragma unroll
            for (int e = 0; e < 4; e++) acc[mf][nf][e] = 0.f;

    const float* Ag = A + (size_t)m0 * EMB;
    const float* Wg = W + (size_t)n0 * EMB;

    float4 avr[4], wvr[4];
#pragma unroll
    for (int u = 0; u < 4; u++) {
        avr[u] = *(const float4*)(Ag + (size_t)(grow + u * 32) * EMB + gc4);
        wvr[u] = *(const float4*)(Wg + (size_t)(grow + u * 32) * EMB + gc4);
    }

    for (int kk = 0; kk < EMB / GBK; kk++) {
        __syncthreads();
#pragma unroll
        for (int u = 0; u < 4; u++) {
            const int row = grow + u * 32;
            const int w0 = row * SROWW + kp;
            uint32_t h0, l0, h1, l1;
            split2(avr[u].x, avr[u].y, h0, l0);
            split2(avr[u].z, avr[u].w, h1, l1);
            *(uint2*)(Ah + w0) = make_uint2(h0, h1);
            *(uint2*)(Al + w0) = make_uint2(l0, l1);
            split2(wvr[u].x, wvr[u].y, h0, l0);
            split2(wvr[u].z, wvr[u].w, h1, l1);
            *(uint2*)(Bh + w0) = make_uint2(h0, h1);
            *(uint2*)(Bl + w0) = make_uint2(l0, l1);
        }
        __syncthreads();

        if (kk + 1 < EMB / GBK) {
            const int kcol = (kk + 1) * GBK + gc4;
#pragma unroll
            for (int u = 0; u < 4; u++) {
                avr[u] = *(const float4*)(Ag + (size_t)(grow + u * 32) * EMB + kcol);
                wvr[u] = *(const float4*)(Wg + (size_t)(grow + u * 32) * EMB + kcol);
            }
        }

#pragma unroll
        for (int ks = 0; ks < 2; ks++) {
            const uint32_t kadd = ks * 32;
            uint32_t ah[2][4], al[2][4], bh[4][4], bl[4][4];
#pragma unroll
            for (int mf = 0; mf < 2; mf++) {
                ldsm4(ah[mf], sAh + mf * 16 * SROWB + kadd);
                ldsm4(al[mf], sAl + mf * 16 * SROWB + kadd);
            }
#pragma unroll
            for (int np = 0; np < 4; np++) {
                ldsm4(bh[np], sBh + np * 16 * SROWB + kadd);
                ldsm4(bl[np], sBl + np * 16 * SROWB + kadd);
            }
#pragma unroll
            for (int mf = 0; mf < 2; mf++)
#pragma unroll
                for (int nf = 0; nf < 8; nf++) {
                    const int np = nf >> 1;
                    uint32_t* bhp = &bh[np][(nf & 1) * 2];
                    uint32_t* blp = &bl[np][(nf & 1) * 2];
                    mma_bf16(acc[mf][nf], ah[mf], bhp);
                    mma_bf16(acc[mf][nf], ah[mf], blp);
                    mma_bf16(acc[mf][nf], al[mf], bhp);
                }
        }
    }

#pragma unroll
    for (int mf = 0; mf < 2; mf++) {
#pragma unroll
        for (int half = 0; half < 2; half++) {
            const int m = m0 + wm * 32 + mf * 16 + (lane >> 2) + half * 8;
            const int b = m >> 11;
            const int s = m & (SEQ - 1);
#pragma unroll
            for (int nf = 0; nf < 8; nf++) {
                const int n = n0 + wn * 64 + nf * 8 + ((lane & 3) << 1);
                float2 v;
                v.x = acc[mf][nf][half * 2 + 0] + bias[n];
                v.y = acc[mf][nf][half * 2 + 1] + bias[n + 1];
                if (writeQKV) {
                    const int h = n >> 6;
                    const int d = n & 63;
                    *(float2*)(C + (((size_t)(b * NHEAD + h)) * SEQ + s) * HDIM + d) = v;
                } else {
                    *(float2*)(C + (size_t)m * EMB + n) = v;
                }
            }
        }
    }
}

// ===========================================================================
// Tensor-core causal flash attention, DOUBLE-BUFFERED K/V:
// 8 smem regions (Kh/Kl/Vh/Vl x 2 parities, 73.7KB dynamic). Iteration jb
// stores tile jb+1 into parity (jb+1)&1, LDGs tile jb+2, computes from
// parity jb&1, ONE __syncthreads per tile.
// ===========================================================================
#define QT 128
#define KT 64
#define AROWW 36            // u32 words per smem row (144 B)
#define ABUF (64 * AROWW)   // 2304 words (9216 B) per region
#define ATT_SMEM (8 * ABUF * 4)   // 73728 B

__global__ __launch_bounds__(256, 1) void attn_tc(
    const float* __restrict__ Q, const float* __restrict__ K,
    const float* __restrict__ V, float* __restrict__ O)
{
    extern __shared__ uint32_t sm[];
    const int tid = threadIdx.x;
    const int lane = tid & 31;
    const int wid = tid >> 5;
    const int lr8 = lane & 7;
    const int mat = lane >> 3;
    const int qb = blockIdx.x;
    const int bh = blockIdx.y;

    const uint32_t sbase = smem_u32(sm);

    const float* Qg = Q + ((size_t)bh * SEQ + (size_t)qb * QT) * HDIM;
    const float* Kg = K + (size_t)bh * SEQ * HDIM;
    const float* Vg = V + (size_t)bh * SEQ * HDIM;

    const int r16 = tid >> 4;             // 0..15
    const int c4f = (tid & 15) << 2;      // 0..60
    const int kw  = (tid & 15) << 1;      // u32 word offset in row

    // ---- stage Q (x 1/8), split hi/lo into regions 0-3, ldsm to regs ----
#pragma unroll
    for (int u = 0; u < 8; u++) {
        const int row = r16 + u * 16;
        const float4 q = *(const float4*)(Qg + (size_t)row * HDIM + c4f);
        uint32_t h0, l0, h1, l1;
        split2(q.x * 0.125f, q.y * 0.125f, h0, l0);
        split2(q.z * 0.125f, q.w * 0.125f, h1, l1);
        const int w = row * AROWW + kw;
        *(uint2*)(sm + w) = make_uint2(h0, h1);             // Qh: regions 0-1
        *(uint2*)(sm + 2 * ABUF + w) = make_uint2(l0, l1);  // Ql: regions 2-3
    }
    __syncthreads();

    uint32_t qh[4][4], ql[4][4];
    {
        const uint32_t qa = sbase +
            (uint32_t)((wid * 16 + (mat & 1) * 8 + lr8) * 144 + (mat >> 1) * 16);
#pragma unroll
        for (int ks = 0; ks < 4; ks++) {
            ldsm4(qh[ks], qa + ks * 32);
            ldsm4(ql[ks], qa + 2 * ABUF * 4 + ks * 32);
        }
    }

    float oacc[8][4];
#pragma unroll
    for (int nf = 0; nf < 8; nf++)
#pragma unroll
        for (int e = 0; e < 4; e++) oacc[nf][e] = 0.f;
    float m0r = -INFINITY, m1r = -INFINITY, l0r = 0.f, l1r = 0.f;

    const int jbmax = 2 * qb + 1;
    const int qrow0 = qb * QT + wid * 16 + (lane >> 2);

    // ---- prologue: tile 0 -> parity 0; prefetch tile 1 into regs ----
    float4 kreg[4], vreg[4];
#pragma unroll
    for (int u = 0; u < 4; u++) {
        kreg[u] = *(const float4*)(Kg + (size_t)(r16 + u * 16) * HDIM + c4f);
        vreg[u] = *(const float4*)(Vg + (size_t)(r16 + u * 16) * HDIM + c4f);
    }
    __syncthreads();   // Q ldsm complete in all warps before regions reused
#pragma unroll
    for (int u = 0; u < 4; u++) {
        const int w = (r16 + u * 16) * AROWW + kw;
        uint32_t h0, l0, h1, l1;
        split2(kreg[u].x, kreg[u].y, h0, l0);
        split2(kreg[u].z, kreg[u].w, h1, l1);
        *(uint2*)(sm + 0 * ABUF + w) = make_uint2(h0, h1);   // Kh0
        *(uint2*)(sm + 1 * ABUF + w) = make_uint2(l0, l1);   // Kl0
        split2(vreg[u].x, vreg[u].y, h0, l0);
        split2(vreg[u].z, vreg[u].w, h1, l1);
        *(uint2*)(sm + 2 * ABUF + w) = make_uint2(h0, h1);   // Vh0
        *(uint2*)(sm + 3 * ABUF + w) = make_uint2(l0, l1);   // Vl0
    }
    if (jbmax >= 1) {
        const float* Kt = Kg + (size_t)KT * HDIM;
        const float* Vt = Vg + (size_t)KT * HDIM;
#pragma unroll
        for (int u = 0; u < 4; u++) {
            kreg[u] = *(const float4*)(Kt + (size_t)(r16 + u * 16) * HDIM + c4f);
            vreg[u] = *(const float4*)(Vt + (size_t)(r16 + u * 16) * HDIM + c4f);
        }
    }
    __syncthreads();

    for (int jb = 0; jb <= jbmax; jb++) {
        const uint32_t pw = (uint32_t)((jb & 1) * 4 * ABUF);       // compute parity
        const uint32_t nw = (uint32_t)(((jb + 1) & 1) * 4 * ABUF); // store parity

        // store tile jb+1 (from regs) into opposite parity — overlaps MMA
        if (jb < jbmax) {
#pragma unroll
            for (int u = 0; u < 4; u++) {
                const int w = (r16 + u * 16) * AROWW + kw;
                uint32_t h0, l0, h1, l1;
                split2(kreg[u].x, kreg[u].y, h0, l0);
                split2(kreg[u].z, kreg[u].w, h1, l1);
                *(uint2*)(sm + nw + 0 * ABUF + w) = make_uint2(h0, h1);
                *(uint2*)(sm + nw + 1 * ABUF + w) = make_uint2(l0, l1);
                split2(vreg[u].x, vreg[u].y, h0, l0);
                split2(vreg[u].z, vreg[u].w, h1, l1);
                *(uint2*)(sm + nw + 2 * ABUF + w) = make_uint2(h0, h1);
                *(uint2*)(sm + nw + 3 * ABUF + w) = make_uint2(l0, l1);
            }
        }
        // prefetch tile jb+2 (LDG latency hidden under MMA)
        if (jb + 2 <= jbmax) {
            const float* Kt = Kg + (size_t)(jb + 2) * KT * HDIM;
            const float* Vt = Vg + (size_t)(jb + 2) * KT * HDIM;
#pragma unroll
            for (int u = 0; u < 4; u++) {
                kreg[u] = *(const float4*)(Kt + (size_t)(r16 + u * 16) * HDIM + c4f);
                vreg[u] = *(const float4*)(Vt + (size_t)(r16 + u * 16) * HDIM + c4f);
            }
        }

        // S = Q K^T (3-term split) from parity pw
        float sacc[8][4];
#pragma unroll
        for (int nf = 0; nf < 8; nf++)
#pragma unroll
            for (int e = 0; e < 4; e++) sacc[nf][e] = 0.f;

#pragma unroll
        for (int ks = 0; ks < 4; ks++) {
#pragma unroll
            for (int np = 0; np < 4; np++) {
                uint32_t kh[4], kl[4];
                const uint32_t ka = sbase + pw * 4 +
                    (uint32_t)((np * 16 + (mat >> 1) * 8 + lr8) * 144 + ks * 32 + (mat & 1) * 16);
                ldsm4(kh, ka);
                ldsm4(kl, ka + ABUF * 4);
#pragma unroll
                for (int hh = 0; hh < 2; hh++) {
                    float* d = sacc[np * 2 + hh];
                    mma_bf16(d, qh[ks], &kh[hh * 2]);
                    mma_bf16(d, qh[ks], &kl[hh * 2]);
                    mma_bf16(d, ql[ks], &kh[hh * 2]);
                }
            }
        }

        // causal mask (diagonal-band tiles only)
        if (jb * KT + KT - 1 > qrow0) {
#pragma unroll
            for (int nt = 0; nt < 8; nt++) {
                const int c = jb * KT + nt * 8 + ((lane & 3) << 1);
                if (c     > qrow0)     sacc[nt][0] = -INFINITY;
                if (c + 1 > qrow0)     sacc[nt][1] = -INFINITY;
                if (c     > qrow0 + 8) sacc[nt][2] = -INFINITY;
                if (c + 1 > qrow0 + 8) sacc[nt][3] = -INFINITY;
            }
        }

        // online softmax (rows r, r+8; reduce across 4 lanes)
        float mx0 = sacc[0][0], mx1 = sacc[0][2];
#pragma unroll
        for (int nt = 0; nt < 8; nt++) {
            mx0 = fmaxf(mx0, fmaxf(sacc[nt][0], sacc[nt][1]));
            mx1 = fmaxf(mx1, fmaxf(sacc[nt][2], sacc[nt][3]));
        }
        mx0 = fmaxf(mx0, __shfl_xor_sync(~0u, mx0, 1));
        mx0 = fmaxf(mx0, __shfl_xor_sync(~0u, mx0, 2));
        mx1 = fmaxf(mx1, __shfl_xor_sync(~0u, mx1, 1));
        mx1 = fmaxf(mx1, __shfl_xor_sync(~0u, mx1, 2));
        const float mn0 = fmaxf(m0r, mx0), mn1 = fmaxf(m1r, mx1);
        const float cr0 = __expf(m0r - mn0), cr1 = __expf(m1r - mn1);
        m0r = mn0; m1r = mn1;
        float rs0 = 0.f, rs1 = 0.f;
#pragma unroll
        for (int nt = 0; nt < 8; nt++) {
            sacc[nt][0] = __expf(sacc[nt][0] - mn0);
            sacc[nt][1] = __expf(sacc[nt][1] - mn0);
            sacc[nt][2] = __expf(sacc[nt][2] - mn1);
            sacc[nt][3] = __expf(sacc[nt][3] - mn1);
            rs0 += sacc[nt][0] + sacc[nt][1];
            rs1 += sacc[nt][2] + sacc[nt][3];
        }
        rs0 += __shfl_xor_sync(~0u, rs0, 1);
        rs0 += __shfl_xor_sync(~0u, rs0, 2);
        rs1 += __shfl_xor_sync(~0u, rs1, 1);
        rs1 += __shfl_xor_sync(~0u, rs1, 2);
        l0r = l0r * cr0 + rs0;
        l1r = l1r * cr1 + rs1;
#pragma unroll
        for (int nf = 0; nf < 8; nf++) {
            oacc[nf][0] *= cr0; oacc[nf][1] *= cr0;
            oacc[nf][2] *= cr1; oacc[nf][3] *= cr1;
        }

        // O += P V (3-term split) from parity pw
#pragma unroll
        for (int ks = 0; ks < 4; ks++) {
            uint32_t ph[4], pl[4];
            split2(sacc[2 * ks][0],     sacc[2 * ks][1],     ph[0], pl[0]);
            split2(sacc[2 * ks][2],     sacc[2 * ks][3],     ph[1], pl[1]);
            split2(sacc[2 * ks + 1][0], sacc[2 * ks + 1][1], ph[2], pl[2]);
            split2(sacc[2 * ks + 1][2], sacc[2 * ks + 1][3], ph[3], pl[3]);
#pragma unroll
            for (int np = 0; np < 4; np++) {
                uint32_t vh[4], vl[4];
                const uint32_t va = sbase + pw * 4 + (uint32_t)(2 * ABUF * 4) +
                    (uint32_t)((ks * 16 + (mat & 1) * 8 + lr8) * 144 + np * 32 + (mat >> 1) * 16);
                ldsm4t(vh, va);
                ldsm4t(vl, va + ABUF * 4);
#pragma unroll
                for (int hh = 0; hh < 2; hh++) {
                    float* d = oacc[np * 2 + hh];
                    mma_bf16(d, ph, &vh[hh * 2]);
                    mma_bf16(d, ph, &vl[hh * 2]);
                    mma_bf16(d, pl, &vh[hh * 2]);
                }
            }
        }

        __syncthreads();   // single barrier: publishes tile jb+1, retires parity pw
    }

    // epilogue: normalize, write [b, s, h*64 + d]
    const int b = bh >> 4, h = bh & 15;
    const float inv0 = 1.f / l0r, inv1 = 1.f / l1r;
#pragma unroll
    for (int nt = 0; nt < 8; nt++) {
        const int col = h * HDIM + nt * 8 + ((lane & 3) << 1);
        *(float2*)(O + ((size_t)(b * SEQ) + qrow0) * EMB + col) =
            make_float2(oacc[nt][0] * inv0, oacc[nt][1] * inv0);
        *(float2*)(O + ((size_t)(b * SEQ) + qrow0 + 8) * EMB + col) =
            make_float2(oacc[nt][2] * inv1, oacc[nt][3] * inv1);
    }
}

// ---------------------------------------------------------------------------
extern "C" void kernel_launch(void* const* d_in, const int* in_sizes, int n_in,
                              void* d_out, int out_size)
{
    (void)in_sizes; (void)n_in; (void)out_size;
    const float* x  = (const float*)d_in[0];
    // d_in[1] = mask (causal tril, implied — unused)
    const float* Wq = (const float*)d_in[2];
    const float* bq = (const float*)d_in[3];
    const float* Wk = (const float*)d_in[4];
    const float* bk = (const float*)d_in[5];
    const float* Wv = (const float*)d_in[6];
    const float* bv = (const float*)d_in[7];
    const float* Wo = (const float*)d_in[8];
    const float* bo = (const float*)d_in[9];
    float* out = (float*)d_out;

    float *gq, *gk, *gv, *go;
    cudaGetSymbolAddress((void**)&gq, g_q);
    cudaGetSymbolAddress((void**)&gk, g_k);
    cudaGetSymbolAddress((void**)&gv, g_v);
    cudaGetSymbolAddress((void**)&go, g_o);

    cudaFuncSetAttribute(attn_tc, cudaFuncAttributeMaxDynamicSharedMemorySize,
                         ATT_SMEM);

    // Q, K, V projections in ONE launch (grid.z selects weight/bias/output)
    const dim3 qkv_grid(EMB / 128, MTOT / 128, 3);  // (8, 32, 3)
    gemm_tc<<<qkv_grid, 256>>>(x, Wq, Wk, Wv, bq, bk, bv, gq, gk, gv, 1);

    const dim3 attn_grid(SEQ / QT, BATCH * NHEAD);  // (16, 32)
    attn_tc<<<attn_grid, 256, ATT_SMEM>>>(gq, gk, gv, go);

    const dim3 out_grid(EMB / 128, MTOT / 128, 1);
    gemm_tc<<<out_grid, 256>>>(go, Wo, Wo, Wo, bo, bo, bo, out, out, out, 0);
}

// round 10
// speedup vs baseline: 1.1739x; 1.0344x over previous
#include <cuda_runtime.h>
#include <cuda_bf16.h>
#include <math.h>
#include <stddef.h>
#include <stdint.h>

// Problem constants
#define NHEAD 16
#define HDIM  64
#define SEQ   2048
#define BATCH 2
#define EMB   1024
#define MTOT  (BATCH * SEQ)   // 4096

// Scratch (device globals: allocation-free, graph-capturable)
__device__ float g_q[BATCH * NHEAD * SEQ * HDIM];
__device__ float g_k[BATCH * NHEAD * SEQ * HDIM];
__device__ float g_v[BATCH * NHEAD * SEQ * HDIM];
__device__ float g_o[MTOT * EMB];

// ===========================================================================
// mma.sync helpers (arch-portable tensor core path; works at compute_103)
// ===========================================================================
__device__ __forceinline__ void mma_bf16(float* d, const uint32_t* a, const uint32_t* b) {
    asm volatile(
        "mma.sync.aligned.m16n8k16.row.col.f32.bf16.bf16.f32 "
        "{%0,%1,%2,%3}, {%4,%5,%6,%7}, {%8,%9}, {%0,%1,%2,%3};"
        : "+f"(d[0]), "+f"(d[1]), "+f"(d[2]), "+f"(d[3])
        : "r"(a[0]), "r"(a[1]), "r"(a[2]), "r"(a[3]), "r"(b[0]), "r"(b[1]));
}

__device__ __forceinline__ void ldsm4(uint32_t* r, uint32_t addr) {
    asm volatile("ldmatrix.sync.aligned.m8n8.x4.shared.b16 {%0,%1,%2,%3}, [%4];"
        : "=r"(r[0]), "=r"(r[1]), "=r"(r[2]), "=r"(r[3]) : "r"(addr));
}

__device__ __forceinline__ void ldsm4t(uint32_t* r, uint32_t addr) {
    asm volatile("ldmatrix.sync.aligned.m8n8.x4.trans.shared.b16 {%0,%1,%2,%3}, [%4];"
        : "=r"(r[0]), "=r"(r[1]), "=r"(r[2]), "=r"(r[3]) : "r"(addr));
}

__device__ __forceinline__ uint32_t smem_u32(const void* p) {
    uint32_t a;
    asm("{ .reg .u64 t; cvta.to.shared.u64 t, %1; cvt.u32.u64 %0, t; }"
        : "=r"(a) : "l"(p));
    return a;
}

// hi/lo bf16 split of 2 floats (packed into u32 each)
__device__ __forceinline__ void split2(float x, float y, uint32_t& hi, uint32_t& lo) {
    __nv_bfloat162 h = __floats2bfloat162_rn(x, y);
    float hx = __bfloat162float(h.x), hy = __bfloat162float(h.y);
    __nv_bfloat162 l = __floats2bfloat162_rn(x - hx, y - hy);
    hi = *(uint32_t*)&h;
    lo = *(uint32_t*)&l;
}

// ===========================================================================
// Tensor-core GEMM, DOUBLE-BUFFERED smem with MMA-sandwiched stores:
// per chunk: MMA(ks=0) -> split+STS of chunk kk+1 to other parity ->
// MMA(ks=1) -> LDG prefetch kk+2 -> ONE __syncthreads. Zero extra registers
// vs round-5 loop (staging avr/wvr reused). grid.z selects W/bias/C.
// ===========================================================================
#define GBK 32
#define SROWB 80
#define SROWW (SROWB / 4)
#define TILE_U32 (128 * SROWW)     // 2560 words (10240 B)
#define BUFW (4 * TILE_U32)        // 10240 words (40960 B) per parity
#define GEMM_SMEM_B (2 * BUFW * 4) // 81920 B
#define NCH (EMB / GBK)            // 32

__global__ __launch_bounds__(256, 1) void gemm_tc(
    const float* __restrict__ A,
    const float* __restrict__ W0, const float* __restrict__ W1,
    const float* __restrict__ W2,
    const float* __restrict__ bias0, const float* __restrict__ bias1,
    const float* __restrict__ bias2,
    float* __restrict__ C0, float* __restrict__ C1, float* __restrict__ C2,
    int writeQKV)
{
    extern __shared__ uint32_t sh[];

    const int z = blockIdx.z;
    const float* W = (z == 0) ? W0 : (z == 1) ? W1 : W2;
    const float* bias = (z == 0) ? bias0 : (z == 1) ? bias1 : bias2;
    float* C = (z == 0) ? C0 : (z == 1) ? C1 : C2;

    const int tid = threadIdx.x;
    const int lane = tid & 31;
    const int wid = tid >> 5;
    const int wm = wid & 3;
    const int wn = wid >> 2;
    const int m0 = blockIdx.y * 128;
    const int n0 = blockIdx.x * 128;

    const int grow = tid >> 3;
    const int gc4 = (tid & 7) << 2;
    const int kp = (tid & 7) << 1;

    const int mat = lane >> 3, lr8 = lane & 7;
    const uint32_t sbase = smem_u32(sh);
    const uint32_t a_off = (uint32_t)((wm * 32 + (mat & 1) * 8 + lr8) * SROWB + (mat >> 1) * 16);
    const uint32_t b_off = (uint32_t)((wn * 64 + (mat >> 1) * 8 + lr8) * SROWB + (mat & 1) * 16);

    float acc[2][8][4];
#pragma unroll
    for (int mf = 0; mf < 2; mf++)
#pragma unroll
        for (int nf = 0; nf < 8; nf++)
#pragma unroll
            for (int e = 0; e < 4; e++) acc[mf][nf][e] = 0.f;

    const float* Ag = A + (size_t)m0 * EMB;
    const float* Wg = W + (size_t)n0 * EMB;

    float4 avr[4], wvr[4];

    // ---- prologue: chunk 0 -> parity 0; prefetch chunk 1 into regs ----
#pragma unroll
    for (int u = 0; u < 4; u++) {
        avr[u] = *(const float4*)(Ag + (size_t)(grow + u * 32) * EMB + gc4);
        wvr[u] = *(const float4*)(Wg + (size_t)(grow + u * 32) * EMB + gc4);
    }
#pragma unroll
    for (int u = 0; u < 4; u++) {
        const int w0 = (grow + u * 32) * SROWW + kp;
        uint32_t h0, l0, h1, l1;
        split2(avr[u].x, avr[u].y, h0, l0);
        split2(avr[u].z, avr[u].w, h1, l1);
        *(uint2*)(sh + w0) = make_uint2(h0, h1);
        *(uint2*)(sh + TILE_U32 + w0) = make_uint2(l0, l1);
        split2(wvr[u].x, wvr[u].y, h0, l0);
        split2(wvr[u].z, wvr[u].w, h1, l1);
        *(uint2*)(sh + 2 * TILE_U32 + w0) = make_uint2(h0, h1);
        *(uint2*)(sh + 3 * TILE_U32 + w0) = make_uint2(l0, l1);
    }
#pragma unroll
    for (int u = 0; u < 4; u++) {
        avr[u] = *(const float4*)(Ag + (size_t)(grow + u * 32) * EMB + GBK + gc4);
        wvr[u] = *(const float4*)(Wg + (size_t)(grow + u * 32) * EMB + GBK + gc4);
    }
    __syncthreads();

    for (int kk = 0; kk < NCH; kk++) {
        const uint32_t pofs = (uint32_t)((kk & 1) * BUFW);
        const uint32_t nofs = (uint32_t)(((kk + 1) & 1) * BUFW);

        const uint32_t sAh = sbase + pofs * 4 + a_off;
        const uint32_t sAl = sAh + TILE_U32 * 4;
        const uint32_t sBh = sbase + pofs * 4 + 2 * TILE_U32 * 4 + b_off;
        const uint32_t sBl = sBh + TILE_U32 * 4;

        // ---- ks = 0 MMA group ----
        {
            uint32_t ah[2][4], al[2][4], bh[4][4], bl[4][4];
#pragma unroll
            for (int mf = 0; mf < 2; mf++) {
                ldsm4(ah[mf], sAh + mf * 16 * SROWB);
                ldsm4(al[mf], sAl + mf * 16 * SROWB);
            }
#pragma unroll
            for (int np = 0; np < 4; np++) {
                ldsm4(bh[np], sBh + np * 16 * SROWB);
                ldsm4(bl[np], sBl + np * 16 * SROWB);
            }
#pragma unroll
            for (int mf = 0; mf < 2; mf++)
#pragma unroll
                for (int nf = 0; nf < 8; nf++) {
                    const int np = nf >> 1;
                    uint32_t* bhp = &bh[np][(nf & 1) * 2];
                    uint32_t* blp = &bl[np][(nf & 1) * 2];
                    mma_bf16(acc[mf][nf], ah[mf], bhp);
                    mma_bf16(acc[mf][nf], ah[mf], blp);
                    mma_bf16(acc[mf][nf], al[mf], bhp);
                }
        }

        // ---- split+STS chunk kk+1 -> other parity (sandwiched) ----
        if (kk + 1 < NCH) {
#pragma unroll
            for (int u = 0; u < 4; u++) {
                const int w0 = (grow + u * 32) * SROWW + kp;
                uint32_t h0, l0, h1, l1;
                split2(avr[u].x, avr[u].y, h0, l0);
                split2(avr[u].z, avr[u].w, h1, l1);
                *(uint2*)(sh + nofs + w0) = make_uint2(h0, h1);
                *(uint2*)(sh + nofs + TILE_U32 + w0) = make_uint2(l0, l1);
                split2(wvr[u].x, wvr[u].y, h0, l0);
                split2(wvr[u].z, wvr[u].w, h1, l1);
                *(uint2*)(sh + nofs + 2 * TILE_U32 + w0) = make_uint2(h0, h1);
                *(uint2*)(sh + nofs + 3 * TILE_U32 + w0) = make_uint2(l0, l1);
            }
        }

        // ---- ks = 1 MMA group ----
        {
            uint32_t ah[2][4], al[2][4], bh[4][4], bl[4][4];
#pragma unroll
            for (int mf = 0; mf < 2; mf++) {
                ldsm4(ah[mf], sAh + mf * 16 * SROWB + 32);
                ldsm4(al[mf], sAl + mf * 16 * SROWB + 32);
            }
#pragma unroll
            for (int np = 0; np < 4; np++) {
                ldsm4(bh[np], sBh + np * 16 * SROWB + 32);
                ldsm4(bl[np], sBl + np * 16 * SROWB + 32);
            }
#pragma unroll
            for (int mf = 0; mf < 2; mf++)
#pragma unroll
                for (int nf = 0; nf < 8; nf++) {
                    const int np = nf >> 1;
                    uint32_t* bhp = &bh[np][(nf & 1) * 2];
                    uint32_t* blp = &bl[np][(nf & 1) * 2];
                    mma_bf16(acc[mf][nf], ah[mf], bhp);
                    mma_bf16(acc[mf][nf], ah[mf], blp);
                    mma_bf16(acc[mf][nf], al[mf], bhp);
                }
        }

        // ---- prefetch chunk kk+2 (LDG latency hidden under next MMAs) ----
        if (kk + 2 < NCH) {
            const int kcol = (kk + 2) * GBK + gc4;
#pragma unroll
            for (int u = 0; u < 4; u++) {
                avr[u] = *(const float4*)(Ag + (size_t)(grow + u * 32) * EMB + kcol);
                wvr[u] = *(const float4*)(Wg + (size_t)(grow + u * 32) * EMB + kcol);
            }
        }

        __syncthreads();   // single barrier: publishes parity nofs, retires pofs
    }

#pragma unroll
    for (int mf = 0; mf < 2; mf++) {
#pragma unroll
        for (int half = 0; half < 2; half++) {
            const int m = m0 + wm * 32 + mf * 16 + (lane >> 2) + half * 8;
            const int b = m >> 11;
            const int s = m & (SEQ - 1);
#pragma unroll
            for (int nf = 0; nf < 8; nf++) {
                const int n = n0 + wn * 64 + nf * 8 + ((lane & 3) << 1);
                float2 v;
                v.x = acc[mf][nf][half * 2 + 0] + bias[n];
                v.y = acc[mf][nf][half * 2 + 1] + bias[n + 1];
                if (writeQKV) {
                    const int h = n >> 6;
                    const int d = n & 63;
                    *(float2*)(C + (((size_t)(b * NHEAD + h)) * SEQ + s) * HDIM + d) = v;
                } else {
                    *(float2*)(C + (size_t)m * EMB + n) = v;
                }
            }
        }
    }
}

// ===========================================================================
// Tensor-core causal flash attention, DOUBLE-BUFFERED K/V (round-9 version,
// unchanged — passing at ~190us).
// ===========================================================================
#define QT 128
#define KT 64
#define AROWW 36            // u32 words per smem row (144 B)
#define ABUF (64 * AROWW)   // 2304 words (9216 B) per region
#define ATT_SMEM (8 * ABUF * 4)   // 73728 B

__global__ __launch_bounds__(256, 1) void attn_tc(
    const float* __restrict__ Q, const float* __restrict__ K,
    const float* __restrict__ V, float* __restrict__ O)
{
    extern __shared__ uint32_t sm[];
    const int tid = threadIdx.x;
    const int lane = tid & 31;
    const int wid = tid >> 5;
    const int lr8 = lane & 7;
    const int mat = lane >> 3;
    const int qb = blockIdx.x;
    const int bh = blockIdx.y;

    const uint32_t sbase = smem_u32(sm);

    const float* Qg = Q + ((size_t)bh * SEQ + (size_t)qb * QT) * HDIM;
    const float* Kg = K + (size_t)bh * SEQ * HDIM;
    const float* Vg = V + (size_t)bh * SEQ * HDIM;

    const int r16 = tid >> 4;
    const int c4f = (tid & 15) << 2;
    const int kw  = (tid & 15) << 1;

#pragma unroll
    for (int u = 0; u < 8; u++) {
        const int row = r16 + u * 16;
        const float4 q = *(const float4*)(Qg + (size_t)row * HDIM + c4f);
        uint32_t h0, l0, h1, l1;
        split2(q.x * 0.125f, q.y * 0.125f, h0, l0);
        split2(q.z * 0.125f, q.w * 0.125f, h1, l1);
        const int w = row * AROWW + kw;
        *(uint2*)(sm + w) = make_uint2(h0, h1);
        *(uint2*)(sm + 2 * ABUF + w) = make_uint2(l0, l1);
    }
    __syncthreads();

    uint32_t qh[4][4], ql[4][4];
    {
        const uint32_t qa = sbase +
            (uint32_t)((wid * 16 + (mat & 1) * 8 + lr8) * 144 + (mat >> 1) * 16);
#pragma unroll
        for (int ks = 0; ks < 4; ks++) {
            ldsm4(qh[ks], qa + ks * 32);
            ldsm4(ql[ks], qa + 2 * ABUF * 4 + ks * 32);
        }
    }

    float oacc[8][4];
#pragma unroll
    for (int nf = 0; nf < 8; nf++)
#pragma unroll
        for (int e = 0; e < 4; e++) oacc[nf][e] = 0.f;
    float m0r = -INFINITY, m1r = -INFINITY, l0r = 0.f, l1r = 0.f;

    const int jbmax = 2 * qb + 1;
    const int qrow0 = qb * QT + wid * 16 + (lane >> 2);

    float4 kreg[4], vreg[4];
#pragma unroll
    for (int u = 0; u < 4; u++) {
        kreg[u] = *(const float4*)(Kg + (size_t)(r16 + u * 16) * HDIM + c4f);
        vreg[u] = *(const float4*)(Vg + (size_t)(r16 + u * 16) * HDIM + c4f);
    }
    __syncthreads();
#pragma unroll
    for (int u = 0; u < 4; u++) {
        const int w = (r16 + u * 16) * AROWW + kw;
        uint32_t h0, l0, h1, l1;
        split2(kreg[u].x, kreg[u].y, h0, l0);
        split2(kreg[u].z, kreg[u].w, h1, l1);
        *(uint2*)(sm + 0 * ABUF + w) = make_uint2(h0, h1);
        *(uint2*)(sm + 1 * ABUF + w) = make_uint2(l0, l1);
        split2(vreg[u].x, vreg[u].y, h0, l0);
        split2(vreg[u].z, vreg[u].w, h1, l1);
        *(uint2*)(sm + 2 * ABUF + w) = make_uint2(h0, h1);
        *(uint2*)(sm + 3 * ABUF + w) = make_uint2(l0, l1);
    }
    if (jbmax >= 1) {
        const float* Kt = Kg + (size_t)KT * HDIM;
        const float* Vt = Vg + (size_t)KT * HDIM;
#pragma unroll
        for (int u = 0; u < 4; u++) {
            kreg[u] = *(const float4*)(Kt + (size_t)(r16 + u * 16) * HDIM + c4f);
            vreg[u] = *(const float4*)(Vt + (size_t)(r16 + u * 16) * HDIM + c4f);
        }
    }
    __syncthreads();

    for (int jb = 0; jb <= jbmax; jb++) {
        const uint32_t pw = (uint32_t)((jb & 1) * 4 * ABUF);
        const uint32_t nw = (uint32_t)(((jb + 1) & 1) * 4 * ABUF);

        if (jb < jbmax) {
#pragma unroll
            for (int u = 0; u < 4; u++) {
                const int w = (r16 + u * 16) * AROWW + kw;
                uint32_t h0, l0, h1, l1;
                split2(kreg[u].x, kreg[u].y, h0, l0);
                split2(kreg[u].z, kreg[u].w, h1, l1);
                *(uint2*)(sm + nw + 0 * ABUF + w) = make_uint2(h0, h1);
                *(uint2*)(sm + nw + 1 * ABUF + w) = make_uint2(l0, l1);
                split2(vreg[u].x, vreg[u].y, h0, l0);
                split2(vreg[u].z, vreg[u].w, h1, l1);
                *(uint2*)(sm + nw + 2 * ABUF + w) = make_uint2(h0, h1);
                *(uint2*)(sm + nw + 3 * ABUF + w) = make_uint2(l0, l1);
            }
        }
        if (jb + 2 <= jbmax) {
            const float* Kt = Kg + (size_t)(jb + 2) * KT * HDIM;
            const float* Vt = Vg + (size_t)(jb + 2) * KT * HDIM;
#pragma unroll
            for (int u = 0; u < 4; u++) {
                kreg[u] = *(const float4*)(Kt + (size_t)(r16 + u * 16) * HDIM + c4f);
                vreg[u] = *(const float4*)(Vt + (size_t)(r16 + u * 16) * HDIM + c4f);
            }
        }

        float sacc[8][4];
#pragma unroll
        for (int nf = 0; nf < 8; nf++)
#pragma unroll
            for (int e = 0; e < 4; e++) sacc[nf][e] = 0.f;

#pragma unroll
        for (int ks = 0; ks < 4; ks++) {
#pragma unroll
            for (int np = 0; np < 4; np++) {
                uint32_t kh[4], kl[4];
                const uint32_t ka = sbase + pw * 4 +
                    (uint32_t)((np * 16 + (mat >> 1) * 8 + lr8) * 144 + ks * 32 + (mat & 1) * 16);
                ldsm4(kh, ka);
                ldsm4(kl, ka + ABUF * 4);
#pragma unroll
                for (int hh = 0; hh < 2; hh++) {
                    float* d = sacc[np * 2 + hh];
                    mma_bf16(d, qh[ks], &kh[hh * 2]);
                    mma_bf16(d, qh[ks], &kl[hh * 2]);
                    mma_bf16(d, ql[ks], &kh[hh * 2]);
                }
            }
        }

        if (jb * KT + KT - 1 > qrow0) {
#pragma unroll
            for (int nt = 0; nt < 8; nt++) {
                const int c = jb * KT + nt * 8 + ((lane & 3) << 1);
                if (c     > qrow0)     sacc[nt][0] = -INFINITY;
                if (c + 1 > qrow0)     sacc[nt][1] = -INFINITY;
                if (c     > qrow0 + 8) sacc[nt][2] = -INFINITY;
                if (c + 1 > qrow0 + 8) sacc[nt][3] = -INFINITY;
            }
        }

        float mx0 = sacc[0][0], mx1 = sacc[0][2];
#pragma unroll
        for (int nt = 0; nt < 8; nt++) {
            mx0 = fmaxf(mx0, fmaxf(sacc[nt][0], sacc[nt][1]));
            mx1 = fmaxf(mx1, fmaxf(sacc[nt][2], sacc[nt][3]));
        }
        mx0 = fmaxf(mx0, __shfl_xor_sync(~0u, mx0, 1));
        mx0 = fmaxf(mx0, __shfl_xor_sync(~0u, mx0, 2));
        mx1 = fmaxf(mx1, __shfl_xor_sync(~0u, mx1, 1));
        mx1 = fmaxf(mx1, __shfl_xor_sync(~0u, mx1, 2));
        const float mn0 = fmaxf(m0r, mx0), mn1 = fmaxf(m1r, mx1);
        const float cr0 = __expf(m0r - mn0), cr1 = __expf(m1r - mn1);
        m0r = mn0; m1r = mn1;
        float rs0 = 0.f, rs1 = 0.f;
#pragma unroll
        for (int nt = 0; nt < 8; nt++) {
            sacc[nt][0] = __expf(sacc[nt][0] - mn0);
            sacc[nt][1] = __expf(sacc[nt][1] - mn0);
            sacc[nt][2] = __expf(sacc[nt][2] - mn1);
            sacc[nt][3] = __expf(sacc[nt][3] - mn1);
            rs0 += sacc[nt][0] + sacc[nt][1];
            rs1 += sacc[nt][2] + sacc[nt][3];
        }
        rs0 += __shfl_xor_sync(~0u, rs0, 1);
        rs0 += __shfl_xor_sync(~0u, rs0, 2);
        rs1 += __shfl_xor_sync(~0u, rs1, 1);
        rs1 += __shfl_xor_sync(~0u, rs1, 2);
        l0r = l0r * cr0 + rs0;
        l1r = l1r * cr1 + rs1;
#pragma unroll
        for (int nf = 0; nf < 8; nf++) {
            oacc[nf][0] *= cr0; oacc[nf][1] *= cr0;
            oacc[nf][2] *= cr1; oacc[nf][3] *= cr1;
        }

#pragma unroll
        for (int ks = 0; ks < 4; ks++) {
            uint32_t ph[4], pl[4];
            split2(sacc[2 * ks][0],     sacc[2 * ks][1],     ph[0], pl[0]);
            split2(sacc[2 * ks][2],     sacc[2 * ks][3],     ph[1], pl[1]);
            split2(sacc[2 * ks + 1][0], sacc[2 * ks + 1][1], ph[2], pl[2]);
            split2(sacc[2 * ks + 1][2], sacc[2 * ks + 1][3], ph[3], pl[3]);
#pragma unroll
            for (int np = 0; np < 4; np++) {
                uint32_t vh[4], vl[4];
                const uint32_t va = sbase + pw * 4 + (uint32_t)(2 * ABUF * 4) +
                    (uint32_t)((ks * 16 + (mat & 1) * 8 + lr8) * 144 + np * 32 + (mat >> 1) * 16);
                ldsm4t(vh, va);
                ldsm4t(vl, va + ABUF * 4);
#pragma unroll
                for (int hh = 0; hh < 2; hh++) {
                    float* d = oacc[np * 2 + hh];
                    mma_bf16(d, ph, &vh[hh * 2]);
                    mma_bf16(d, ph, &vl[hh * 2]);
                    mma_bf16(d, pl, &vh[hh * 2]);
                }
            }
        }

        __syncthreads();
    }

    const int b = bh >> 4, h = bh & 15;
    const float inv0 = 1.f / l0r, inv1 = 1.f / l1r;
#pragma unroll
    for (int nt = 0; nt < 8; nt++) {
        const int col = h * HDIM + nt * 8 + ((lane & 3) << 1);
        *(float2*)(O + ((size_t)(b * SEQ) + qrow0) * EMB + col) =
            make_float2(oacc[nt][0] * inv0, oacc[nt][1] * inv0);
        *(float2*)(O + ((size_t)(b * SEQ) + qrow0 + 8) * EMB + col) =
            make_float2(oacc[nt][2] * inv1, oacc[nt][3] * inv1);
    }
}

// ---------------------------------------------------------------------------
extern "C" void kernel_launch(void* const* d_in, const int* in_sizes, int n_in,
                              void* d_out, int out_size)
{
    (void)in_sizes; (void)n_in; (void)out_size;
    const float* x  = (const float*)d_in[0];
    // d_in[1] = mask (causal tril, implied — unused)
    const float* Wq = (const float*)d_in[2];
    const float* bq = (const float*)d_in[3];
    const float* Wk = (const float*)d_in[4];
    const float* bk = (const float*)d_in[5];
    const float* Wv = (const float*)d_in[6];
    const float* bv = (const float*)d_in[7];
    const float* Wo = (const float*)d_in[8];
    const float* bo = (const float*)d_in[9];
    float* out = (float*)d_out;

    float *gq, *gk, *gv, *go;
    cudaGetSymbolAddress((void**)&gq, g_q);
    cudaGetSymbolAddress((void**)&gk, g_k);
    cudaGetSymbolAddress((void**)&gv, g_v);
    cudaGetSymbolAddress((void**)&go, g_o);

    cudaFuncSetAttribute(gemm_tc, cudaFuncAttributeMaxDynamicSharedMemorySize,
                         GEMM_SMEM_B);
    cudaFuncSetAttribute(attn_tc, cudaFuncAttributeMaxDynamicSharedMemorySize,
                         ATT_SMEM);

    // Q, K, V projections in ONE launch (grid.z selects weight/bias/output)
    const dim3 qkv_grid(EMB / 128, MTOT / 128, 3);  // (8, 32, 3)
    gemm_tc<<<qkv_grid, 256, GEMM_SMEM_B>>>(x, Wq, Wk, Wv, bq, bk, bv, gq, gk, gv, 1);

    const dim3 attn_grid(SEQ / QT, BATCH * NHEAD);  // (16, 32)
    attn_tc<<<attn_grid, 256, ATT_SMEM>>>(gq, gk, gv, go);

    const dim3 out_grid(EMB / 128, MTOT / 128, 1);
    gemm_tc<<<out_grid, 256, GEMM_SMEM_B>>>(go, Wo, Wo, Wo, bo, bo, bo, out, out, out, 0);
}

// round 11
// speedup vs baseline: 1.1832x; 1.0080x over previous
#include <cuda_runtime.h>
#include <cuda_bf16.h>
#include <math.h>
#include <stddef.h>
#include <stdint.h>

// Problem constants
#define NHEAD 16
#define HDIM  64
#define SEQ   2048
#define BATCH 2
#define EMB   1024
#define MTOT  (BATCH * SEQ)   // 4096

// Scratch (device globals: allocation-free, graph-capturable)
__device__ float g_q[BATCH * NHEAD * SEQ * HDIM];
__device__ float g_k[BATCH * NHEAD * SEQ * HDIM];
__device__ float g_v[BATCH * NHEAD * SEQ * HDIM];
__device__ float g_o[MTOT * EMB];

// ===========================================================================
// mma.sync helpers (arch-portable tensor core path; works at compute_103)
// ===========================================================================
__device__ __forceinline__ void mma_bf16(float* d, const uint32_t* a, const uint32_t* b) {
    asm volatile(
        "mma.sync.aligned.m16n8k16.row.col.f32.bf16.bf16.f32 "
        "{%0,%1,%2,%3}, {%4,%5,%6,%7}, {%8,%9}, {%0,%1,%2,%3};"
        : "+f"(d[0]), "+f"(d[1]), "+f"(d[2]), "+f"(d[3])
        : "r"(a[0]), "r"(a[1]), "r"(a[2]), "r"(a[3]), "r"(b[0]), "r"(b[1]));
}

__device__ __forceinline__ void ldsm4(uint32_t* r, uint32_t addr) {
    asm volatile("ldmatrix.sync.aligned.m8n8.x4.shared.b16 {%0,%1,%2,%3}, [%4];"
        : "=r"(r[0]), "=r"(r[1]), "=r"(r[2]), "=r"(r[3]) : "r"(addr));
}

__device__ __forceinline__ void ldsm4t(uint32_t* r, uint32_t addr) {
    asm volatile("ldmatrix.sync.aligned.m8n8.x4.trans.shared.b16 {%0,%1,%2,%3}, [%4];"
        : "=r"(r[0]), "=r"(r[1]), "=r"(r[2]), "=r"(r[3]) : "r"(addr));
}

__device__ __forceinline__ uint32_t smem_u32(const void* p) {
    uint32_t a;
    asm("{ .reg .u64 t; cvta.to.shared.u64 t, %1; cvt.u32.u64 %0, t; }"
        : "=r"(a) : "l"(p));
    return a;
}

// hi/lo bf16 split of 2 floats (packed into u32 each)
__device__ __forceinline__ void split2(float x, float y, uint32_t& hi, uint32_t& lo) {
    __nv_bfloat162 h = __floats2bfloat162_rn(x, y);
    float hx = __bfloat162float(h.x), hy = __bfloat162float(h.y);
    __nv_bfloat162 l = __floats2bfloat162_rn(x - hx, y - hy);
    hi = *(uint32_t*)&h;
    lo = *(uint32_t*)&l;
}

// ===========================================================================
// Tensor-core GEMM, 512 threads (16 warps, 4x4, warp tile 32x32):
// double-buffered smem, MMA-sandwiched stores, one barrier per chunk.
// ~105 regs/thread -> 16 warps/SM (4 per SMSP) for latency hiding.
// grid.z selects W/bias/C.
// ===========================================================================
#define GBK 32
#define SROWB 80
#define SROWW (SROWB / 4)
#define TILE_U32 (128 * SROWW)     // 2560 words (10240 B)
#define BUFW (4 * TILE_U32)        // 10240 words (40960 B) per parity
#define GEMM_SMEM_B (2 * BUFW * 4) // 81920 B
#define NCH (EMB / GBK)            // 32

__global__ __launch_bounds__(512, 1) void gemm_tc(
    const float* __restrict__ A,
    const float* __restrict__ W0, const float* __restrict__ W1,
    const float* __restrict__ W2,
    const float* __restrict__ bias0, const float* __restrict__ bias1,
    const float* __restrict__ bias2,
    float* __restrict__ C0, float* __restrict__ C1, float* __restrict__ C2,
    int writeQKV)
{
    extern __shared__ uint32_t sh[];

    const int z = blockIdx.z;
    const float* W = (z == 0) ? W0 : (z == 1) ? W1 : W2;
    const float* bias = (z == 0) ? bias0 : (z == 1) ? bias1 : bias2;
    float* C = (z == 0) ? C0 : (z == 1) ? C1 : C2;

    const int tid = threadIdx.x;
    const int lane = tid & 31;
    const int wid = tid >> 5;          // 0..15
    const int wm = wid & 3;            // m-group (32 rows)
    const int wn = wid >> 2;           // n-group (32 cols)
    const int m0 = blockIdx.y * 128;
    const int n0 = blockIdx.x * 128;

    // gmem staging: idx = u*512 + tid, u in {0,1}; row = idx>>3, c8 = idx&7
    const int grow0 = tid >> 3;         // 0..63 (u=1 adds 64)
    const int gc4 = (tid & 7) << 2;     // float offset in 32-wide chunk
    const int kp = (tid & 7) << 1;      // u32 word offset in smem row

    const int mat = lane >> 3, lr8 = lane & 7;
    const uint32_t sbase = smem_u32(sh);
    const uint32_t a_off = (uint32_t)((wm * 32 + (mat & 1) * 8 + lr8) * SROWB + (mat >> 1) * 16);
    const uint32_t b_off = (uint32_t)((wn * 32 + (mat >> 1) * 8 + lr8) * SROWB + (mat & 1) * 16);

    float acc[2][4][4];
#pragma unroll
    for (int mf = 0; mf < 2; mf++)
#pragma unroll
        for (int nf = 0; nf < 4; nf++)
#pragma unroll
            for (int e = 0; e < 4; e++) acc[mf][nf][e] = 0.f;

    const float* Ag = A + (size_t)m0 * EMB;
    const float* Wg = W + (size_t)n0 * EMB;

    float4 avr[2], wvr[2];

    // ---- prologue: chunk 0 -> parity 0; prefetch chunk 1 into regs ----
#pragma unroll
    for (int u = 0; u < 2; u++) {
        const int row = grow0 + u * 64;
        avr[u] = *(const float4*)(Ag + (size_t)row * EMB + gc4);
        wvr[u] = *(const float4*)(Wg + (size_t)row * EMB + gc4);
    }
#pragma unroll
    for (int u = 0; u < 2; u++) {
        const int w0 = (grow0 + u * 64) * SROWW + kp;
        uint32_t h0, l0, h1, l1;
        split2(avr[u].x, avr[u].y, h0, l0);
        split2(avr[u].z, avr[u].w, h1, l1);
        *(uint2*)(sh + w0) = make_uint2(h0, h1);
        *(uint2*)(sh + TILE_U32 + w0) = make_uint2(l0, l1);
        split2(wvr[u].x, wvr[u].y, h0, l0);
        split2(wvr[u].z, wvr[u].w, h1, l1);
        *(uint2*)(sh + 2 * TILE_U32 + w0) = make_uint2(h0, h1);
        *(uint2*)(sh + 3 * TILE_U32 + w0) = make_uint2(l0, l1);
    }
#pragma unroll
    for (int u = 0; u < 2; u++) {
        const int row = grow0 + u * 64;
        avr[u] = *(const float4*)(Ag + (size_t)row * EMB + GBK + gc4);
        wvr[u] = *(const float4*)(Wg + (size_t)row * EMB + GBK + gc4);
    }
    __syncthreads();

    for (int kk = 0; kk < NCH; kk++) {
        const uint32_t pofs = (uint32_t)((kk & 1) * BUFW);
        const uint32_t nofs = (uint32_t)(((kk + 1) & 1) * BUFW);

        const uint32_t sAh = sbase + pofs * 4 + a_off;
        const uint32_t sAl = sAh + TILE_U32 * 4;
        const uint32_t sBh = sbase + pofs * 4 + 2 * TILE_U32 * 4 + b_off;
        const uint32_t sBl = sBh + TILE_U32 * 4;

        // ---- ks = 0 MMA group ----
        {
            uint32_t ah[2][4], al[2][4], bh[2][4], bl[2][4];
#pragma unroll
            for (int mf = 0; mf < 2; mf++) {
                ldsm4(ah[mf], sAh + mf * 16 * SROWB);
                ldsm4(al[mf], sAl + mf * 16 * SROWB);
            }
#pragma unroll
            for (int np = 0; np < 2; np++) {
                ldsm4(bh[np], sBh + np * 16 * SROWB);
                ldsm4(bl[np], sBl + np * 16 * SROWB);
            }
#pragma unroll
            for (int mf = 0; mf < 2; mf++)
#pragma unroll
                for (int nf = 0; nf < 4; nf++) {
                    const int np = nf >> 1;
                    uint32_t* bhp = &bh[np][(nf & 1) * 2];
                    uint32_t* blp = &bl[np][(nf & 1) * 2];
                    mma_bf16(acc[mf][nf], ah[mf], bhp);
                    mma_bf16(acc[mf][nf], ah[mf], blp);
                    mma_bf16(acc[mf][nf], al[mf], bhp);
                }
        }

        // ---- split+STS chunk kk+1 -> other parity (sandwiched) ----
        if (kk + 1 < NCH) {
#pragma unroll
            for (int u = 0; u < 2; u++) {
                const int w0 = (grow0 + u * 64) * SROWW + kp;
                uint32_t h0, l0, h1, l1;
                split2(avr[u].x, avr[u].y, h0, l0);
                split2(avr[u].z, avr[u].w, h1, l1);
                *(uint2*)(sh + nofs + w0) = make_uint2(h0, h1);
                *(uint2*)(sh + nofs + TILE_U32 + w0) = make_uint2(l0, l1);
                split2(wvr[u].x, wvr[u].y, h0, l0);
                split2(wvr[u].z, wvr[u].w, h1, l1);
                *(uint2*)(sh + nofs + 2 * TILE_U32 + w0) = make_uint2(h0, h1);
                *(uint2*)(sh + nofs + 3 * TILE_U32 + w0) = make_uint2(l0, l1);
            }
        }

        // ---- ks = 1 MMA group ----
        {
            uint32_t ah[2][4], al[2][4], bh[2][4], bl[2][4];
#pragma unroll
            for (int mf = 0; mf < 2; mf++) {
                ldsm4(ah[mf], sAh + mf * 16 * SROWB + 32);
                ldsm4(al[mf], sAl + mf * 16 * SROWB + 32);
            }
#pragma unroll
            for (int np = 0; np < 2; np++) {
                ldsm4(bh[np], sBh + np * 16 * SROWB + 32);
                ldsm4(bl[np], sBl + np * 16 * SROWB + 32);
            }
#pragma unroll
            for (int mf = 0; mf < 2; mf++)
#pragma unroll
                for (int nf = 0; nf < 4; nf++) {
                    const int np = nf >> 1;
                    uint32_t* bhp = &bh[np][(nf & 1) * 2];
                    uint32_t* blp = &bl[np][(nf & 1) * 2];
                    mma_bf16(acc[mf][nf], ah[mf], bhp);
                    mma_bf16(acc[mf][nf], ah[mf], blp);
                    mma_bf16(acc[mf][nf], al[mf], bhp);
                }
        }

        // ---- prefetch chunk kk+2 (LDG latency hidden under next MMAs) ----
        if (kk + 2 < NCH) {
            const int kcol = (kk + 2) * GBK + gc4;
#pragma unroll
            for (int u = 0; u < 2; u++) {
                const int row = grow0 + u * 64;
                avr[u] = *(const float4*)(Ag + (size_t)row * EMB + kcol);
                wvr[u] = *(const float4*)(Wg + (size_t)row * EMB + kcol);
            }
        }

        __syncthreads();   // single barrier per chunk
    }

    // Epilogue: bias + write
#pragma unroll
    for (int mf = 0; mf < 2; mf++) {
#pragma unroll
        for (int half = 0; half < 2; half++) {
            const int m = m0 + wm * 32 + mf * 16 + (lane >> 2) + half * 8;
            const int b = m >> 11;
            const int s = m & (SEQ - 1);
#pragma unroll
            for (int nf = 0; nf < 4; nf++) {
                const int n = n0 + wn * 32 + nf * 8 + ((lane & 3) << 1);
                float2 v;
                v.x = acc[mf][nf][half * 2 + 0] + bias[n];
                v.y = acc[mf][nf][half * 2 + 1] + bias[n + 1];
                if (writeQKV) {
                    const int h = n >> 6;
                    const int d = n & 63;
                    *(float2*)(C + (((size_t)(b * NHEAD + h)) * SEQ + s) * HDIM + d) = v;
                } else {
                    *(float2*)(C + (size_t)m * EMB + n) = v;
                }
            }
        }
    }
}

// ===========================================================================
// Tensor-core causal flash attention, DOUBLE-BUFFERED K/V (round-9/10
// version, unchanged — passing at ~190us).
// ===========================================================================
#define QT 128
#define KT 64
#define AROWW 36            // u32 words per smem row (144 B)
#define ABUF (64 * AROWW)   // 2304 words (9216 B) per region
#define ATT_SMEM (8 * ABUF * 4)   // 73728 B

__global__ __launch_bounds__(256, 1) void attn_tc(
    const float* __restrict__ Q, const float* __restrict__ K,
    const float* __restrict__ V, float* __restrict__ O)
{
    extern __shared__ uint32_t sm[];
    const int tid = threadIdx.x;
    const int lane = tid & 31;
    const int wid = tid >> 5;
    const int lr8 = lane & 7;
    const int mat = lane >> 3;
    const int qb = blockIdx.x;
    const int bh = blockIdx.y;

    const uint32_t sbase = smem_u32(sm);

    const float* Qg = Q + ((size_t)bh * SEQ + (size_t)qb * QT) * HDIM;
    const float* Kg = K + (size_t)bh * SEQ * HDIM;
    const float* Vg = V + (size_t)bh * SEQ * HDIM;

    const int r16 = tid >> 4;
    const int c4f = (tid & 15) << 2;
    const int kw  = (tid & 15) << 1;

#pragma unroll
    for (int u = 0; u < 8; u++) {
        const int row = r16 + u * 16;
        const float4 q = *(const float4*)(Qg + (size_t)row * HDIM + c4f);
        uint32_t h0, l0, h1, l1;
        split2(q.x * 0.125f, q.y * 0.125f, h0, l0);
        split2(q.z * 0.125f, q.w * 0.125f, h1, l1);
        const int w = row * AROWW + kw;
        *(uint2*)(sm + w) = make_uint2(h0, h1);
        *(uint2*)(sm + 2 * ABUF + w) = make_uint2(l0, l1);
    }
    __syncthreads();

    uint32_t qh[4][4], ql[4][4];
    {
        const uint32_t qa = sbase +
            (uint32_t)((wid * 16 + (mat & 1) * 8 + lr8) * 144 + (mat >> 1) * 16);
#pragma unroll
        for (int ks = 0; ks < 4; ks++) {
            ldsm4(qh[ks], qa + ks * 32);
            ldsm4(ql[ks], qa + 2 * ABUF * 4 + ks * 32);
        }
    }

    float oacc[8][4];
#pragma unroll
    for (int nf = 0; nf < 8; nf++)
#pragma unroll
        for (int e = 0; e < 4; e++) oacc[nf][e] = 0.f;
    float m0r = -INFINITY, m1r = -INFINITY, l0r = 0.f, l1r = 0.f;

    const int jbmax = 2 * qb + 1;
    const int qrow0 = qb * QT + wid * 16 + (lane >> 2);

    float4 kreg[4], vreg[4];
#pragma unroll
    for (int u = 0; u < 4; u++) {
        kreg[u] = *(const float4*)(Kg + (size_t)(r16 + u * 16) * HDIM + c4f);
        vreg[u] = *(const float4*)(Vg + (size_t)(r16 + u * 16) * HDIM + c4f);
    }
    __syncthreads();
#pragma unroll
    for (int u = 0; u < 4; u++) {
        const int w = (r16 + u * 16) * AROWW + kw;
        uint32_t h0, l0, h1, l1;
        split2(kreg[u].x, kreg[u].y, h0, l0);
        split2(kreg[u].z, kreg[u].w, h1, l1);
        *(uint2*)(sm + 0 * ABUF + w) = make_uint2(h0, h1);
        *(uint2*)(sm + 1 * ABUF + w) = make_uint2(l0, l1);
        split2(vreg[u].x, vreg[u].y, h0, l0);
        split2(vreg[u].z, vreg[u].w, h1, l1);
        *(uint2*)(sm + 2 * ABUF + w) = make_uint2(h0, h1);
        *(uint2*)(sm + 3 * ABUF + w) = make_uint2(l0, l1);
    }
    if (jbmax >= 1) {
        const float* Kt = Kg + (size_t)KT * HDIM;
        const float* Vt = Vg + (size_t)KT * HDIM;
#pragma unroll
        for (int u = 0; u < 4; u++) {
            kreg[u] = *(const float4*)(Kt + (size_t)(r16 + u * 16) * HDIM + c4f);
            vreg[u] = *(const float4*)(Vt + (size_t)(r16 + u * 16) * HDIM + c4f);
        }
    }
    __syncthreads();

    for (int jb = 0; jb <= jbmax; jb++) {
        const uint32_t pw = (uint32_t)((jb & 1) * 4 * ABUF);
        const uint32_t nw = (uint32_t)(((jb + 1) & 1) * 4 * ABUF);

        if (jb < jbmax) {
#pragma unroll
            for (int u = 0; u < 4; u++) {
                const int w = (r16 + u * 16) * AROWW + kw;
                uint32_t h0, l0, h1, l1;
                split2(kreg[u].x, kreg[u].y, h0, l0);
                split2(kreg[u].z, kreg[u].w, h1, l1);
                *(uint2*)(sm + nw + 0 * ABUF + w) = make_uint2(h0, h1);
                *(uint2*)(sm + nw + 1 * ABUF + w) = make_uint2(l0, l1);
                split2(vreg[u].x, vreg[u].y, h0, l0);
                split2(vreg[u].z, vreg[u].w, h1, l1);
                *(uint2*)(sm + nw + 2 * ABUF + w) = make_uint2(h0, h1);
                *(uint2*)(sm + nw + 3 * ABUF + w) = make_uint2(l0, l1);
            }
        }
        if (jb + 2 <= jbmax) {
            const float* Kt = Kg + (size_t)(jb + 2) * KT * HDIM;
            const float* Vt = Vg + (size_t)(jb + 2) * KT * HDIM;
#pragma unroll
            for (int u = 0; u < 4; u++) {
                kreg[u] = *(const float4*)(Kt + (size_t)(r16 + u * 16) * HDIM + c4f);
                vreg[u] = *(const float4*)(Vt + (size_t)(r16 + u * 16) * HDIM + c4f);
            }
        }

        float sacc[8][4];
#pragma unroll
        for (int nf = 0; nf < 8; nf++)
#pragma unroll
            for (int e = 0; e < 4; e++) sacc[nf][e] = 0.f;

#pragma unroll
        for (int ks = 0; ks < 4; ks++) {
#pragma unroll
            for (int np = 0; np < 4; np++) {
                uint32_t kh[4], kl[4];
                const uint32_t ka = sbase + pw * 4 +
                    (uint32_t)((np * 16 + (mat >> 1) * 8 + lr8) * 144 + ks * 32 + (mat & 1) * 16);
                ldsm4(kh, ka);
                ldsm4(kl, ka + ABUF * 4);
#pragma unroll
                for (int hh = 0; hh < 2; hh++) {
                    float* d = sacc[np * 2 + hh];
                    mma_bf16(d, qh[ks], &kh[hh * 2]);
                    mma_bf16(d, qh[ks], &kl[hh * 2]);
                    mma_bf16(d, ql[ks], &kh[hh * 2]);
                }
            }
        }

        if (jb * KT + KT - 1 > qrow0) {
#pragma unroll
            for (int nt = 0; nt < 8; nt++) {
                const int c = jb * KT + nt * 8 + ((lane & 3) << 1);
                if (c     > qrow0)     sacc[nt][0] = -INFINITY;
                if (c + 1 > qrow0)     sacc[nt][1] = -INFINITY;
                if (c     > qrow0 + 8) sacc[nt][2] = -INFINITY;
                if (c + 1 > qrow0 + 8) sacc[nt][3] = -INFINITY;
            }
        }

        float mx0 = sacc[0][0], mx1 = sacc[0][2];
#pragma unroll
        for (int nt = 0; nt < 8; nt++) {
            mx0 = fmaxf(mx0, fmaxf(sacc[nt][0], sacc[nt][1]));
            mx1 = fmaxf(mx1, fmaxf(sacc[nt][2], sacc[nt][3]));
        }
        mx0 = fmaxf(mx0, __shfl_xor_sync(~0u, mx0, 1));
        mx0 = fmaxf(mx0, __shfl_xor_sync(~0u, mx0, 2));
        mx1 = fmaxf(mx1, __shfl_xor_sync(~0u, mx1, 1));
        mx1 = fmaxf(mx1, __shfl_xor_sync(~0u, mx1, 2));
        const float mn0 = fmaxf(m0r, mx0), mn1 = fmaxf(m1r, mx1);
        const float cr0 = __expf(m0r - mn0), cr1 = __expf(m1r - mn1);
        m0r = mn0; m1r = mn1;
        float rs0 = 0.f, rs1 = 0.f;
#pragma unroll
        for (int nt = 0; nt < 8; nt++) {
            sacc[nt][0] = __expf(sacc[nt][0] - mn0);
            sacc[nt][1] = __expf(sacc[nt][1] - mn0);
            sacc[nt][2] = __expf(sacc[nt][2] - mn1);
            sacc[nt][3] = __expf(sacc[nt][3] - mn1);
            rs0 += sacc[nt][0] + sacc[nt][1];
            rs1 += sacc[nt][2] + sacc[nt][3];
        }
        rs0 += __shfl_xor_sync(~0u, rs0, 1);
        rs0 += __shfl_xor_sync(~0u, rs0, 2);
        rs1 += __shfl_xor_sync(~0u, rs1, 1);
        rs1 += __shfl_xor_sync(~0u, rs1, 2);
        l0r = l0r * cr0 + rs0;
        l1r = l1r * cr1 + rs1;
#pragma unroll
        for (int nf = 0; nf < 8; nf++) {
            oacc[nf][0] *= cr0; oacc[nf][1] *= cr0;
            oacc[nf][2] *= cr1; oacc[nf][3] *= cr1;
        }

#pragma unroll
        for (int ks = 0; ks < 4; ks++) {
            uint32_t ph[4], pl[4];
            split2(sacc[2 * ks][0],     sacc[2 * ks][1],     ph[0], pl[0]);
            split2(sacc[2 * ks][2],     sacc[2 * ks][3],     ph[1], pl[1]);
            split2(sacc[2 * ks + 1][0], sacc[2 * ks + 1][1], ph[2], pl[2]);
            split2(sacc[2 * ks + 1][2], sacc[2 * ks + 1][3], ph[3], pl[3]);
#pragma unroll
            for (int np = 0; np < 4; np++) {
                uint32_t vh[4], vl[4];
                const uint32_t va = sbase + pw * 4 + (uint32_t)(2 * ABUF * 4) +
                    (uint32_t)((ks * 16 + (mat & 1) * 8 + lr8) * 144 + np * 32 + (mat >> 1) * 16);
                ldsm4t(vh, va);
                ldsm4t(vl, va + ABUF * 4);
#pragma unroll
                for (int hh = 0; hh < 2; hh++) {
                    float* d = oacc[np * 2 + hh];
                    mma_bf16(d, ph, &vh[hh * 2]);
                    mma_bf16(d, ph, &vl[hh * 2]);
                    mma_bf16(d, pl, &vh[hh * 2]);
                }
            }
        }

        __syncthreads();
    }

    const int b = bh >> 4, h = bh & 15;
    const float inv0 = 1.f / l0r, inv1 = 1.f / l1r;
#pragma unroll
    for (int nt = 0; nt < 8; nt++) {
        const int col = h * HDIM + nt * 8 + ((lane & 3) << 1);
        *(float2*)(O + ((size_t)(b * SEQ) + qrow0) * EMB + col) =
            make_float2(oacc[nt][0] * inv0, oacc[nt][1] * inv0);
        *(float2*)(O + ((size_t)(b * SEQ) + qrow0 + 8) * EMB + col) =
            make_float2(oacc[nt][2] * inv1, oacc[nt][3] * inv1);
    }
}

// ---------------------------------------------------------------------------
extern "C" void kernel_launch(void* const* d_in, const int* in_sizes, int n_in,
                              void* d_out, int out_size)
{
    (void)in_sizes; (void)n_in; (void)out_size;
    const float* x  = (const float*)d_in[0];
    // d_in[1] = mask (causal tril, implied — unused)
    const float* Wq = (const float*)d_in[2];
    const float* bq = (const float*)d_in[3];
    const float* Wk = (const float*)d_in[4];
    const float* bk = (const float*)d_in[5];
    const float* Wv = (const float*)d_in[6];
    const float* bv = (const float*)d_in[7];
    const float* Wo = (const float*)d_in[8];
    const float* bo = (const float*)d_in[9];
    float* out = (float*)d_out;

    float *gq, *gk, *gv, *go;
    cudaGetSymbolAddress((void**)&gq, g_q);
    cudaGetSymbolAddress((void**)&gk, g_k);
    cudaGetSymbolAddress((void**)&gv, g_v);
    cudaGetSymbolAddress((void**)&go, g_o);

    cudaFuncSetAttribute(gemm_tc, cudaFuncAttributeMaxDynamicSharedMemorySize,
                         GEMM_SMEM_B);
    cudaFuncSetAttribute(attn_tc, cudaFuncAttributeMaxDynamicSharedMemorySize,
                         ATT_SMEM);

    // Q, K, V projections in ONE launch (grid.z selects weight/bias/output)
    const dim3 qkv_grid(EMB / 128, MTOT / 128, 3);  // (8, 32, 3)
    gemm_tc<<<qkv_grid, 512, GEMM_SMEM_B>>>(x, Wq, Wk, Wv, bq, bk, bv, gq, gk, gv, 1);

    const dim3 attn_grid(SEQ / QT, BATCH * NHEAD);  // (16, 32)
    attn_tc<<<attn_grid, 256, ATT_SMEM>>>(gq, gk, gv, go);

    const dim3 out_grid(EMB / 128, MTOT / 128, 1);
    gemm_tc<<<out_grid, 512, GEMM_SMEM_B>>>(go, Wo, Wo, Wo, bo, bo, bo, out, out, out, 0);
}

// round 12
// speedup vs baseline: 1.5670x; 1.3243x over previous
#include <cuda_runtime.h>
#include <cuda_fp16.h>
#include <math.h>
#include <stddef.h>
#include <stdint.h>

// Problem constants
#define NHEAD 16
#define HDIM  64
#define SEQ   2048
#define BATCH 2
#define EMB   1024
#define MTOT  (BATCH * SEQ)   // 4096

// Scratch (device globals: allocation-free, graph-capturable)
__device__ float g_q[BATCH * NHEAD * SEQ * HDIM];
__device__ float g_k[BATCH * NHEAD * SEQ * HDIM];
__device__ float g_v[BATCH * NHEAD * SEQ * HDIM];
__device__ float g_o[MTOT * EMB];

// ===========================================================================
// mma.sync helpers (arch-portable tensor core path; works at compute_103)
// ===========================================================================
__device__ __forceinline__ void mma_fp16(float* d, const uint32_t* a, const uint32_t* b) {
    asm volatile(
        "mma.sync.aligned.m16n8k16.row.col.f32.f16.f16.f32 "
        "{%0,%1,%2,%3}, {%4,%5,%6,%7}, {%8,%9}, {%0,%1,%2,%3};"
        : "+f"(d[0]), "+f"(d[1]), "+f"(d[2]), "+f"(d[3])
        : "r"(a[0]), "r"(a[1]), "r"(a[2]), "r"(a[3]), "r"(b[0]), "r"(b[1]));
}

__device__ __forceinline__ void ldsm4(uint32_t* r, uint32_t addr) {
    asm volatile("ldmatrix.sync.aligned.m8n8.x4.shared.b16 {%0,%1,%2,%3}, [%4];"
        : "=r"(r[0]), "=r"(r[1]), "=r"(r[2]), "=r"(r[3]) : "r"(addr));
}

__device__ __forceinline__ void ldsm4t(uint32_t* r, uint32_t addr) {
    asm volatile("ldmatrix.sync.aligned.m8n8.x4.trans.shared.b16 {%0,%1,%2,%3}, [%4];"
        : "=r"(r[0]), "=r"(r[1]), "=r"(r[2]), "=r"(r[3]) : "r"(addr));
}

__device__ __forceinline__ uint32_t smem_u32(const void* p) {
    uint32_t a;
    asm("{ .reg .u64 t; cvta.to.shared.u64 t, %1; cvt.u32.u64 %0, t; }"
        : "=r"(a) : "l"(p));
    return a;
}

// fp16 hi/lo split of 2 floats (packed into u32 each): x = hi + lo + O(2^-22)
__device__ __forceinline__ void split2h(float x, float y, uint32_t& hi, uint32_t& lo) {
    __half2 h = __floats2half2_rn(x, y);
    float hx = __low2float(h), hy = __high2float(h);
    __half2 l = __floats2half2_rn(x - hx, y - hy);
    hi = *(uint32_t*)&h;
    lo = *(uint32_t*)&l;
}

// plain fp16 conversion of 2 floats packed into u32
__device__ __forceinline__ uint32_t cvt2h(float x, float y) {
    __half2 h = __floats2half2_rn(x, y);
    return *(uint32_t*)&h;
}

// ===========================================================================
// Tensor-core GEMM, fp16 2-term split: C = (Ah+Al) @ Bh^T + bias.
// 512 threads (16 warps 4x4, warp tile 32x32), double-buffered smem
// (3 tiles/parity: Ah, Al, Bh), MMA-sandwiched stores, 1 barrier/chunk.
// grid.z selects W/bias/C.
// ===========================================================================
#define GBK 32
#define SROWB 80
#define SROWW (SROWB / 4)
#define TILE_U32 (128 * SROWW)     // 2560 words (10240 B)
#define BUFW (3 * TILE_U32)        // 7680 words (30720 B) per parity
#define GEMM_SMEM_B (2 * BUFW * 4) // 61440 B
#define NCH (EMB / GBK)            // 32

__global__ __launch_bounds__(512, 1) void gemm_tc(
    const float* __restrict__ A,
    const float* __restrict__ W0, const float* __restrict__ W1,
    const float* __restrict__ W2,
    const float* __restrict__ bias0, const float* __restrict__ bias1,
    const float* __restrict__ bias2,
    float* __restrict__ C0, float* __restrict__ C1, float* __restrict__ C2,
    int writeQKV)
{
    extern __shared__ uint32_t sh[];

    const int z = blockIdx.z;
    const float* W = (z == 0) ? W0 : (z == 1) ? W1 : W2;
    const float* bias = (z == 0) ? bias0 : (z == 1) ? bias1 : bias2;
    float* C = (z == 0) ? C0 : (z == 1) ? C1 : C2;

    const int tid = threadIdx.x;
    const int lane = tid & 31;
    const int wid = tid >> 5;          // 0..15
    const int wm = wid & 3;            // m-group (32 rows)
    const int wn = wid >> 2;           // n-group (32 cols)
    const int m0 = blockIdx.y * 128;
    const int n0 = blockIdx.x * 128;

    const int grow0 = tid >> 3;         // 0..63 (u=1 adds 64)
    const int gc4 = (tid & 7) << 2;     // float offset in 32-wide chunk
    const int kp = (tid & 7) << 1;      // u32 word offset in smem row

    const int mat = lane >> 3, lr8 = lane & 7;
    const uint32_t sbase = smem_u32(sh);
    const uint32_t a_off = (uint32_t)((wm * 32 + (mat & 1) * 8 + lr8) * SROWB + (mat >> 1) * 16);
    const uint32_t b_off = (uint32_t)((wn * 32 + (mat >> 1) * 8 + lr8) * SROWB + (mat & 1) * 16);

    float acc[2][4][4];
#pragma unroll
    for (int mf = 0; mf < 2; mf++)
#pragma unroll
        for (int nf = 0; nf < 4; nf++)
#pragma unroll
            for (int e = 0; e < 4; e++) acc[mf][nf][e] = 0.f;

    const float* Ag = A + (size_t)m0 * EMB;
    const float* Wg = W + (size_t)n0 * EMB;

    float4 avr[2], wvr[2];

    // ---- prologue: chunk 0 -> parity 0; prefetch chunk 1 into regs ----
#pragma unroll
    for (int u = 0; u < 2; u++) {
        const int row = grow0 + u * 64;
        avr[u] = *(const float4*)(Ag + (size_t)row * EMB + gc4);
        wvr[u] = *(const float4*)(Wg + (size_t)row * EMB + gc4);
    }
#pragma unroll
    for (int u = 0; u < 2; u++) {
        const int w0 = (grow0 + u * 64) * SROWW + kp;
        uint32_t h0, l0, h1, l1;
        split2h(avr[u].x, avr[u].y, h0, l0);
        split2h(avr[u].z, avr[u].w, h1, l1);
        *(uint2*)(sh + w0) = make_uint2(h0, h1);
        *(uint2*)(sh + TILE_U32 + w0) = make_uint2(l0, l1);
        *(uint2*)(sh + 2 * TILE_U32 + w0) =
            make_uint2(cvt2h(wvr[u].x, wvr[u].y), cvt2h(wvr[u].z, wvr[u].w));
    }
#pragma unroll
    for (int u = 0; u < 2; u++) {
        const int row = grow0 + u * 64;
        avr[u] = *(const float4*)(Ag + (size_t)row * EMB + GBK + gc4);
        wvr[u] = *(const float4*)(Wg + (size_t)row * EMB + GBK + gc4);
    }
    __syncthreads();

    for (int kk = 0; kk < NCH; kk++) {
        const uint32_t pofs = (uint32_t)((kk & 1) * BUFW);
        const uint32_t nofs = (uint32_t)(((kk + 1) & 1) * BUFW);

        const uint32_t sAh = sbase + pofs * 4 + a_off;
        const uint32_t sAl = sAh + TILE_U32 * 4;
        const uint32_t sBh = sbase + pofs * 4 + 2 * TILE_U32 * 4 + b_off;

        // ---- ks = 0 MMA group ----
        {
            uint32_t ah[2][4], al[2][4], bh[2][4];
#pragma unroll
            for (int mf = 0; mf < 2; mf++) {
                ldsm4(ah[mf], sAh + mf * 16 * SROWB);
                ldsm4(al[mf], sAl + mf * 16 * SROWB);
            }
#pragma unroll
            for (int np = 0; np < 2; np++)
                ldsm4(bh[np], sBh + np * 16 * SROWB);
#pragma unroll
            for (int mf = 0; mf < 2; mf++)
#pragma unroll
                for (int nf = 0; nf < 4; nf++) {
                    uint32_t* bhp = &bh[nf >> 1][(nf & 1) * 2];
                    mma_fp16(acc[mf][nf], ah[mf], bhp);
                    mma_fp16(acc[mf][nf], al[mf], bhp);
                }
        }

        // ---- split+STS chunk kk+1 -> other parity (sandwiched) ----
        if (kk + 1 < NCH) {
#pragma unroll
            for (int u = 0; u < 2; u++) {
                const int w0 = (grow0 + u * 64) * SROWW + kp;
                uint32_t h0, l0, h1, l1;
                split2h(avr[u].x, avr[u].y, h0, l0);
                split2h(avr[u].z, avr[u].w, h1, l1);
                *(uint2*)(sh + nofs + w0) = make_uint2(h0, h1);
                *(uint2*)(sh + nofs + TILE_U32 + w0) = make_uint2(l0, l1);
                *(uint2*)(sh + nofs + 2 * TILE_U32 + w0) =
                    make_uint2(cvt2h(wvr[u].x, wvr[u].y), cvt2h(wvr[u].z, wvr[u].w));
            }
        }

        // ---- ks = 1 MMA group ----
        {
            uint32_t ah[2][4], al[2][4], bh[2][4];
#pragma unroll
            for (int mf = 0; mf < 2; mf++) {
                ldsm4(ah[mf], sAh + mf * 16 * SROWB + 32);
                ldsm4(al[mf], sAl + mf * 16 * SROWB + 32);
            }
#pragma unroll
            for (int np = 0; np < 2; np++)
                ldsm4(bh[np], sBh + np * 16 * SROWB + 32);
#pragma unroll
            for (int mf = 0; mf < 2; mf++)
#pragma unroll
                for (int nf = 0; nf < 4; nf++) {
                    uint32_t* bhp = &bh[nf >> 1][(nf & 1) * 2];
                    mma_fp16(acc[mf][nf], ah[mf], bhp);
                    mma_fp16(acc[mf][nf], al[mf], bhp);
                }
        }

        // ---- prefetch chunk kk+2 ----
        if (kk + 2 < NCH) {
            const int kcol = (kk + 2) * GBK + gc4;
#pragma unroll
            for (int u = 0; u < 2; u++) {
                const int row = grow0 + u * 64;
                avr[u] = *(const float4*)(Ag + (size_t)row * EMB + kcol);
                wvr[u] = *(const float4*)(Wg + (size_t)row * EMB + kcol);
            }
        }

        __syncthreads();   // single barrier per chunk
    }

    // Epilogue: bias + write
#pragma unroll
    for (int mf = 0; mf < 2; mf++) {
#pragma unroll
        for (int half = 0; half < 2; half++) {
            const int m = m0 + wm * 32 + mf * 16 + (lane >> 2) + half * 8;
            const int b = m >> 11;
            const int s = m & (SEQ - 1);
#pragma unroll
            for (int nf = 0; nf < 4; nf++) {
                const int n = n0 + wn * 32 + nf * 8 + ((lane & 3) << 1);
                float2 v;
                v.x = acc[mf][nf][half * 2 + 0] + bias[n];
                v.y = acc[mf][nf][half * 2 + 1] + bias[n + 1];
                if (writeQKV) {
                    const int h = n >> 6;
                    const int d = n & 63;
                    *(float2*)(C + (((size_t)(b * NHEAD + h)) * SEQ + s) * HDIM + d) = v;
                } else {
                    *(float2*)(C + (size_t)m * EMB + n) = v;
                }
            }
        }
    }
}

// ===========================================================================
// Tensor-core causal flash attention, fp16 2-term split, double-buffered K/V:
// 4 smem regions (Kh/Vh x 2 parities). S = (Qh+Ql)Kh, O = (Ph+Pl)Vh.
// ===========================================================================
#define QT 128
#define KT 64
#define AROWW 36            // u32 words per smem row (144 B)
#define ABUF (64 * AROWW)   // 2304 words (9216 B) per region
#define ATT_SMEM (4 * ABUF * 4)   // 36864 B

__global__ __launch_bounds__(256, 1) void attn_tc(
    const float* __restrict__ Q, const float* __restrict__ K,
    const float* __restrict__ V, float* __restrict__ O)
{
    extern __shared__ uint32_t sm[];
    const int tid = threadIdx.x;
    const int lane = tid & 31;
    const int wid = tid >> 5;
    const int lr8 = lane & 7;
    const int mat = lane >> 3;
    const int qb = blockIdx.x;
    const int bh = blockIdx.y;

    const uint32_t sbase = smem_u32(sm);

    const float* Qg = Q + ((size_t)bh * SEQ + (size_t)qb * QT) * HDIM;
    const float* Kg = K + (size_t)bh * SEQ * HDIM;
    const float* Vg = V + (size_t)bh * SEQ * HDIM;

    const int r16 = tid >> 4;
    const int c4f = (tid & 15) << 2;
    const int kwo = (tid & 15) << 1;

    // ---- stage Q (x 1/8), fp16 split: Qh -> regions 0-1, Ql -> 2-3 ----
#pragma unroll
    for (int u = 0; u < 8; u++) {
        const int row = r16 + u * 16;
        const float4 q = *(const float4*)(Qg + (size_t)row * HDIM + c4f);
        uint32_t h0, l0, h1, l1;
        split2h(q.x * 0.125f, q.y * 0.125f, h0, l0);
        split2h(q.z * 0.125f, q.w * 0.125f, h1, l1);
        const int w = row * AROWW + kwo;
        *(uint2*)(sm + w) = make_uint2(h0, h1);
        *(uint2*)(sm + 2 * ABUF + w) = make_uint2(l0, l1);
    }
    __syncthreads();

    uint32_t qh[4][4], ql[4][4];
    {
        const uint32_t qa = sbase +
            (uint32_t)((wid * 16 + (mat & 1) * 8 + lr8) * 144 + (mat >> 1) * 16);
#pragma unroll
        for (int ks = 0; ks < 4; ks++) {
            ldsm4(qh[ks], qa + ks * 32);
            ldsm4(ql[ks], qa + 2 * ABUF * 4 + ks * 32);
        }
    }

    float oacc[8][4];
#pragma unroll
    for (int nf = 0; nf < 8; nf++)
#pragma unroll
        for (int e = 0; e < 4; e++) oacc[nf][e] = 0.f;
    float m0r = -INFINITY, m1r = -INFINITY, l0r = 0.f, l1r = 0.f;

    const int jbmax = 2 * qb + 1;
    const int qrow0 = qb * QT + wid * 16 + (lane >> 2);

    // ---- prologue: tile 0 -> parity 0 {Kh@0, Vh@ABUF}; prefetch tile 1 ----
    float4 kreg[4], vreg[4];
#pragma unroll
    for (int u = 0; u < 4; u++) {
        kreg[u] = *(const float4*)(Kg + (size_t)(r16 + u * 16) * HDIM + c4f);
        vreg[u] = *(const float4*)(Vg + (size_t)(r16 + u * 16) * HDIM + c4f);
    }
    __syncthreads();   // Q ldsm complete before regions reused for K/V
#pragma unroll
    for (int u = 0; u < 4; u++) {
        const int w = (r16 + u * 16) * AROWW + kwo;
        *(uint2*)(sm + w) =
            make_uint2(cvt2h(kreg[u].x, kreg[u].y), cvt2h(kreg[u].z, kreg[u].w));
        *(uint2*)(sm + ABUF + w) =
            make_uint2(cvt2h(vreg[u].x, vreg[u].y), cvt2h(vreg[u].z, vreg[u].w));
    }
    if (jbmax >= 1) {
        const float* Kt = Kg + (size_t)KT * HDIM;
        const float* Vt = Vg + (size_t)KT * HDIM;
#pragma unroll
        for (int u = 0; u < 4; u++) {
            kreg[u] = *(const float4*)(Kt + (size_t)(r16 + u * 16) * HDIM + c4f);
            vreg[u] = *(const float4*)(Vt + (size_t)(r16 + u * 16) * HDIM + c4f);
        }
    }
    __syncthreads();

    for (int jb = 0; jb <= jbmax; jb++) {
        const uint32_t pw = (uint32_t)((jb & 1) * 2 * ABUF);
        const uint32_t nw = (uint32_t)(((jb + 1) & 1) * 2 * ABUF);

        // store tile jb+1 into opposite parity (overlaps MMA)
        if (jb < jbmax) {
#pragma unroll
            for (int u = 0; u < 4; u++) {
                const int w = (r16 + u * 16) * AROWW + kwo;
                *(uint2*)(sm + nw + w) =
                    make_uint2(cvt2h(kreg[u].x, kreg[u].y), cvt2h(kreg[u].z, kreg[u].w));
                *(uint2*)(sm + nw + ABUF + w) =
                    make_uint2(cvt2h(vreg[u].x, vreg[u].y), cvt2h(vreg[u].z, vreg[u].w));
            }
        }
        // prefetch tile jb+2
        if (jb + 2 <= jbmax) {
            const float* Kt = Kg + (size_t)(jb + 2) * KT * HDIM;
            const float* Vt = Vg + (size_t)(jb + 2) * KT * HDIM;
#pragma unroll
            for (int u = 0; u < 4; u++) {
                kreg[u] = *(const float4*)(Kt + (size_t)(r16 + u * 16) * HDIM + c4f);
                vreg[u] = *(const float4*)(Vt + (size_t)(r16 + u * 16) * HDIM + c4f);
            }
        }

        // S = (Qh+Ql) Kh^T from parity pw
        float sacc[8][4];
#pragma unroll
        for (int nf = 0; nf < 8; nf++)
#pragma unroll
            for (int e = 0; e < 4; e++) sacc[nf][e] = 0.f;

#pragma unroll
        for (int ks = 0; ks < 4; ks++) {
#pragma unroll
            for (int np = 0; np < 4; np++) {
                uint32_t kh[4];
                const uint32_t ka = sbase + pw * 4 +
                    (uint32_t)((np * 16 + (mat >> 1) * 8 + lr8) * 144 + ks * 32 + (mat & 1) * 16);
                ldsm4(kh, ka);
#pragma unroll
                for (int hh = 0; hh < 2; hh++) {
                    float* d = sacc[np * 2 + hh];
                    mma_fp16(d, qh[ks], &kh[hh * 2]);
                    mma_fp16(d, ql[ks], &kh[hh * 2]);
                }
            }
        }

        // causal mask (diagonal-band tiles only)
        if (jb * KT + KT - 1 > qrow0) {
#pragma unroll
            for (int nt = 0; nt < 8; nt++) {
                const int c = jb * KT + nt * 8 + ((lane & 3) << 1);
                if (c     > qrow0)     sacc[nt][0] = -INFINITY;
                if (c + 1 > qrow0)     sacc[nt][1] = -INFINITY;
                if (c     > qrow0 + 8) sacc[nt][2] = -INFINITY;
                if (c + 1 > qrow0 + 8) sacc[nt][3] = -INFINITY;
            }
        }

        // online softmax (rows r, r+8; reduce across 4 lanes)
        float mx0 = sacc[0][0], mx1 = sacc[0][2];
#pragma unroll
        for (int nt = 0; nt < 8; nt++) {
            mx0 = fmaxf(mx0, fmaxf(sacc[nt][0], sacc[nt][1]));
            mx1 = fmaxf(mx1, fmaxf(sacc[nt][2], sacc[nt][3]));
        }
        mx0 = fmaxf(mx0, __shfl_xor_sync(~0u, mx0, 1));
        mx0 = fmaxf(mx0, __shfl_xor_sync(~0u, mx0, 2));
        mx1 = fmaxf(mx1, __shfl_xor_sync(~0u, mx1, 1));
        mx1 = fmaxf(mx1, __shfl_xor_sync(~0u, mx1, 2));
        const float mn0 = fmaxf(m0r, mx0), mn1 = fmaxf(m1r, mx1);
        const float cr0 = __expf(m0r - mn0), cr1 = __expf(m1r - mn1);
        m0r = mn0; m1r = mn1;
        float rs0 = 0.f, rs1 = 0.f;
#pragma unroll
        for (int nt = 0; nt < 8; nt++) {
            sacc[nt][0] = __expf(sacc[nt][0] - mn0);
            sacc[nt][1] = __expf(sacc[nt][1] - mn0);
            sacc[nt][2] = __expf(sacc[nt][2] - mn1);
            sacc[nt][3] = __expf(sacc[nt][3] - mn1);
            rs0 += sacc[nt][0] + sacc[nt][1];
            rs1 += sacc[nt][2] + sacc[nt][3];
        }
        rs0 += __shfl_xor_sync(~0u, rs0, 1);
        rs0 += __shfl_xor_sync(~0u, rs0, 2);
        rs1 += __shfl_xor_sync(~0u, rs1, 1);
        rs1 += __shfl_xor_sync(~0u, rs1, 2);
        l0r = l0r * cr0 + rs0;
        l1r = l1r * cr1 + rs1;
#pragma unroll
        for (int nf = 0; nf < 8; nf++) {
            oacc[nf][0] *= cr0; oacc[nf][1] *= cr0;
            oacc[nf][2] *= cr1; oacc[nf][3] *= cr1;
        }

        // O += (Ph+Pl) Vh from parity pw
#pragma unroll
        for (int ks = 0; ks < 4; ks++) {
            uint32_t ph[4], pl[4];
            split2h(sacc[2 * ks][0],     sacc[2 * ks][1],     ph[0], pl[0]);
            split2h(sacc[2 * ks][2],     sacc[2 * ks][3],     ph[1], pl[1]);
            split2h(sacc[2 * ks + 1][0], sacc[2 * ks + 1][1], ph[2], pl[2]);
            split2h(sacc[2 * ks + 1][2], sacc[2 * ks + 1][3], ph[3], pl[3]);
#pragma unroll
            for (int np = 0; np < 4; np++) {
                uint32_t vh[4];
                const uint32_t va = sbase + pw * 4 + (uint32_t)(ABUF * 4) +
                    (uint32_t)((ks * 16 + (mat & 1) * 8 + lr8) * 144 + np * 32 + (mat >> 1) * 16);
                ldsm4t(vh, va);
#pragma unroll
                for (int hh = 0; hh < 2; hh++) {
                    float* d = oacc[np * 2 + hh];
                    mma_fp16(d, ph, &vh[hh * 2]);
                    mma_fp16(d, pl, &vh[hh * 2]);
                }
            }
        }

        __syncthreads();   // single barrier: publishes tile jb+1, retires parity pw
    }

    // epilogue: normalize, write [b, s, h*64 + d]
    const int b = bh >> 4, h = bh & 15;
    const float inv0 = 1.f / l0r, inv1 = 1.f / l1r;
#pragma unroll
    for (int nt = 0; nt < 8; nt++) {
        const int col = h * HDIM + nt * 8 + ((lane & 3) << 1);
        *(float2*)(O + ((size_t)(b * SEQ) + qrow0) * EMB + col) =
            make_float2(oacc[nt][0] * inv0, oacc[nt][1] * inv0);
        *(float2*)(O + ((size_t)(b * SEQ) + qrow0 + 8) * EMB + col) =
            make_float2(oacc[nt][2] * inv1, oacc[nt][3] * inv1);
    }
}

// ---------------------------------------------------------------------------
extern "C" void kernel_launch(void* const* d_in, const int* in_sizes, int n_in,
                              void* d_out, int out_size)
{
    (void)in_sizes; (void)n_in; (void)out_size;
    const float* x  = (const float*)d_in[0];
    // d_in[1] = mask (causal tril, implied — unused)
    const float* Wq = (const float*)d_in[2];
    const float* bq = (const float*)d_in[3];
    const float* Wk = (const float*)d_in[4];
    const float* bk = (const float*)d_in[5];
    const float* Wv = (const float*)d_in[6];
    const float* bv = (const float*)d_in[7];
    const float* Wo = (const float*)d_in[8];
    const float* bo = (const float*)d_in[9];
    float* out = (float*)d_out;

    float *gq, *gk, *gv, *go;
    cudaGetSymbolAddress((void**)&gq, g_q);
    cudaGetSymbolAddress((void**)&gk, g_k);
    cudaGetSymbolAddress((void**)&gv, g_v);
    cudaGetSymbolAddress((void**)&go, g_o);

    cudaFuncSetAttribute(gemm_tc, cudaFuncAttributeMaxDynamicSharedMemorySize,
                         GEMM_SMEM_B);
    cudaFuncSetAttribute(attn_tc, cudaFuncAttributeMaxDynamicSharedMemorySize,
                         ATT_SMEM);

    // Q, K, V projections in ONE launch (grid.z selects weight/bias/output)
    const dim3 qkv_grid(EMB / 128, MTOT / 128, 3);  // (8, 32, 3)
    gemm_tc<<<qkv_grid, 512, GEMM_SMEM_B>>>(x, Wq, Wk, Wv, bq, bk, bv, gq, gk, gv, 1);

    const dim3 attn_grid(SEQ / QT, BATCH * NHEAD);  // (16, 32)
    attn_tc<<<attn_grid, 256, ATT_SMEM>>>(gq, gk, gv, go);

    const dim3 out_grid(EMB / 128, MTOT / 128, 1);
    gemm_tc<<<out_grid, 512, GEMM_SMEM_B>>>(go, Wo, Wo, Wo, bo, bo, bo, out, out, out, 0);
}

// round 13
// speedup vs baseline: 1.6181x; 1.0326x over previous
#include <cuda_runtime.h>
#include <cuda_fp16.h>
#include <math.h>
#include <stddef.h>
#include <stdint.h>

// Problem constants
#define NHEAD 16
#define HDIM  64
#define SEQ   2048
#define BATCH 2
#define EMB   1024
#define MTOT  (BATCH * SEQ)   // 4096

// Scratch (device globals: allocation-free, graph-capturable)
__device__ float g_q[BATCH * NHEAD * SEQ * HDIM];
__device__ float g_k[BATCH * NHEAD * SEQ * HDIM];
__device__ float g_v[BATCH * NHEAD * SEQ * HDIM];
__device__ float g_o[MTOT * EMB];

// ===========================================================================
// mma.sync helpers (arch-portable tensor core path; works at compute_103)
// ===========================================================================
__device__ __forceinline__ void mma_fp16(float* d, const uint32_t* a, const uint32_t* b) {
    asm volatile(
        "mma.sync.aligned.m16n8k16.row.col.f32.f16.f16.f32 "
        "{%0,%1,%2,%3}, {%4,%5,%6,%7}, {%8,%9}, {%0,%1,%2,%3};"
        : "+f"(d[0]), "+f"(d[1]), "+f"(d[2]), "+f"(d[3])
        : "r"(a[0]), "r"(a[1]), "r"(a[2]), "r"(a[3]), "r"(b[0]), "r"(b[1]));
}

__device__ __forceinline__ void ldsm4(uint32_t* r, uint32_t addr) {
    asm volatile("ldmatrix.sync.aligned.m8n8.x4.shared.b16 {%0,%1,%2,%3}, [%4];"
        : "=r"(r[0]), "=r"(r[1]), "=r"(r[2]), "=r"(r[3]) : "r"(addr));
}

__device__ __forceinline__ void ldsm4t(uint32_t* r, uint32_t addr) {
    asm volatile("ldmatrix.sync.aligned.m8n8.x4.trans.shared.b16 {%0,%1,%2,%3}, [%4];"
        : "=r"(r[0]), "=r"(r[1]), "=r"(r[2]), "=r"(r[3]) : "r"(addr));
}

__device__ __forceinline__ uint32_t smem_u32(const void* p) {
    uint32_t a;
    asm("{ .reg .u64 t; cvta.to.shared.u64 t, %1; cvt.u32.u64 %0, t; }"
        : "=r"(a) : "l"(p));
    return a;
}

// fp16 hi/lo split of 2 floats (packed into u32 each): x = hi + lo + O(2^-22)
__device__ __forceinline__ void split2h(float x, float y, uint32_t& hi, uint32_t& lo) {
    __half2 h = __floats2half2_rn(x, y);
    float hx = __low2float(h), hy = __high2float(h);
    __half2 l = __floats2half2_rn(x - hx, y - hy);
    hi = *(uint32_t*)&h;
    lo = *(uint32_t*)&l;
}

// plain fp16 conversion of 2 floats packed into u32
__device__ __forceinline__ uint32_t cvt2h(float x, float y) {
    __half2 h = __floats2half2_rn(x, y);
    return *(uint32_t*)&h;
}

// ===========================================================================
// Tensor-core GEMM, fp16 2-term split, 256 threads (8 warps 4x2, warp tile
// 32x64 -> MMA:LDSM ratio 4.0): C = (Ah+Al) @ Bh^T + bias.
// Double-buffered smem (3 tiles/parity: Ah, Al, Bh), MMA-sandwiched stores,
// 1 barrier/chunk. grid.z selects W/bias/C.
// ===========================================================================
#define GBK 32
#define SROWB 80
#define SROWW (SROWB / 4)
#define TILE_U32 (128 * SROWW)     // 2560 words (10240 B)
#define BUFW (3 * TILE_U32)        // 7680 words (30720 B) per parity
#define GEMM_SMEM_B (2 * BUFW * 4) // 61440 B
#define NCH (EMB / GBK)            // 32

__global__ __launch_bounds__(256, 1) void gemm_tc(
    const float* __restrict__ A,
    const float* __restrict__ W0, const float* __restrict__ W1,
    const float* __restrict__ W2,
    const float* __restrict__ bias0, const float* __restrict__ bias1,
    const float* __restrict__ bias2,
    float* __restrict__ C0, float* __restrict__ C1, float* __restrict__ C2,
    int writeQKV)
{
    extern __shared__ uint32_t sh[];

    const int z = blockIdx.z;
    const float* W = (z == 0) ? W0 : (z == 1) ? W1 : W2;
    const float* bias = (z == 0) ? bias0 : (z == 1) ? bias1 : bias2;
    float* C = (z == 0) ? C0 : (z == 1) ? C1 : C2;

    const int tid = threadIdx.x;
    const int lane = tid & 31;
    const int wid = tid >> 5;          // 0..7
    const int wm = wid & 3;            // m-group (32 rows)
    const int wn = wid >> 2;           // n-group (64 cols)
    const int m0 = blockIdx.y * 128;
    const int n0 = blockIdx.x * 128;

    // gmem staging: idx = u*256+tid covers 1024 = 128 rows x 8 float4 chunks
    const int grow = tid >> 3;          // base row (0..31); rows step by 32
    const int gc4 = (tid & 7) << 2;     // float offset within 32-wide chunk
    const int kp = (tid & 7) << 1;      // u32 word offset within smem row

    const int mat = lane >> 3, lr8 = lane & 7;
    const uint32_t sbase = smem_u32(sh);
    const uint32_t a_off = (uint32_t)((wm * 32 + (mat & 1) * 8 + lr8) * SROWB + (mat >> 1) * 16);
    const uint32_t b_off = (uint32_t)((wn * 64 + (mat >> 1) * 8 + lr8) * SROWB + (mat & 1) * 16);

    float acc[2][8][4];
#pragma unroll
    for (int mf = 0; mf < 2; mf++)
#pragma unroll
        for (int nf = 0; nf < 8; nf++)
#pragma unroll
            for (int e = 0; e < 4; e++) acc[mf][nf][e] = 0.f;

    const float* Ag = A + (size_t)m0 * EMB;
    const float* Wg = W + (size_t)n0 * EMB;

    float4 avr[4], wvr[4];

    // ---- prologue: chunk 0 -> parity 0; prefetch chunk 1 into regs ----
#pragma unroll
    for (int u = 0; u < 4; u++) {
        avr[u] = *(const float4*)(Ag + (size_t)(grow + u * 32) * EMB + gc4);
        wvr[u] = *(const float4*)(Wg + (size_t)(grow + u * 32) * EMB + gc4);
    }
#pragma unroll
    for (int u = 0; u < 4; u++) {
        const int w0 = (grow + u * 32) * SROWW + kp;
        uint32_t h0, l0, h1, l1;
        split2h(avr[u].x, avr[u].y, h0, l0);
        split2h(avr[u].z, avr[u].w, h1, l1);
        *(uint2*)(sh + w0) = make_uint2(h0, h1);
        *(uint2*)(sh + TILE_U32 + w0) = make_uint2(l0, l1);
        *(uint2*)(sh + 2 * TILE_U32 + w0) =
            make_uint2(cvt2h(wvr[u].x, wvr[u].y), cvt2h(wvr[u].z, wvr[u].w));
    }
#pragma unroll
    for (int u = 0; u < 4; u++) {
        avr[u] = *(const float4*)(Ag + (size_t)(grow + u * 32) * EMB + GBK + gc4);
        wvr[u] = *(const float4*)(Wg + (size_t)(grow + u * 32) * EMB + GBK + gc4);
    }
    __syncthreads();

    for (int kk = 0; kk < NCH; kk++) {
        const uint32_t pofs = (uint32_t)((kk & 1) * BUFW);
        const uint32_t nofs = (uint32_t)(((kk + 1) & 1) * BUFW);

        const uint32_t sAh = sbase + pofs * 4 + a_off;
        const uint32_t sAl = sAh + TILE_U32 * 4;
        const uint32_t sBh = sbase + pofs * 4 + 2 * TILE_U32 * 4 + b_off;

        // ---- ks = 0 MMA group ----
        {
            uint32_t ah[2][4], al[2][4], bh[4][4];
#pragma unroll
            for (int mf = 0; mf < 2; mf++) {
                ldsm4(ah[mf], sAh + mf * 16 * SROWB);
                ldsm4(al[mf], sAl + mf * 16 * SROWB);
            }
#pragma unroll
            for (int np = 0; np < 4; np++)
                ldsm4(bh[np], sBh + np * 16 * SROWB);
#pragma unroll
            for (int mf = 0; mf < 2; mf++)
#pragma unroll
                for (int nf = 0; nf < 8; nf++) {
                    uint32_t* bhp = &bh[nf >> 1][(nf & 1) * 2];
                    mma_fp16(acc[mf][nf], ah[mf], bhp);
                    mma_fp16(acc[mf][nf], al[mf], bhp);
                }
        }

        // ---- split+STS chunk kk+1 -> other parity (sandwiched) ----
        if (kk + 1 < NCH) {
#pragma unroll
            for (int u = 0; u < 4; u++) {
                const int w0 = (grow + u * 32) * SROWW + kp;
                uint32_t h0, l0, h1, l1;
                split2h(avr[u].x, avr[u].y, h0, l0);
                split2h(avr[u].z, avr[u].w, h1, l1);
                *(uint2*)(sh + nofs + w0) = make_uint2(h0, h1);
                *(uint2*)(sh + nofs + TILE_U32 + w0) = make_uint2(l0, l1);
                *(uint2*)(sh + nofs + 2 * TILE_U32 + w0) =
                    make_uint2(cvt2h(wvr[u].x, wvr[u].y), cvt2h(wvr[u].z, wvr[u].w));
            }
        }

        // ---- ks = 1 MMA group ----
        {
            uint32_t ah[2][4], al[2][4], bh[4][4];
#pragma unroll
            for (int mf = 0; mf < 2; mf++) {
                ldsm4(ah[mf], sAh + mf * 16 * SROWB + 32);
                ldsm4(al[mf], sAl + mf * 16 * SROWB + 32);
            }
#pragma unroll
            for (int np = 0; np < 4; np++)
                ldsm4(bh[np], sBh + np * 16 * SROWB + 32);
#pragma unroll
            for (int mf = 0; mf < 2; mf++)
#pragma unroll
                for (int nf = 0; nf < 8; nf++) {
                    uint32_t* bhp = &bh[nf >> 1][(nf & 1) * 2];
                    mma_fp16(acc[mf][nf], ah[mf], bhp);
                    mma_fp16(acc[mf][nf], al[mf], bhp);
                }
        }

        // ---- prefetch chunk kk+2 ----
        if (kk + 2 < NCH) {
            const int kcol = (kk + 2) * GBK + gc4;
#pragma unroll
            for (int u = 0; u < 4; u++) {
                avr[u] = *(const float4*)(Ag + (size_t)(grow + u * 32) * EMB + kcol);
                wvr[u] = *(const float4*)(Wg + (size_t)(grow + u * 32) * EMB + kcol);
            }
        }

        __syncthreads();   // single barrier per chunk
    }

    // Epilogue: bias + write
#pragma unroll
    for (int mf = 0; mf < 2; mf++) {
#pragma unroll
        for (int half = 0; half < 2; half++) {
            const int m = m0 + wm * 32 + mf * 16 + (lane >> 2) + half * 8;
            const int b = m >> 11;
            const int s = m & (SEQ - 1);
#pragma unroll
            for (int nf = 0; nf < 8; nf++) {
                const int n = n0 + wn * 64 + nf * 8 + ((lane & 3) << 1);
                float2 v;
                v.x = acc[mf][nf][half * 2 + 0] + bias[n];
                v.y = acc[mf][nf][half * 2 + 1] + bias[n + 1];
                if (writeQKV) {
                    const int h = n >> 6;
                    const int d = n & 63;
                    *(float2*)(C + (((size_t)(b * NHEAD + h)) * SEQ + s) * HDIM + d) = v;
                } else {
                    *(float2*)(C + (size_t)m * EMB + n) = v;
                }
            }
        }
    }
}

// ===========================================================================
// Tensor-core causal flash attention, fp16 2-term split, double-buffered K/V
// (round-12 version, unchanged — passing).
// ===========================================================================
#define QT 128
#define KT 64
#define AROWW 36            // u32 words per smem row (144 B)
#define ABUF (64 * AROWW)   // 2304 words (9216 B) per region
#define ATT_SMEM (4 * ABUF * 4)   // 36864 B

__global__ __launch_bounds__(256, 1) void attn_tc(
    const float* __restrict__ Q, const float* __restrict__ K,
    const float* __restrict__ V, float* __restrict__ O)
{
    extern __shared__ uint32_t sm[];
    const int tid = threadIdx.x;
    const int lane = tid & 31;
    const int wid = tid >> 5;
    const int lr8 = lane & 7;
    const int mat = lane >> 3;
    const int qb = blockIdx.x;
    const int bh = blockIdx.y;

    const uint32_t sbase = smem_u32(sm);

    const float* Qg = Q + ((size_t)bh * SEQ + (size_t)qb * QT) * HDIM;
    const float* Kg = K + (size_t)bh * SEQ * HDIM;
    const float* Vg = V + (size_t)bh * SEQ * HDIM;

    const int r16 = tid >> 4;
    const int c4f = (tid & 15) << 2;
    const int kwo = (tid & 15) << 1;

    // ---- stage Q (x 1/8), fp16 split: Qh -> regions 0-1, Ql -> 2-3 ----
#pragma unroll
    for (int u = 0; u < 8; u++) {
        const int row = r16 + u * 16;
        const float4 q = *(const float4*)(Qg + (size_t)row * HDIM + c4f);
        uint32_t h0, l0, h1, l1;
        split2h(q.x * 0.125f, q.y * 0.125f, h0, l0);
        split2h(q.z * 0.125f, q.w * 0.125f, h1, l1);
        const int w = row * AROWW + kwo;
        *(uint2*)(sm + w) = make_uint2(h0, h1);
        *(uint2*)(sm + 2 * ABUF + w) = make_uint2(l0, l1);
    }
    __syncthreads();

    uint32_t qh[4][4], ql[4][4];
    {
        const uint32_t qa = sbase +
            (uint32_t)((wid * 16 + (mat & 1) * 8 + lr8) * 144 + (mat >> 1) * 16);
#pragma unroll
        for (int ks = 0; ks < 4; ks++) {
            ldsm4(qh[ks], qa + ks * 32);
            ldsm4(ql[ks], qa + 2 * ABUF * 4 + ks * 32);
        }
    }

    float oacc[8][4];
#pragma unroll
    for (int nf = 0; nf < 8; nf++)
#pragma unroll
        for (int e = 0; e < 4; e++) oacc[nf][e] = 0.f;
    float m0r = -INFINITY, m1r = -INFINITY, l0r = 0.f, l1r = 0.f;

    const int jbmax = 2 * qb + 1;
    const int qrow0 = qb * QT + wid * 16 + (lane >> 2);

    // ---- prologue: tile 0 -> parity 0 {Kh@0, Vh@ABUF}; prefetch tile 1 ----
    float4 kreg[4], vreg[4];
#pragma unroll
    for (int u = 0; u < 4; u++) {
        kreg[u] = *(const float4*)(Kg + (size_t)(r16 + u * 16) * HDIM + c4f);
        vreg[u] = *(const float4*)(Vg + (size_t)(r16 + u * 16) * HDIM + c4f);
    }
    __syncthreads();   // Q ldsm complete before regions reused for K/V
#pragma unroll
    for (int u = 0; u < 4; u++) {
        const int w = (r16 + u * 16) * AROWW + kwo;
        *(uint2*)(sm + w) =
            make_uint2(cvt2h(kreg[u].x, kreg[u].y), cvt2h(kreg[u].z, kreg[u].w));
        *(uint2*)(sm + ABUF + w) =
            make_uint2(cvt2h(vreg[u].x, vreg[u].y), cvt2h(vreg[u].z, vreg[u].w));
    }
    if (jbmax >= 1) {
        const float* Kt = Kg + (size_t)KT * HDIM;
        const float* Vt = Vg + (size_t)KT * HDIM;
#pragma unroll
        for (int u = 0; u < 4; u++) {
            kreg[u] = *(const float4*)(Kt + (size_t)(r16 + u * 16) * HDIM + c4f);
            vreg[u] = *(const float4*)(Vt + (size_t)(r16 + u * 16) * HDIM + c4f);
        }
    }
    __syncthreads();

    for (int jb = 0; jb <= jbmax; jb++) {
        const uint32_t pw = (uint32_t)((jb & 1) * 2 * ABUF);
        const uint32_t nw = (uint32_t)(((jb + 1) & 1) * 2 * ABUF);

        // store tile jb+1 into opposite parity (overlaps MMA)
        if (jb < jbmax) {
#pragma unroll
            for (int u = 0; u < 4; u++) {
                const int w = (r16 + u * 16) * AROWW + kwo;
                *(uint2*)(sm + nw + w) =
                    make_uint2(cvt2h(kreg[u].x, kreg[u].y), cvt2h(kreg[u].z, kreg[u].w));
                *(uint2*)(sm + nw + ABUF + w) =
                    make_uint2(cvt2h(vreg[u].x, vreg[u].y), cvt2h(vreg[u].z, vreg[u].w));
            }
        }
        // prefetch tile jb+2
        if (jb + 2 <= jbmax) {
            const float* Kt = Kg + (size_t)(jb + 2) * KT * HDIM;
            const float* Vt = Vg + (size_t)(jb + 2) * KT * HDIM;
#pragma unroll
            for (int u = 0; u < 4; u++) {
                kreg[u] = *(const float4*)(Kt + (size_t)(r16 + u * 16) * HDIM + c4f);
                vreg[u] = *(const float4*)(Vt + (size_t)(r16 + u * 16) * HDIM + c4f);
            }
        }

        // S = (Qh+Ql) Kh^T from parity pw
        float sacc[8][4];
#pragma unroll
        for (int nf = 0; nf < 8; nf++)
#pragma unroll
            for (int e = 0; e < 4; e++) sacc[nf][e] = 0.f;

#pragma unroll
        for (int ks = 0; ks < 4; ks++) {
#pragma unroll
            for (int np = 0; np < 4; np++) {
                uint32_t kh[4];
                const uint32_t ka = sbase + pw * 4 +
                    (uint32_t)((np * 16 + (mat >> 1) * 8 + lr8) * 144 + ks * 32 + (mat & 1) * 16);
                ldsm4(kh, ka);
#pragma unroll
                for (int hh = 0; hh < 2; hh++) {
                    float* d = sacc[np * 2 + hh];
                    mma_fp16(d, qh[ks], &kh[hh * 2]);
                    mma_fp16(d, ql[ks], &kh[hh * 2]);
                }
            }
        }

        // causal mask (diagonal-band tiles only)
        if (jb * KT + KT - 1 > qrow0) {
#pragma unroll
            for (int nt = 0; nt < 8; nt++) {
                const int c = jb * KT + nt * 8 + ((lane & 3) << 1);
                if (c     > qrow0)     sacc[nt][0] = -INFINITY;
                if (c + 1 > qrow0)     sacc[nt][1] = -INFINITY;
                if (c     > qrow0 + 8) sacc[nt][2] = -INFINITY;
                if (c + 1 > qrow0 + 8) sacc[nt][3] = -INFINITY;
            }
        }

        // online softmax (rows r, r+8; reduce across 4 lanes)
        float mx0 = sacc[0][0], mx1 = sacc[0][2];
#pragma unroll
        for (int nt = 0; nt < 8; nt++) {
            mx0 = fmaxf(mx0, fmaxf(sacc[nt][0], sacc[nt][1]));
            mx1 = fmaxf(mx1, fmaxf(sacc[nt][2], sacc[nt][3]));
        }
        mx0 = fmaxf(mx0, __shfl_xor_sync(~0u, mx0, 1));
        mx0 = fmaxf(mx0, __shfl_xor_sync(~0u, mx0, 2));
        mx1 = fmaxf(mx1, __shfl_xor_sync(~0u, mx1, 1));
        mx1 = fmaxf(mx1, __shfl_xor_sync(~0u, mx1, 2));
        const float mn0 = fmaxf(m0r, mx0), mn1 = fmaxf(m1r, mx1);
        const float cr0 = __expf(m0r - mn0), cr1 = __expf(m1r - mn1);
        m0r = mn0; m1r = mn1;
        float rs0 = 0.f, rs1 = 0.f;
#pragma unroll
        for (int nt = 0; nt < 8; nt++) {
            sacc[nt][0] = __expf(sacc[nt][0] - mn0);
            sacc[nt][1] = __expf(sacc[nt][1] - mn0);
            sacc[nt][2] = __expf(sacc[nt][2] - mn1);
            sacc[nt][3] = __expf(sacc[nt][3] - mn1);
            rs0 += sacc[nt][0] + sacc[nt][1];
            rs1 += sacc[nt][2] + sacc[nt][3];
        }
        rs0 += __shfl_xor_sync(~0u, rs0, 1);
        rs0 += __shfl_xor_sync(~0u, rs0, 2);
        rs1 += __shfl_xor_sync(~0u, rs1, 1);
        rs1 += __shfl_xor_sync(~0u, rs1, 2);
        l0r = l0r * cr0 + rs0;
        l1r = l1r * cr1 + rs1;
#pragma unroll
        for (int nf = 0; nf < 8; nf++) {
            oacc[nf][0] *= cr0; oacc[nf][1] *= cr0;
            oacc[nf][2] *= cr1; oacc[nf][3] *= cr1;
        }

        // O += (Ph+Pl) Vh from parity pw
#pragma unroll
        for (int ks = 0; ks < 4; ks++) {
            uint32_t ph[4], pl[4];
            split2h(sacc[2 * ks][0],     sacc[2 * ks][1],     ph[0], pl[0]);
            split2h(sacc[2 * ks][2],     sacc[2 * ks][3],     ph[1], pl[1]);
            split2h(sacc[2 * ks + 1][0], sacc[2 * ks + 1][1], ph[2], pl[2]);
            split2h(sacc[2 * ks + 1][2], sacc[2 * ks + 1][3], ph[3], pl[3]);
#pragma unroll
            for (int np = 0; np < 4; np++) {
                uint32_t vh[4];
                const uint32_t va = sbase + pw * 4 + (uint32_t)(ABUF * 4) +
                    (uint32_t)((ks * 16 + (mat & 1) * 8 + lr8) * 144 + np * 32 + (mat >> 1) * 16);
                ldsm4t(vh, va);
#pragma unroll
                for (int hh = 0; hh < 2; hh++) {
                    float* d = oacc[np * 2 + hh];
                    mma_fp16(d, ph, &vh[hh * 2]);
                    mma_fp16(d, pl, &vh[hh * 2]);
                }
            }
        }

        __syncthreads();   // single barrier: publishes tile jb+1, retires parity pw
    }

    // epilogue: normalize, write [b, s, h*64 + d]
    const int b = bh >> 4, h = bh & 15;
    const float inv0 = 1.f / l0r, inv1 = 1.f / l1r;
#pragma unroll
    for (int nt = 0; nt < 8; nt++) {
        const int col = h * HDIM + nt * 8 + ((lane & 3) << 1);
        *(float2*)(O + ((size_t)(b * SEQ) + qrow0) * EMB + col) =
            make_float2(oacc[nt][0] * inv0, oacc[nt][1] * inv0);
        *(float2*)(O + ((size_t)(b * SEQ) + qrow0 + 8) * EMB + col) =
            make_float2(oacc[nt][2] * inv1, oacc[nt][3] * inv1);
    }
}

// ---------------------------------------------------------------------------
extern "C" void kernel_launch(void* const* d_in, const int* in_sizes, int n_in,
                              void* d_out, int out_size)
{
    (void)in_sizes; (void)n_in; (void)out_size;
    const float* x  = (const float*)d_in[0];
    // d_in[1] = mask (causal tril, implied — unused)
    const float* Wq = (const float*)d_in[2];
    const float* bq = (const float*)d_in[3];
    const float* Wk = (const float*)d_in[4];
    const float* bk = (const float*)d_in[5];
    const float* Wv = (const float*)d_in[6];
    const float* bv = (const float*)d_in[7];
    const float* Wo = (const float*)d_in[8];
    const float* bo = (const float*)d_in[9];
    float* out = (float*)d_out;

    float *gq, *gk, *gv, *go;
    cudaGetSymbolAddress((void**)&gq, g_q);
    cudaGetSymbolAddress((void**)&gk, g_k);
    cudaGetSymbolAddress((void**)&gv, g_v);
    cudaGetSymbolAddress((void**)&go, g_o);

    cudaFuncSetAttribute(gemm_tc, cudaFuncAttributeMaxDynamicSharedMemorySize,
                         GEMM_SMEM_B);
    cudaFuncSetAttribute(attn_tc, cudaFuncAttributeMaxDynamicSharedMemorySize,
                         ATT_SMEM);

    // Q, K, V projections in ONE launch (grid.z selects weight/bias/output)
    const dim3 qkv_grid(EMB / 128, MTOT / 128, 3);  // (8, 32, 3)
    gemm_tc<<<qkv_grid, 256, GEMM_SMEM_B>>>(x, Wq, Wk, Wv, bq, bk, bv, gq, gk, gv, 1);

    const dim3 attn_grid(SEQ / QT, BATCH * NHEAD);  // (16, 32)
    attn_tc<<<attn_grid, 256, ATT_SMEM>>>(gq, gk, gv, go);

    const dim3 out_grid(EMB / 128, MTOT / 128, 1);
    gemm_tc<<<out_grid, 256, GEMM_SMEM_B>>>(go, Wo, Wo, Wo, bo, bo, bo, out, out, out, 0);
}

// round 14
// speedup vs baseline: 2.1581x; 1.3338x over previous
#include <cuda_runtime.h>
#include <cuda_fp16.h>
#include <math.h>
#include <stddef.h>
#include <stdint.h>

// Problem constants
#define NHEAD 16
#define HDIM  64
#define SEQ   2048
#define BATCH 2
#define EMB   1024
#define MTOT  (BATCH * SEQ)   // 4096

// Scratch (device globals: allocation-free, graph-capturable)
__device__ float g_q[BATCH * NHEAD * SEQ * HDIM];
__device__ float g_k[BATCH * NHEAD * SEQ * HDIM];
__device__ float g_v[BATCH * NHEAD * SEQ * HDIM];
__device__ float g_o[MTOT * EMB];

// ===========================================================================
// mma.sync helpers (arch-portable tensor core path; works at compute_103)
// ===========================================================================
__device__ __forceinline__ void mma_fp16(float* d, const uint32_t* a, const uint32_t* b) {
    asm volatile(
        "mma.sync.aligned.m16n8k16.row.col.f32.f16.f16.f32 "
        "{%0,%1,%2,%3}, {%4,%5,%6,%7}, {%8,%9}, {%0,%1,%2,%3};"
        : "+f"(d[0]), "+f"(d[1]), "+f"(d[2]), "+f"(d[3])
        : "r"(a[0]), "r"(a[1]), "r"(a[2]), "r"(a[3]), "r"(b[0]), "r"(b[1]));
}

__device__ __forceinline__ void ldsm4(uint32_t* r, uint32_t addr) {
    asm volatile("ldmatrix.sync.aligned.m8n8.x4.shared.b16 {%0,%1,%2,%3}, [%4];"
        : "=r"(r[0]), "=r"(r[1]), "=r"(r[2]), "=r"(r[3]) : "r"(addr));
}

__device__ __forceinline__ void ldsm4t(uint32_t* r, uint32_t addr) {
    asm volatile("ldmatrix.sync.aligned.m8n8.x4.trans.shared.b16 {%0,%1,%2,%3}, [%4];"
        : "=r"(r[0]), "=r"(r[1]), "=r"(r[2]), "=r"(r[3]) : "r"(addr));
}

__device__ __forceinline__ uint32_t smem_u32(const void* p) {
    uint32_t a;
    asm("{ .reg .u64 t; cvta.to.shared.u64 t, %1; cvt.u32.u64 %0, t; }"
        : "=r"(a) : "l"(p));
    return a;
}

// plain fp16 conversion of 2 floats packed into u32
__device__ __forceinline__ uint32_t cvt2h(float x, float y) {
    __half2 h = __floats2half2_rn(x, y);
    return *(uint32_t*)&h;
}

// ===========================================================================
// Tensor-core GEMM, single-pass fp16: C = Ah @ Bh^T + bias.
// 256 threads (8 warps 4x2, warp tile 32x64). Double-buffered smem
// (2 tiles/parity: A, B), MMA-sandwiched stores, 1 barrier/chunk.
// grid.z selects W/bias/C.
// ===========================================================================
#define GBK 32
#define SROWB 80
#define SROWW (SROWB / 4)
#define TILE_U32 (128 * SROWW)     // 2560 words (10240 B)
#define BUFW (2 * TILE_U32)        // 5120 words (20480 B) per parity
#define GEMM_SMEM_B (2 * BUFW * 4) // 40960 B
#define NCH (EMB / GBK)            // 32

__global__ __launch_bounds__(256, 1) void gemm_tc(
    const float* __restrict__ A,
    const float* __restrict__ W0, const float* __restrict__ W1,
    const float* __restrict__ W2,
    const float* __restrict__ bias0, const float* __restrict__ bias1,
    const float* __restrict__ bias2,
    float* __restrict__ C0, float* __restrict__ C1, float* __restrict__ C2,
    int writeQKV)
{
    extern __shared__ uint32_t sh[];

    const int z = blockIdx.z;
    const float* W = (z == 0) ? W0 : (z == 1) ? W1 : W2;
    const float* bias = (z == 0) ? bias0 : (z == 1) ? bias1 : bias2;
    float* C = (z == 0) ? C0 : (z == 1) ? C1 : C2;

    const int tid = threadIdx.x;
    const int lane = tid & 31;
    const int wid = tid >> 5;          // 0..7
    const int wm = wid & 3;            // m-group (32 rows)
    const int wn = wid >> 2;           // n-group (64 cols)
    const int m0 = blockIdx.y * 128;
    const int n0 = blockIdx.x * 128;

    const int grow = tid >> 3;          // base row (0..31); rows step by 32
    const int gc4 = (tid & 7) << 2;     // float offset within 32-wide chunk
    const int kp = (tid & 7) << 1;      // u32 word offset within smem row

    const int mat = lane >> 3, lr8 = lane & 7;
    const uint32_t sbase = smem_u32(sh);
    const uint32_t a_off = (uint32_t)((wm * 32 + (mat & 1) * 8 + lr8) * SROWB + (mat >> 1) * 16);
    const uint32_t b_off = (uint32_t)((wn * 64 + (mat >> 1) * 8 + lr8) * SROWB + (mat & 1) * 16);

    float acc[2][8][4];
#pragma unroll
    for (int mf = 0; mf < 2; mf++)
#pragma unroll
        for (int nf = 0; nf < 8; nf++)
#pragma unroll
            for (int e = 0; e < 4; e++) acc[mf][nf][e] = 0.f;

    const float* Ag = A + (size_t)m0 * EMB;
    const float* Wg = W + (size_t)n0 * EMB;

    float4 avr[4], wvr[4];

    // ---- prologue: chunk 0 -> parity 0; prefetch chunk 1 into regs ----
#pragma unroll
    for (int u = 0; u < 4; u++) {
        avr[u] = *(const float4*)(Ag + (size_t)(grow + u * 32) * EMB + gc4);
        wvr[u] = *(const float4*)(Wg + (size_t)(grow + u * 32) * EMB + gc4);
    }
#pragma unroll
    for (int u = 0; u < 4; u++) {
        const int w0 = (grow + u * 32) * SROWW + kp;
        *(uint2*)(sh + w0) =
            make_uint2(cvt2h(avr[u].x, avr[u].y), cvt2h(avr[u].z, avr[u].w));
        *(uint2*)(sh + TILE_U32 + w0) =
            make_uint2(cvt2h(wvr[u].x, wvr[u].y), cvt2h(wvr[u].z, wvr[u].w));
    }
#pragma unroll
    for (int u = 0; u < 4; u++) {
        avr[u] = *(const float4*)(Ag + (size_t)(grow + u * 32) * EMB + GBK + gc4);
        wvr[u] = *(const float4*)(Wg + (size_t)(grow + u * 32) * EMB + GBK + gc4);
    }
    __syncthreads();

    for (int kk = 0; kk < NCH; kk++) {
        const uint32_t pofs = (uint32_t)((kk & 1) * BUFW);
        const uint32_t nofs = (uint32_t)(((kk + 1) & 1) * BUFW);

        const uint32_t sA = sbase + pofs * 4 + a_off;
        const uint32_t sB = sbase + pofs * 4 + TILE_U32 * 4 + b_off;

        // ---- ks = 0 MMA group ----
        {
            uint32_t ah[2][4], bh[4][4];
#pragma unroll
            for (int mf = 0; mf < 2; mf++)
                ldsm4(ah[mf], sA + mf * 16 * SROWB);
#pragma unroll
            for (int np = 0; np < 4; np++)
                ldsm4(bh[np], sB + np * 16 * SROWB);
#pragma unroll
            for (int mf = 0; mf < 2; mf++)
#pragma unroll
                for (int nf = 0; nf < 8; nf++)
                    mma_fp16(acc[mf][nf], ah[mf], &bh[nf >> 1][(nf & 1) * 2]);
        }

        // ---- cvt+STS chunk kk+1 -> other parity (sandwiched) ----
        if (kk + 1 < NCH) {
#pragma unroll
            for (int u = 0; u < 4; u++) {
                const int w0 = (grow + u * 32) * SROWW + kp;
                *(uint2*)(sh + nofs + w0) =
                    make_uint2(cvt2h(avr[u].x, avr[u].y), cvt2h(avr[u].z, avr[u].w));
                *(uint2*)(sh + nofs + TILE_U32 + w0) =
                    make_uint2(cvt2h(wvr[u].x, wvr[u].y), cvt2h(wvr[u].z, wvr[u].w));
            }
        }

        // ---- ks = 1 MMA group ----
        {
            uint32_t ah[2][4], bh[4][4];
#pragma unroll
            for (int mf = 0; mf < 2; mf++)
                ldsm4(ah[mf], sA + mf * 16 * SROWB + 32);
#pragma unroll
            for (int np = 0; np < 4; np++)
                ldsm4(bh[np], sB + np * 16 * SROWB + 32);
#pragma unroll
            for (int mf = 0; mf < 2; mf++)
#pragma unroll
                for (int nf = 0; nf < 8; nf++)
                    mma_fp16(acc[mf][nf], ah[mf], &bh[nf >> 1][(nf & 1) * 2]);
        }

        // ---- prefetch chunk kk+2 ----
        if (kk + 2 < NCH) {
            const int kcol = (kk + 2) * GBK + gc4;
#pragma unroll
            for (int u = 0; u < 4; u++) {
                avr[u] = *(const float4*)(Ag + (size_t)(grow + u * 32) * EMB + kcol);
                wvr[u] = *(const float4*)(Wg + (size_t)(grow + u * 32) * EMB + kcol);
            }
        }

        __syncthreads();   // single barrier per chunk
    }

    // Epilogue: bias + write
#pragma unroll
    for (int mf = 0; mf < 2; mf++) {
#pragma unroll
        for (int half = 0; half < 2; half++) {
            const int m = m0 + wm * 32 + mf * 16 + (lane >> 2) + half * 8;
            const int b = m >> 11;
            const int s = m & (SEQ - 1);
#pragma unroll
            for (int nf = 0; nf < 8; nf++) {
                const int n = n0 + wn * 64 + nf * 8 + ((lane & 3) << 1);
                float2 v;
                v.x = acc[mf][nf][half * 2 + 0] + bias[n];
                v.y = acc[mf][nf][half * 2 + 1] + bias[n + 1];
                if (writeQKV) {
                    const int h = n >> 6;
                    const int d = n & 63;
                    *(float2*)(C + (((size_t)(b * NHEAD + h)) * SEQ + s) * HDIM + d) = v;
                } else {
                    *(float2*)(C + (size_t)m * EMB + n) = v;
                }
            }
        }
    }
}

// ===========================================================================
// Tensor-core causal flash attention, single-pass fp16, double-buffered K/V:
// S = Qh Kh^T, O += Ph Vh. 4 smem regions (Kh/Vh x 2 parities).
// ===========================================================================
#define QT 128
#define KT 64
#define AROWW 36            // u32 words per smem row (144 B)
#define ABUF (64 * AROWW)   // 2304 words (9216 B) per region
#define ATT_SMEM (4 * ABUF * 4)   // 36864 B

__global__ __launch_bounds__(256, 1) void attn_tc(
    const float* __restrict__ Q, const float* __restrict__ K,
    const float* __restrict__ V, float* __restrict__ O)
{
    extern __shared__ uint32_t sm[];
    const int tid = threadIdx.x;
    const int lane = tid & 31;
    const int wid = tid >> 5;
    const int lr8 = lane & 7;
    const int mat = lane >> 3;
    const int qb = blockIdx.x;
    const int bh = blockIdx.y;

    const uint32_t sbase = smem_u32(sm);

    const float* Qg = Q + ((size_t)bh * SEQ + (size_t)qb * QT) * HDIM;
    const float* Kg = K + (size_t)bh * SEQ * HDIM;
    const float* Vg = V + (size_t)bh * SEQ * HDIM;

    const int r16 = tid >> 4;
    const int c4f = (tid & 15) << 2;
    const int kwo = (tid & 15) << 1;

    // ---- stage Q (x 1/8) fp16 into regions 0-1, ldsm to regs ----
#pragma unroll
    for (int u = 0; u < 8; u++) {
        const int row = r16 + u * 16;
        const float4 q = *(const float4*)(Qg + (size_t)row * HDIM + c4f);
        const int w = row * AROWW + kwo;
        *(uint2*)(sm + w) = make_uint2(cvt2h(q.x * 0.125f, q.y * 0.125f),
                                       cvt2h(q.z * 0.125f, q.w * 0.125f));
    }
    __syncthreads();

    uint32_t qh[4][4];
    {
        const uint32_t qa = sbase +
            (uint32_t)((wid * 16 + (mat & 1) * 8 + lr8) * 144 + (mat >> 1) * 16);
#pragma unroll
        for (int ks = 0; ks < 4; ks++)
            ldsm4(qh[ks], qa + ks * 32);
    }

    float oacc[8][4];
#pragma unroll
    for (int nf = 0; nf < 8; nf++)
#pragma unroll
        for (int e = 0; e < 4; e++) oacc[nf][e] = 0.f;
    float m0r = -INFINITY, m1r = -INFINITY, l0r = 0.f, l1r = 0.f;

    const int jbmax = 2 * qb + 1;
    const int qrow0 = qb * QT + wid * 16 + (lane >> 2);

    // ---- prologue: tile 0 -> parity 0 {Kh@0, Vh@ABUF}; prefetch tile 1 ----
    float4 kreg[4], vreg[4];
#pragma unroll
    for (int u = 0; u < 4; u++) {
        kreg[u] = *(const float4*)(Kg + (size_t)(r16 + u * 16) * HDIM + c4f);
        vreg[u] = *(const float4*)(Vg + (size_t)(r16 + u * 16) * HDIM + c4f);
    }
    __syncthreads();   // Q ldsm complete before regions reused for K/V
#pragma unroll
    for (int u = 0; u < 4; u++) {
        const int w = (r16 + u * 16) * AROWW + kwo;
        *(uint2*)(sm + w) =
            make_uint2(cvt2h(kreg[u].x, kreg[u].y), cvt2h(kreg[u].z, kreg[u].w));
        *(uint2*)(sm + ABUF + w) =
            make_uint2(cvt2h(vreg[u].x, vreg[u].y), cvt2h(vreg[u].z, vreg[u].w));
    }
    if (jbmax >= 1) {
        const float* Kt = Kg + (size_t)KT * HDIM;
        const float* Vt = Vg + (size_t)KT * HDIM;
#pragma unroll
        for (int u = 0; u < 4; u++) {
            kreg[u] = *(const float4*)(Kt + (size_t)(r16 + u * 16) * HDIM + c4f);
            vreg[u] = *(const float4*)(Vt + (size_t)(r16 + u * 16) * HDIM + c4f);
        }
    }
    __syncthreads();

    for (int jb = 0; jb <= jbmax; jb++) {
        const uint32_t pw = (uint32_t)((jb & 1) * 2 * ABUF);
        const uint32_t nw = (uint32_t)(((jb + 1) & 1) * 2 * ABUF);

        // store tile jb+1 into opposite parity (overlaps MMA)
        if (jb < jbmax) {
#pragma unroll
            for (int u = 0; u < 4; u++) {
                const int w = (r16 + u * 16) * AROWW + kwo;
                *(uint2*)(sm + nw + w) =
                    make_uint2(cvt2h(kreg[u].x, kreg[u].y), cvt2h(kreg[u].z, kreg[u].w));
                *(uint2*)(sm + nw + ABUF + w) =
                    make_uint2(cvt2h(vreg[u].x, vreg[u].y), cvt2h(vreg[u].z, vreg[u].w));
            }
        }
        // prefetch tile jb+2
        if (jb + 2 <= jbmax) {
            const float* Kt = Kg + (size_t)(jb + 2) * KT * HDIM;
            const float* Vt = Vg + (size_t)(jb + 2) * KT * HDIM;
#pragma unroll
            for (int u = 0; u < 4; u++) {
                kreg[u] = *(const float4*)(Kt + (size_t)(r16 + u * 16) * HDIM + c4f);
                vreg[u] = *(const float4*)(Vt + (size_t)(r16 + u * 16) * HDIM + c4f);
            }
        }

        // S = Qh Kh^T from parity pw
        float sacc[8][4];
#pragma unroll
        for (int nf = 0; nf < 8; nf++)
#pragma unroll
            for (int e = 0; e < 4; e++) sacc[nf][e] = 0.f;

#pragma unroll
        for (int ks = 0; ks < 4; ks++) {
#pragma unroll
            for (int np = 0; np < 4; np++) {
                uint32_t kh[4];
                const uint32_t ka = sbase + pw * 4 +
                    (uint32_t)((np * 16 + (mat >> 1) * 8 + lr8) * 144 + ks * 32 + (mat & 1) * 16);
                ldsm4(kh, ka);
#pragma unroll
                for (int hh = 0; hh < 2; hh++)
                    mma_fp16(sacc[np * 2 + hh], qh[ks], &kh[hh * 2]);
            }
        }

        // causal mask (diagonal-band tiles only)
        if (jb * KT + KT - 1 > qrow0) {
#pragma unroll
            for (int nt = 0; nt < 8; nt++) {
                const int c = jb * KT + nt * 8 + ((lane & 3) << 1);
                if (c     > qrow0)     sacc[nt][0] = -INFINITY;
                if (c + 1 > qrow0)     sacc[nt][1] = -INFINITY;
                if (c     > qrow0 + 8) sacc[nt][2] = -INFINITY;
                if (c + 1 > qrow0 + 8) sacc[nt][3] = -INFINITY;
            }
        }

        // online softmax (rows r, r+8; reduce across 4 lanes)
        float mx0 = sacc[0][0], mx1 = sacc[0][2];
#pragma unroll
        for (int nt = 0; nt < 8; nt++) {
            mx0 = fmaxf(mx0, fmaxf(sacc[nt][0], sacc[nt][1]));
            mx1 = fmaxf(mx1, fmaxf(sacc[nt][2], sacc[nt][3]));
        }
        mx0 = fmaxf(mx0, __shfl_xor_sync(~0u, mx0, 1));
        mx0 = fmaxf(mx0, __shfl_xor_sync(~0u, mx0, 2));
        mx1 = fmaxf(mx1, __shfl_xor_sync(~0u, mx1, 1));
        mx1 = fmaxf(mx1, __shfl_xor_sync(~0u, mx1, 2));
        const float mn0 = fmaxf(m0r, mx0), mn1 = fmaxf(m1r, mx1);
        const float cr0 = __expf(m0r - mn0), cr1 = __expf(m1r - mn1);
        m0r = mn0; m1r = mn1;
        float rs0 = 0.f, rs1 = 0.f;
#pragma unroll
        for (int nt = 0; nt < 8; nt++) {
            sacc[nt][0] = __expf(sacc[nt][0] - mn0);
            sacc[nt][1] = __expf(sacc[nt][1] - mn0);
            sacc[nt][2] = __expf(sacc[nt][2] - mn1);
            sacc[nt][3] = __expf(sacc[nt][3] - mn1);
            rs0 += sacc[nt][0] + sacc[nt][1];
            rs1 += sacc[nt][2] + sacc[nt][3];
        }
        rs0 += __shfl_xor_sync(~0u, rs0, 1);
        rs0 += __shfl_xor_sync(~0u, rs0, 2);
        rs1 += __shfl_xor_sync(~0u, rs1, 1);
        rs1 += __shfl_xor_sync(~0u, rs1, 2);
        l0r = l0r * cr0 + rs0;
        l1r = l1r * cr1 + rs1;
#pragma unroll
        for (int nf = 0; nf < 8; nf++) {
            oacc[nf][0] *= cr0; oacc[nf][1] *= cr0;
            oacc[nf][2] *= cr1; oacc[nf][3] *= cr1;
        }

        // O += Ph Vh from parity pw
#pragma unroll
        for (int ks = 0; ks < 4; ks++) {
            uint32_t ph[4];
            ph[0] = cvt2h(sacc[2 * ks][0],     sacc[2 * ks][1]);
            ph[1] = cvt2h(sacc[2 * ks][2],     sacc[2 * ks][3]);
            ph[2] = cvt2h(sacc[2 * ks + 1][0], sacc[2 * ks + 1][1]);
            ph[3] = cvt2h(sacc[2 * ks + 1][2], sacc[2 * ks + 1][3]);
#pragma unroll
            for (int np = 0; np < 4; np++) {
                uint32_t vh[4];
                const uint32_t va = sbase + pw * 4 + (uint32_t)(ABUF * 4) +
                    (uint32_t)((ks * 16 + (mat & 1) * 8 + lr8) * 144 + np * 32 + (mat >> 1) * 16);
                ldsm4t(vh, va);
#pragma unroll
                for (int hh = 0; hh < 2; hh++)
                    mma_fp16(oacc[np * 2 + hh], ph, &vh[hh * 2]);
            }
        }

        __syncthreads();   // single barrier: publishes tile jb+1, retires parity pw
    }

    // epilogue: normalize, write [b, s, h*64 + d]
    const int b = bh >> 4, h = bh & 15;
    const float inv0 = 1.f / l0r, inv1 = 1.f / l1r;
#pragma unroll
    for (int nt = 0; nt < 8; nt++) {
        const int col = h * HDIM + nt * 8 + ((lane & 3) << 1);
        *(float2*)(O + ((size_t)(b * SEQ) + qrow0) * EMB + col) =
            make_float2(oacc[nt][0] * inv0, oacc[nt][1] * inv0);
        *(float2*)(O + ((size_t)(b * SEQ) + qrow0 + 8) * EMB + col) =
            make_float2(oacc[nt][2] * inv1, oacc[nt][3] * inv1);
    }
}

// ---------------------------------------------------------------------------
extern "C" void kernel_launch(void* const* d_in, const int* in_sizes, int n_in,
                              void* d_out, int out_size)
{
    (void)in_sizes; (void)n_in; (void)out_size;
    const float* x  = (const float*)d_in[0];
    // d_in[1] = mask (causal tril, implied — unused)
    const float* Wq = (const float*)d_in[2];
    const float* bq = (const float*)d_in[3];
    const float* Wk = (const float*)d_in[4];
    const float* bk = (const float*)d_in[5];
    const float* Wv = (const float*)d_in[6];
    const float* bv = (const float*)d_in[7];
    const float* Wo = (const float*)d_in[8];
    const float* bo = (const float*)d_in[9];
    float* out = (float*)d_out;

    float *gq, *gk, *gv, *go;
    cudaGetSymbolAddress((void**)&gq, g_q);
    cudaGetSymbolAddress((void**)&gk, g_k);
    cudaGetSymbolAddress((void**)&gv, g_v);
    cudaGetSymbolAddress((void**)&go, g_o);

    cudaFuncSetAttribute(gemm_tc, cudaFuncAttributeMaxDynamicSharedMemorySize,
                         GEMM_SMEM_B);
    cudaFuncSetAttribute(attn_tc, cudaFuncAttributeMaxDynamicSharedMemorySize,
                         ATT_SMEM);

    // Q, K, V projections in ONE launch (grid.z selects weight/bias/output)
    const dim3 qkv_grid(EMB / 128, MTOT / 128, 3);  // (8, 32, 3)
    gemm_tc<<<qkv_grid, 256, GEMM_SMEM_B>>>(x, Wq, Wk, Wv, bq, bk, bv, gq, gk, gv, 1);

    const dim3 attn_grid(SEQ / QT, BATCH * NHEAD);  // (16, 32)
    attn_tc<<<attn_grid, 256, ATT_SMEM>>>(gq, gk, gv, go);

    const dim3 out_grid(EMB / 128, MTOT / 128, 1);
    gemm_tc<<<out_grid, 256, GEMM_SMEM_B>>>(go, Wo, Wo, Wo, bo, bo, bo, out, out, out, 0);
}

// round 15
// speedup vs baseline: 2.2695x; 1.0516x over previous
#include <cuda_runtime.h>
#include <cuda_fp16.h>
#include <math.h>
#include <stddef.h>
#include <stdint.h>

// Problem constants
#define NHEAD 16
#define HDIM  64
#define SEQ   2048
#define BATCH 2
#define EMB   1024
#define MTOT  (BATCH * SEQ)   // 4096
#define WN    (EMB * EMB)

// Scratch (device globals: allocation-free, graph-capturable)
__device__ __half g_xh[MTOT * EMB];
__device__ __half g_wh[4 * WN];
__device__ __half g_q[BATCH * NHEAD * SEQ * HDIM];
__device__ __half g_k[BATCH * NHEAD * SEQ * HDIM];
__device__ __half g_v[BATCH * NHEAD * SEQ * HDIM];
__device__ __half g_o[MTOT * EMB];

// ===========================================================================
// mma.sync helpers
// ===========================================================================
__device__ __forceinline__ void mma_fp16(float* d, const uint32_t* a, const uint32_t* b) {
    asm volatile(
        "mma.sync.aligned.m16n8k16.row.col.f32.f16.f16.f32 "
        "{%0,%1,%2,%3}, {%4,%5,%6,%7}, {%8,%9}, {%0,%1,%2,%3};"
        : "+f"(d[0]), "+f"(d[1]), "+f"(d[2]), "+f"(d[3])
        : "r"(a[0]), "r"(a[1]), "r"(a[2]), "r"(a[3]), "r"(b[0]), "r"(b[1]));
}

__device__ __forceinline__ void ldsm4(uint32_t* r, uint32_t addr) {
    asm volatile("ldmatrix.sync.aligned.m8n8.x4.shared.b16 {%0,%1,%2,%3}, [%4];"
        : "=r"(r[0]), "=r"(r[1]), "=r"(r[2]), "=r"(r[3]) : "r"(addr));
}

__device__ __forceinline__ void ldsm4t(uint32_t* r, uint32_t addr) {
    asm volatile("ldmatrix.sync.aligned.m8n8.x4.trans.shared.b16 {%0,%1,%2,%3}, [%4];"
        : "=r"(r[0]), "=r"(r[1]), "=r"(r[2]), "=r"(r[3]) : "r"(addr));
}

__device__ __forceinline__ uint32_t smem_u32(const void* p) {
    uint32_t a;
    asm("{ .reg .u64 t; cvta.to.shared.u64 t, %1; cvt.u32.u64 %0, t; }"
        : "=r"(a) : "l"(p));
    return a;
}

__device__ __forceinline__ uint32_t cvt2h(float x, float y) {
    __half2 h = __floats2half2_rn(x, y);
    return *(uint32_t*)&h;
}

// ===========================================================================
// fp32 -> fp16 conversion (grid-stride over float4; L2-resident, ~3us)
// ===========================================================================
__global__ __launch_bounds__(256) void cvtk(
    const float* __restrict__ in, __half* __restrict__ out, int n4)
{
    const int i = blockIdx.x * blockDim.x + threadIdx.x;
    if (i < n4) {
        const float4 v = *(const float4*)(in + (size_t)i * 4);
        *(uint2*)(out + (size_t)i * 4) =
            make_uint2(cvt2h(v.x, v.y), cvt2h(v.z, v.w));
    }
}

// ===========================================================================
// Tensor-core GEMM, single-pass fp16, fp16 gmem operands:
// C = A @ W^T + bias. 256 threads (8 warps 4x2, warp tile 32x64).
// Double-buffered smem (2 tiles/parity), sandwiched pure-copy STS,
// 1 barrier/chunk. grid.z selects W/bias/output. writeQKV=1 -> half output
// scattered to [b,h,s,d], with z==0 (Q) pre-scaled by 1/8.
// ===========================================================================
#define GBK 32
#define SROWB 80
#define SROWW (SROWB / 4)
#define TILE_U32 (128 * SROWW)     // 2560 words (10240 B)
#define BUFW (2 * TILE_U32)        // per-parity words
#define GEMM_SMEM_B (2 * BUFW * 4) // 40960 B
#define NCH (EMB / GBK)            // 32

__global__ __launch_bounds__(256, 1) void gemm_tc(
    const __half* __restrict__ A,
    const __half* __restrict__ W0, const __half* __restrict__ W1,
    const __half* __restrict__ W2,
    const float* __restrict__ bias0, const float* __restrict__ bias1,
    const float* __restrict__ bias2,
    __half* __restrict__ H0, __half* __restrict__ H1, __half* __restrict__ H2,
    float* __restrict__ Fout, int writeQKV)
{
    extern __shared__ uint32_t sh[];

    const int z = blockIdx.z;
    const __half* W = (z == 0) ? W0 : (z == 1) ? W1 : W2;
    const float* bias = (z == 0) ? bias0 : (z == 1) ? bias1 : bias2;
    __half* Hc = (z == 0) ? H0 : (z == 1) ? H1 : H2;

    const int tid = threadIdx.x;
    const int lane = tid & 31;
    const int wid = tid >> 5;          // 0..7
    const int wm = wid & 3;            // m-group (32 rows)
    const int wn = wid >> 2;           // n-group (64 cols)
    const int m0 = blockIdx.y * 128;
    const int n0 = blockIdx.x * 128;

    // staging: 128 rows x 64B(32 half) per tile; thread covers 2 uint4
    const int grow = tid >> 2;          // 0..63 (it=1 adds 64)
    const int c16 = tid & 3;            // 16B chunk within row

    const int mat = lane >> 3, lr8 = lane & 7;
    const uint32_t sbase = smem_u32(sh);
    const uint32_t a_off = (uint32_t)((wm * 32 + (mat & 1) * 8 + lr8) * SROWB + (mat >> 1) * 16);
    const uint32_t b_off = (uint32_t)((wn * 64 + (mat >> 1) * 8 + lr8) * SROWB + (mat & 1) * 16);

    float acc[2][8][4];
#pragma unroll
    for (int mf = 0; mf < 2; mf++)
#pragma unroll
        for (int nf = 0; nf < 8; nf++)
#pragma unroll
            for (int e = 0; e < 4; e++) acc[mf][nf][e] = 0.f;

    const __half* Ag = A + (size_t)m0 * EMB;
    const __half* Wg = W + (size_t)n0 * EMB;

    uint4 avr[2], wvr[2];

    // ---- prologue: chunk 0 -> parity 0; prefetch chunk 1 ----
#pragma unroll
    for (int it = 0; it < 2; it++) {
        const int row = grow + it * 64;
        avr[it] = *(const uint4*)(Ag + (size_t)row * EMB + c16 * 8);
        wvr[it] = *(const uint4*)(Wg + (size_t)row * EMB + c16 * 8);
    }
#pragma unroll
    for (int it = 0; it < 2; it++) {
        const int w0 = (grow + it * 64) * SROWW + c16 * 4;
        *(uint4*)(sh + w0) = avr[it];
        *(uint4*)(sh + TILE_U32 + w0) = wvr[it];
    }
#pragma unroll
    for (int it = 0; it < 2; it++) {
        const int row = grow + it * 64;
        avr[it] = *(const uint4*)(Ag + (size_t)row * EMB + GBK + c16 * 8);
        wvr[it] = *(const uint4*)(Wg + (size_t)row * EMB + GBK + c16 * 8);
    }
    __syncthreads();

    for (int kk = 0; kk < NCH; kk++) {
        const uint32_t pofs = (uint32_t)((kk & 1) * BUFW);
        const uint32_t nofs = (uint32_t)(((kk + 1) & 1) * BUFW);

        const uint32_t sA = sbase + pofs * 4 + a_off;
        const uint32_t sB = sbase + pofs * 4 + TILE_U32 * 4 + b_off;

        // ---- ks = 0 MMA group ----
        {
            uint32_t ah[2][4], bh[4][4];
#pragma unroll
            for (int mf = 0; mf < 2; mf++)
                ldsm4(ah[mf], sA + mf * 16 * SROWB);
#pragma unroll
            for (int np = 0; np < 4; np++)
                ldsm4(bh[np], sB + np * 16 * SROWB);
#pragma unroll
            for (int mf = 0; mf < 2; mf++)
#pragma unroll
                for (int nf = 0; nf < 8; nf++)
                    mma_fp16(acc[mf][nf], ah[mf], &bh[nf >> 1][(nf & 1) * 2]);
        }

        // ---- STS chunk kk+1 (pure copy, sandwiched) ----
        if (kk + 1 < NCH) {
#pragma unroll
            for (int it = 0; it < 2; it++) {
                const int w0 = (grow + it * 64) * SROWW + c16 * 4;
                *(uint4*)(sh + nofs + w0) = avr[it];
                *(uint4*)(sh + nofs + TILE_U32 + w0) = wvr[it];
            }
        }

        // ---- ks = 1 MMA group ----
        {
            uint32_t ah[2][4], bh[4][4];
#pragma unroll
            for (int mf = 0; mf < 2; mf++)
                ldsm4(ah[mf], sA + mf * 16 * SROWB + 32);
#pragma unroll
            for (int np = 0; np < 4; np++)
                ldsm4(bh[np], sB + np * 16 * SROWB + 32);
#pragma unroll
            for (int mf = 0; mf < 2; mf++)
#pragma unroll
                for (int nf = 0; nf < 8; nf++)
                    mma_fp16(acc[mf][nf], ah[mf], &bh[nf >> 1][(nf & 1) * 2]);
        }

        // ---- prefetch chunk kk+2 ----
        if (kk + 2 < NCH) {
            const int kcol = (kk + 2) * GBK + c16 * 8;
#pragma unroll
            for (int it = 0; it < 2; it++) {
                const int row = grow + it * 64;
                avr[it] = *(const uint4*)(Ag + (size_t)row * EMB + kcol);
                wvr[it] = *(const uint4*)(Wg + (size_t)row * EMB + kcol);
            }
        }

        __syncthreads();   // single barrier per chunk
    }

    // Epilogue
    const float scl = (writeQKV && z == 0) ? 0.125f : 1.f;
#pragma unroll
    for (int mf = 0; mf < 2; mf++) {
#pragma unroll
        for (int half = 0; half < 2; half++) {
            const int m = m0 + wm * 32 + mf * 16 + (lane >> 2) + half * 8;
            const int b = m >> 11;
            const int s = m & (SEQ - 1);
#pragma unroll
            for (int nf = 0; nf < 8; nf++) {
                const int n = n0 + wn * 64 + nf * 8 + ((lane & 3) << 1);
                const float vx = (acc[mf][nf][half * 2 + 0] + bias[n]) * scl;
                const float vy = (acc[mf][nf][half * 2 + 1] + bias[n + 1]) * scl;
                if (writeQKV) {
                    const int h = n >> 6;
                    const int d = n & 63;
                    *(uint32_t*)(Hc + (((size_t)(b * NHEAD + h)) * SEQ + s) * HDIM + d)
                        = cvt2h(vx, vy);
                } else {
                    *(float2*)(Fout + (size_t)m * EMB + n) = make_float2(vx, vy);
                }
            }
        }
    }
}

// ===========================================================================
// Tensor-core causal flash attention, fp16 I/O, double-buffered K/V.
// Q pre-scaled by 1/8 in projection. Store phase = pure uint2 copies.
// ===========================================================================
#define QT 128
#define KT 64
#define AROWW 36            // u32 words per smem row (144 B)
#define ABUF (64 * AROWW)   // per-region words
#define ATT_SMEM (4 * ABUF * 4)   // 36864 B

__global__ __launch_bounds__(256, 1) void attn_tc(
    const __half* __restrict__ Q, const __half* __restrict__ K,
    const __half* __restrict__ V, __half* __restrict__ O)
{
    extern __shared__ uint32_t sm[];
    const int tid = threadIdx.x;
    const int lane = tid & 31;
    const int wid = tid >> 5;
    const int lr8 = lane & 7;
    const int mat = lane >> 3;
    const int qb = blockIdx.x;
    const int bh = blockIdx.y;

    const uint32_t sbase = smem_u32(sm);

    const __half* Qg = Q + ((size_t)bh * SEQ + (size_t)qb * QT) * HDIM;
    const __half* Kg = K + (size_t)bh * SEQ * HDIM;
    const __half* Vg = V + (size_t)bh * SEQ * HDIM;

    const int r16 = tid >> 4;
    const int hvo = (tid & 15) << 2;      // half offset within row (4 halves)
    const int kwo = (tid & 15) << 1;      // u32 word offset in smem row

    // ---- stage Q (already scaled) into regions 0-1, ldsm to regs ----
#pragma unroll
    for (int u = 0; u < 8; u++) {
        const int row = r16 + u * 16;
        const uint2 qv = *(const uint2*)(Qg + (size_t)row * HDIM + hvo);
        *(uint2*)(sm + row * AROWW + kwo) = qv;
    }
    __syncthreads();

    uint32_t qh[4][4];
    {
        const uint32_t qa = sbase +
            (uint32_t)((wid * 16 + (mat & 1) * 8 + lr8) * 144 + (mat >> 1) * 16);
#pragma unroll
        for (int ks = 0; ks < 4; ks++)
            ldsm4(qh[ks], qa + ks * 32);
    }

    float oacc[8][4];
#pragma unroll
    for (int nf = 0; nf < 8; nf++)
#pragma unroll
        for (int e = 0; e < 4; e++) oacc[nf][e] = 0.f;
    float m0r = -INFINITY, m1r = -INFINITY, l0r = 0.f, l1r = 0.f;

    const int jbmax = 2 * qb + 1;
    const int qrow0 = qb * QT + wid * 16 + (lane >> 2);

    // ---- prologue: tile 0 -> parity 0; prefetch tile 1 ----
    uint2 kreg[4], vreg[4];
#pragma unroll
    for (int u = 0; u < 4; u++) {
        kreg[u] = *(const uint2*)(Kg + (size_t)(r16 + u * 16) * HDIM + hvo);
        vreg[u] = *(const uint2*)(Vg + (size_t)(r16 + u * 16) * HDIM + hvo);
    }
    __syncthreads();   // Q ldsm complete before regions reused
#pragma unroll
    for (int u = 0; u < 4; u++) {
        const int w = (r16 + u * 16) * AROWW + kwo;
        *(uint2*)(sm + w) = kreg[u];
        *(uint2*)(sm + ABUF + w) = vreg[u];
    }
    if (jbmax >= 1) {
        const __half* Kt = Kg + (size_t)KT * HDIM;
        const __half* Vt = Vg + (size_t)KT * HDIM;
#pragma unroll
        for (int u = 0; u < 4; u++) {
            kreg[u] = *(const uint2*)(Kt + (size_t)(r16 + u * 16) * HDIM + hvo);
            vreg[u] = *(const uint2*)(Vt + (size_t)(r16 + u * 16) * HDIM + hvo);
        }
    }
    __syncthreads();

    for (int jb = 0; jb <= jbmax; jb++) {
        const uint32_t pw = (uint32_t)((jb & 1) * 2 * ABUF);
        const uint32_t nw = (uint32_t)(((jb + 1) & 1) * 2 * ABUF);

        // store tile jb+1 into opposite parity (pure copies, overlap MMA)
        if (jb < jbmax) {
#pragma unroll
            for (int u = 0; u < 4; u++) {
                const int w = (r16 + u * 16) * AROWW + kwo;
                *(uint2*)(sm + nw + w) = kreg[u];
                *(uint2*)(sm + nw + ABUF + w) = vreg[u];
            }
        }
        // prefetch tile jb+2
        if (jb + 2 <= jbmax) {
            const __half* Kt = Kg + (size_t)(jb + 2) * KT * HDIM;
            const __half* Vt = Vg + (size_t)(jb + 2) * KT * HDIM;
#pragma unroll
            for (int u = 0; u < 4; u++) {
                kreg[u] = *(const uint2*)(Kt + (size_t)(r16 + u * 16) * HDIM + hvo);
                vreg[u] = *(const uint2*)(Vt + (size_t)(r16 + u * 16) * HDIM + hvo);
            }
        }

        // S = Qh Kh^T from parity pw
        float sacc[8][4];
#pragma unroll
        for (int nf = 0; nf < 8; nf++)
#pragma unroll
            for (int e = 0; e < 4; e++) sacc[nf][e] = 0.f;

#pragma unroll
        for (int ks = 0; ks < 4; ks++) {
#pragma unroll
            for (int np = 0; np < 4; np++) {
                uint32_t kh[4];
                const uint32_t ka = sbase + pw * 4 +
                    (uint32_t)((np * 16 + (mat >> 1) * 8 + lr8) * 144 + ks * 32 + (mat & 1) * 16);
                ldsm4(kh, ka);
#pragma unroll
                for (int hh = 0; hh < 2; hh++)
                    mma_fp16(sacc[np * 2 + hh], qh[ks], &kh[hh * 2]);
            }
        }

        // causal mask (diagonal-band tiles only)
        if (jb * KT + KT - 1 > qrow0) {
#pragma unroll
            for (int nt = 0; nt < 8; nt++) {
                const int c = jb * KT + nt * 8 + ((lane & 3) << 1);
                if (c     > qrow0)     sacc[nt][0] = -INFINITY;
                if (c + 1 > qrow0)     sacc[nt][1] = -INFINITY;
                if (c     > qrow0 + 8) sacc[nt][2] = -INFINITY;
                if (c + 1 > qrow0 + 8) sacc[nt][3] = -INFINITY;
            }
        }

        // online softmax
        float mx0 = sacc[0][0], mx1 = sacc[0][2];
#pragma unroll
        for (int nt = 0; nt < 8; nt++) {
            mx0 = fmaxf(mx0, fmaxf(sacc[nt][0], sacc[nt][1]));
            mx1 = fmaxf(mx1, fmaxf(sacc[nt][2], sacc[nt][3]));
        }
        mx0 = fmaxf(mx0, __shfl_xor_sync(~0u, mx0, 1));
        mx0 = fmaxf(mx0, __shfl_xor_sync(~0u, mx0, 2));
        mx1 = fmaxf(mx1, __shfl_xor_sync(~0u, mx1, 1));
        mx1 = fmaxf(mx1, __shfl_xor_sync(~0u, mx1, 2));
        const float mn0 = fmaxf(m0r, mx0), mn1 = fmaxf(m1r, mx1);
        const float cr0 = __expf(m0r - mn0), cr1 = __expf(m1r - mn1);
        m0r = mn0; m1r = mn1;
        float rs0 = 0.f, rs1 = 0.f;
#pragma unroll
        for (int nt = 0; nt < 8; nt++) {
            sacc[nt][0] = __expf(sacc[nt][0] - mn0);
            sacc[nt][1] = __expf(sacc[nt][1] - mn0);
            sacc[nt][2] = __expf(sacc[nt][2] - mn1);
            sacc[nt][3] = __expf(sacc[nt][3] - mn1);
            rs0 += sacc[nt][0] + sacc[nt][1];
            rs1 += sacc[nt][2] + sacc[nt][3];
        }
        rs0 += __shfl_xor_sync(~0u, rs0, 1);
        rs0 += __shfl_xor_sync(~0u, rs0, 2);
        rs1 += __shfl_xor_sync(~0u, rs1, 1);
        rs1 += __shfl_xor_sync(~0u, rs1, 2);
        l0r = l0r * cr0 + rs0;
        l1r = l1r * cr1 + rs1;
#pragma unroll
        for (int nf = 0; nf < 8; nf++) {
            oacc[nf][0] *= cr0; oacc[nf][1] *= cr0;
            oacc[nf][2] *= cr1; oacc[nf][3] *= cr1;
        }

        // O += Ph Vh from parity pw
#pragma unroll
        for (int ks = 0; ks < 4; ks++) {
            uint32_t ph[4];
            ph[0] = cvt2h(sacc[2 * ks][0],     sacc[2 * ks][1]);
            ph[1] = cvt2h(sacc[2 * ks][2],     sacc[2 * ks][3]);
            ph[2] = cvt2h(sacc[2 * ks + 1][0], sacc[2 * ks + 1][1]);
            ph[3] = cvt2h(sacc[2 * ks + 1][2], sacc[2 * ks + 1][3]);
#pragma unroll
            for (int np = 0; np < 4; np++) {
                uint32_t vh[4];
                const uint32_t va = sbase + pw * 4 + (uint32_t)(ABUF * 4) +
                    (uint32_t)((ks * 16 + (mat & 1) * 8 + lr8) * 144 + np * 32 + (mat >> 1) * 16);
                ldsm4t(vh, va);
#pragma unroll
                for (int hh = 0; hh < 2; hh++)
                    mma_fp16(oacc[np * 2 + hh], ph, &vh[hh * 2]);
            }
        }

        __syncthreads();
    }

    // epilogue: normalize, write fp16 O [b, s, h*64 + d]
    const int b = bh >> 4, h = bh & 15;
    const float inv0 = 1.f / l0r, inv1 = 1.f / l1r;
#pragma unroll
    for (int nt = 0; nt < 8; nt++) {
        const int col = h * HDIM + nt * 8 + ((lane & 3) << 1);
        *(uint32_t*)(O + ((size_t)(b * SEQ) + qrow0) * EMB + col) =
            cvt2h(oacc[nt][0] * inv0, oacc[nt][1] * inv0);
        *(uint32_t*)(O + ((size_t)(b * SEQ) + qrow0 + 8) * EMB + col) =
            cvt2h(oacc[nt][2] * inv1, oacc[nt][3] * inv1);
    }
}

// ---------------------------------------------------------------------------
extern "C" void kernel_launch(void* const* d_in, const int* in_sizes, int n_in,
                              void* d_out, int out_size)
{
    (void)in_sizes; (void)n_in; (void)out_size;
    const float* x  = (const float*)d_in[0];
    // d_in[1] = mask (causal tril, implied — unused)
    const float* Wq = (const float*)d_in[2];
    const float* bq = (const float*)d_in[3];
    const float* Wk = (const float*)d_in[4];
    const float* bk = (const float*)d_in[5];
    const float* Wv = (const float*)d_in[6];
    const float* bv = (const float*)d_in[7];
    const float* Wo = (const float*)d_in[8];
    const float* bo = (const float*)d_in[9];
    float* out = (float*)d_out;

    __half *xh, *wh, *gq, *gk, *gv, *go;
    cudaGetSymbolAddress((void**)&xh, g_xh);
    cudaGetSymbolAddress((void**)&wh, g_wh);
    cudaGetSymbolAddress((void**)&gq, g_q);
    cudaGetSymbolAddress((void**)&gk, g_k);
    cudaGetSymbolAddress((void**)&gv, g_v);
    cudaGetSymbolAddress((void**)&go, g_o);

    cudaFuncSetAttribute(gemm_tc, cudaFuncAttributeMaxDynamicSharedMemorySize,
                         GEMM_SMEM_B);
    cudaFuncSetAttribute(attn_tc, cudaFuncAttributeMaxDynamicSharedMemorySize,
                         ATT_SMEM);

    // Convert inputs to fp16 once (L2-resident, cheap)
    cvtk<<<(MTOT * EMB / 4) / 256, 256>>>(x, xh, MTOT * EMB / 4);
    cvtk<<<(WN / 4) / 256, 256>>>(Wq, wh + 0 * WN, WN / 4);
    cvtk<<<(WN / 4) / 256, 256>>>(Wk, wh + 1 * WN, WN / 4);
    cvtk<<<(WN / 4) / 256, 256>>>(Wv, wh + 2 * WN, WN / 4);
    cvtk<<<(WN / 4) / 256, 256>>>(Wo, wh + 3 * WN, WN / 4);

    // Q, K, V projections in ONE launch (fp16 in, fp16 out; Q pre-scaled)
    const dim3 qkv_grid(EMB / 128, MTOT / 128, 3);  // (8, 32, 3)
    gemm_tc<<<qkv_grid, 256, GEMM_SMEM_B>>>(
        xh, wh + 0 * WN, wh + 1 * WN, wh + 2 * WN, bq, bk, bv,
        gq, gk, gv, nullptr, 1);

    const dim3 attn_grid(SEQ / QT, BATCH * NHEAD);  // (16, 32)
    attn_tc<<<attn_grid, 256, ATT_SMEM>>>(gq, gk, gv, go);

    // Output projection (fp16 in, fp32 out)
    const dim3 out_grid(EMB / 128, MTOT / 128, 1);
    gemm_tc<<<out_grid, 256, GEMM_SMEM_B>>>(
        go, wh + 3 * WN, wh + 3 * WN, wh + 3 * WN, bo, bo, bo,
        gq, gq, gq, out, 0);
}

// round 16
// speedup vs baseline: 2.3866x; 1.0516x over previous
#include <cuda_runtime.h>
#include <cuda_fp16.h>
#include <math.h>
#include <stddef.h>
#include <stdint.h>

// Problem constants
#define NHEAD 16
#define HDIM  64
#define SEQ   2048
#define BATCH 2
#define EMB   1024
#define MTOT  (BATCH * SEQ)   // 4096
#define WN    (EMB * EMB)

// Scratch (device globals: allocation-free, graph-capturable)
__device__ __half g_xh[MTOT * EMB];
__device__ __half g_wh[4 * WN];
__device__ __half g_q[BATCH * NHEAD * SEQ * HDIM];
__device__ __half g_k[BATCH * NHEAD * SEQ * HDIM];
__device__ __half g_v[BATCH * NHEAD * SEQ * HDIM];
__device__ __half g_o[MTOT * EMB];

// ===========================================================================
// mma.sync helpers
// ===========================================================================
__device__ __forceinline__ void mma_fp16(float* d, const uint32_t* a, const uint32_t* b) {
    asm volatile(
        "mma.sync.aligned.m16n8k16.row.col.f32.f16.f16.f32 "
        "{%0,%1,%2,%3}, {%4,%5,%6,%7}, {%8,%9}, {%0,%1,%2,%3};"
        : "+f"(d[0]), "+f"(d[1]), "+f"(d[2]), "+f"(d[3])
        : "r"(a[0]), "r"(a[1]), "r"(a[2]), "r"(a[3]), "r"(b[0]), "r"(b[1]));
}

__device__ __forceinline__ void ldsm4(uint32_t* r, uint32_t addr) {
    asm volatile("ldmatrix.sync.aligned.m8n8.x4.shared.b16 {%0,%1,%2,%3}, [%4];"
        : "=r"(r[0]), "=r"(r[1]), "=r"(r[2]), "=r"(r[3]) : "r"(addr));
}

__device__ __forceinline__ void ldsm4t(uint32_t* r, uint32_t addr) {
    asm volatile("ldmatrix.sync.aligned.m8n8.x4.trans.shared.b16 {%0,%1,%2,%3}, [%4];"
        : "=r"(r[0]), "=r"(r[1]), "=r"(r[2]), "=r"(r[3]) : "r"(addr));
}

__device__ __forceinline__ uint32_t smem_u32(const void* p) {
    uint32_t a;
    asm("{ .reg .u64 t; cvta.to.shared.u64 t, %1; cvt.u32.u64 %0, t; }"
        : "=r"(a) : "l"(p));
    return a;
}

__device__ __forceinline__ uint32_t cvt2h(float x, float y) {
    __half2 h = __floats2half2_rn(x, y);
    return *(uint32_t*)&h;
}

// ===========================================================================
// Fused fp32 -> fp16 conversion of x + 4 weights (ONE launch).
// Segments (in float4 units): [0, 1M) = x, then 256K each for Wq,Wk,Wv,Wo.
// ===========================================================================
#define X4   (MTOT * EMB / 4)   // 1048576
#define W4   (WN / 4)           // 262144
#define TOT4 (X4 + 4 * W4)      // 2097152

__global__ __launch_bounds__(256) void cvt_all(
    const float* __restrict__ x,
    const float* __restrict__ Wq, const float* __restrict__ Wk,
    const float* __restrict__ Wv, const float* __restrict__ Wo,
    __half* __restrict__ xh, __half* __restrict__ wh)
{
    const int i = blockIdx.x * blockDim.x + threadIdx.x;
    if (i >= TOT4) return;
    const float* src;
    __half* dst;
    if (i < X4) {
        src = x + (size_t)i * 4;
        dst = xh + (size_t)i * 4;
    } else {
        const int j = i - X4;
        const int seg = j / W4;          // 0..3
        const int off = j - seg * W4;
        const float* Ws = (seg == 0) ? Wq : (seg == 1) ? Wk : (seg == 2) ? Wv : Wo;
        src = Ws + (size_t)off * 4;
        dst = wh + (size_t)seg * WN + (size_t)off * 4;
    }
    const float4 v = *(const float4*)src;
    *(uint2*)dst = make_uint2(cvt2h(v.x, v.y), cvt2h(v.z, v.w));
}

// ===========================================================================
// Tensor-core GEMM, single-pass fp16, fp16 gmem operands (round-15 version,
// unchanged — passing). grid.z selects W/bias/output.
// ===========================================================================
#define GBK 32
#define SROWB 80
#define SROWW (SROWB / 4)
#define TILE_U32 (128 * SROWW)     // 2560 words (10240 B)
#define BUFW (2 * TILE_U32)
#define GEMM_SMEM_B (2 * BUFW * 4) // 40960 B
#define NCH (EMB / GBK)            // 32

__global__ __launch_bounds__(256, 1) void gemm_tc(
    const __half* __restrict__ A,
    const __half* __restrict__ W0, const __half* __restrict__ W1,
    const __half* __restrict__ W2,
    const float* __restrict__ bias0, const float* __restrict__ bias1,
    const float* __restrict__ bias2,
    __half* __restrict__ H0, __half* __restrict__ H1, __half* __restrict__ H2,
    float* __restrict__ Fout, int writeQKV)
{
    extern __shared__ uint32_t sh[];

    const int z = blockIdx.z;
    const __half* W = (z == 0) ? W0 : (z == 1) ? W1 : W2;
    const float* bias = (z == 0) ? bias0 : (z == 1) ? bias1 : bias2;
    __half* Hc = (z == 0) ? H0 : (z == 1) ? H1 : H2;

    const int tid = threadIdx.x;
    const int lane = tid & 31;
    const int wid = tid >> 5;
    const int wm = wid & 3;
    const int wn = wid >> 2;
    const int m0 = blockIdx.y * 128;
    const int n0 = blockIdx.x * 128;

    const int grow = tid >> 2;          // 0..63 (it=1 adds 64)
    const int c16 = tid & 3;

    const int mat = lane >> 3, lr8 = lane & 7;
    const uint32_t sbase = smem_u32(sh);
    const uint32_t a_off = (uint32_t)((wm * 32 + (mat & 1) * 8 + lr8) * SROWB + (mat >> 1) * 16);
    const uint32_t b_off = (uint32_t)((wn * 64 + (mat >> 1) * 8 + lr8) * SROWB + (mat & 1) * 16);

    float acc[2][8][4];
#pragma unroll
    for (int mf = 0; mf < 2; mf++)
#pragma unroll
        for (int nf = 0; nf < 8; nf++)
#pragma unroll
            for (int e = 0; e < 4; e++) acc[mf][nf][e] = 0.f;

    const __half* Ag = A + (size_t)m0 * EMB;
    const __half* Wg = W + (size_t)n0 * EMB;

    uint4 avr[2], wvr[2];

#pragma unroll
    for (int it = 0; it < 2; it++) {
        const int row = grow + it * 64;
        avr[it] = *(const uint4*)(Ag + (size_t)row * EMB + c16 * 8);
        wvr[it] = *(const uint4*)(Wg + (size_t)row * EMB + c16 * 8);
    }
#pragma unroll
    for (int it = 0; it < 2; it++) {
        const int w0 = (grow + it * 64) * SROWW + c16 * 4;
        *(uint4*)(sh + w0) = avr[it];
        *(uint4*)(sh + TILE_U32 + w0) = wvr[it];
    }
#pragma unroll
    for (int it = 0; it < 2; it++) {
        const int row = grow + it * 64;
        avr[it] = *(const uint4*)(Ag + (size_t)row * EMB + GBK + c16 * 8);
        wvr[it] = *(const uint4*)(Wg + (size_t)row * EMB + GBK + c16 * 8);
    }
    __syncthreads();

    for (int kk = 0; kk < NCH; kk++) {
        const uint32_t pofs = (uint32_t)((kk & 1) * BUFW);
        const uint32_t nofs = (uint32_t)(((kk + 1) & 1) * BUFW);

        const uint32_t sA = sbase + pofs * 4 + a_off;
        const uint32_t sB = sbase + pofs * 4 + TILE_U32 * 4 + b_off;

        {
            uint32_t ah[2][4], bh[4][4];
#pragma unroll
            for (int mf = 0; mf < 2; mf++)
                ldsm4(ah[mf], sA + mf * 16 * SROWB);
#pragma unroll
            for (int np = 0; np < 4; np++)
                ldsm4(bh[np], sB + np * 16 * SROWB);
#pragma unroll
            for (int mf = 0; mf < 2; mf++)
#pragma unroll
                for (int nf = 0; nf < 8; nf++)
                    mma_fp16(acc[mf][nf], ah[mf], &bh[nf >> 1][(nf & 1) * 2]);
        }

        if (kk + 1 < NCH) {
#pragma unroll
            for (int it = 0; it < 2; it++) {
                const int w0 = (grow + it * 64) * SROWW + c16 * 4;
                *(uint4*)(sh + nofs + w0) = avr[it];
                *(uint4*)(sh + nofs + TILE_U32 + w0) = wvr[it];
            }
        }

        {
            uint32_t ah[2][4], bh[4][4];
#pragma unroll
            for (int mf = 0; mf < 2; mf++)
                ldsm4(ah[mf], sA + mf * 16 * SROWB + 32);
#pragma unroll
            for (int np = 0; np < 4; np++)
                ldsm4(bh[np], sB + np * 16 * SROWB + 32);
#pragma unroll
            for (int mf = 0; mf < 2; mf++)
#pragma unroll
                for (int nf = 0; nf < 8; nf++)
                    mma_fp16(acc[mf][nf], ah[mf], &bh[nf >> 1][(nf & 1) * 2]);
        }

        if (kk + 2 < NCH) {
            const int kcol = (kk + 2) * GBK + c16 * 8;
#pragma unroll
            for (int it = 0; it < 2; it++) {
                const int row = grow + it * 64;
                avr[it] = *(const uint4*)(Ag + (size_t)row * EMB + kcol);
                wvr[it] = *(const uint4*)(Wg + (size_t)row * EMB + kcol);
            }
        }

        __syncthreads();
    }

    const float scl = (writeQKV && z == 0) ? 0.125f : 1.f;
#pragma unroll
    for (int mf = 0; mf < 2; mf++) {
#pragma unroll
        for (int half = 0; half < 2; half++) {
            const int m = m0 + wm * 32 + mf * 16 + (lane >> 2) + half * 8;
            const int b = m >> 11;
            const int s = m & (SEQ - 1);
#pragma unroll
            for (int nf = 0; nf < 8; nf++) {
                const int n = n0 + wn * 64 + nf * 8 + ((lane & 3) << 1);
                const float vx = (acc[mf][nf][half * 2 + 0] + bias[n]) * scl;
                const float vy = (acc[mf][nf][half * 2 + 1] + bias[n + 1]) * scl;
                if (writeQKV) {
                    const int h = n >> 6;
                    const int d = n & 63;
                    *(uint32_t*)(Hc + (((size_t)(b * NHEAD + h)) * SEQ + s) * HDIM + d)
                        = cvt2h(vx, vy);
                } else {
                    *(float2*)(Fout + (size_t)m * EMB + n) = make_float2(vx, vy);
                }
            }
        }
    }
}

// ===========================================================================
// Tensor-core causal flash attention, fp16 I/O, KT=128 k-tiles (halved
// per-tile softmax/barrier overhead), double-buffered K/V.
// ===========================================================================
#define QT 128
#define KT 128
#define AROWW 36            // u32 words per smem row (144 B)
#define ABUF (128 * AROWW)  // 4608 words (18432 B) per region
#define ATT_SMEM (4 * ABUF * 4)   // 73728 B

__global__ __launch_bounds__(256, 1) void attn_tc(
    const __half* __restrict__ Q, const __half* __restrict__ K,
    const __half* __restrict__ V, __half* __restrict__ O)
{
    extern __shared__ uint32_t sm[];
    const int tid = threadIdx.x;
    const int lane = tid & 31;
    const int wid = tid >> 5;
    const int lr8 = lane & 7;
    const int mat = lane >> 3;
    const int qb = blockIdx.x;
    const int bh = blockIdx.y;

    const uint32_t sbase = smem_u32(sm);

    const __half* Qg = Q + ((size_t)bh * SEQ + (size_t)qb * QT) * HDIM;
    const __half* Kg = K + (size_t)bh * SEQ * HDIM;
    const __half* Vg = V + (size_t)bh * SEQ * HDIM;

    const int r16 = tid >> 4;             // 0..15
    const int hvo = (tid & 15) << 2;      // half offset within row
    const int kwo = (tid & 15) << 1;      // u32 word offset in smem row

    // ---- stage Q (pre-scaled) into region 0, ldsm to regs ----
#pragma unroll
    for (int u = 0; u < 8; u++) {
        const int row = r16 + u * 16;
        const uint2 qv = *(const uint2*)(Qg + (size_t)row * HDIM + hvo);
        *(uint2*)(sm + row * AROWW + kwo) = qv;
    }
    __syncthreads();

    uint32_t qh[4][4];
    {
        const uint32_t qa = sbase +
            (uint32_t)((wid * 16 + (mat & 1) * 8 + lr8) * 144 + (mat >> 1) * 16);
#pragma unroll
        for (int ks = 0; ks < 4; ks++)
            ldsm4(qh[ks], qa + ks * 32);
    }

    float oacc[8][4];
#pragma unroll
    for (int nf = 0; nf < 8; nf++)
#pragma unroll
        for (int e = 0; e < 4; e++) oacc[nf][e] = 0.f;
    float m0r = -INFINITY, m1r = -INFINITY, l0r = 0.f, l1r = 0.f;

    const int jbmax = qb;
    const int qrow0 = qb * QT + wid * 16 + (lane >> 2);

    // ---- prologue: tile 0 -> parity 0; prefetch tile 1 ----
    uint2 kreg[8], vreg[8];
#pragma unroll
    for (int u = 0; u < 8; u++) {
        kreg[u] = *(const uint2*)(Kg + (size_t)(r16 + u * 16) * HDIM + hvo);
        vreg[u] = *(const uint2*)(Vg + (size_t)(r16 + u * 16) * HDIM + hvo);
    }
    __syncthreads();   // Q ldsm complete before regions reused
#pragma unroll
    for (int u = 0; u < 8; u++) {
        const int w = (r16 + u * 16) * AROWW + kwo;
        *(uint2*)(sm + w) = kreg[u];
        *(uint2*)(sm + ABUF + w) = vreg[u];
    }
    if (jbmax >= 1) {
        const __half* Kt = Kg + (size_t)KT * HDIM;
        const __half* Vt = Vg + (size_t)KT * HDIM;
#pragma unroll
        for (int u = 0; u < 8; u++) {
            kreg[u] = *(const uint2*)(Kt + (size_t)(r16 + u * 16) * HDIM + hvo);
            vreg[u] = *(const uint2*)(Vt + (size_t)(r16 + u * 16) * HDIM + hvo);
        }
    }
    __syncthreads();

    for (int jb = 0; jb <= jbmax; jb++) {
        const uint32_t pw = (uint32_t)((jb & 1) * 2 * ABUF);
        const uint32_t nw = (uint32_t)(((jb + 1) & 1) * 2 * ABUF);

        // store tile jb+1 into opposite parity (pure copies, overlap MMA)
        if (jb < jbmax) {
#pragma unroll
            for (int u = 0; u < 8; u++) {
                const int w = (r16 + u * 16) * AROWW + kwo;
                *(uint2*)(sm + nw + w) = kreg[u];
                *(uint2*)(sm + nw + ABUF + w) = vreg[u];
            }
        }
        // prefetch tile jb+2
        if (jb + 2 <= jbmax) {
            const __half* Kt = Kg + (size_t)(jb + 2) * KT * HDIM;
            const __half* Vt = Vg + (size_t)(jb + 2) * KT * HDIM;
#pragma unroll
            for (int u = 0; u < 8; u++) {
                kreg[u] = *(const uint2*)(Kt + (size_t)(r16 + u * 16) * HDIM + hvo);
                vreg[u] = *(const uint2*)(Vt + (size_t)(r16 + u * 16) * HDIM + hvo);
            }
        }

        // S = Qh Kh^T (128 cols) from parity pw
        float sacc[16][4];
#pragma unroll
        for (int nf = 0; nf < 16; nf++)
#pragma unroll
            for (int e = 0; e < 4; e++) sacc[nf][e] = 0.f;

#pragma unroll
        for (int ks = 0; ks < 4; ks++) {
#pragma unroll
            for (int np = 0; np < 8; np++) {
                uint32_t kh[4];
                const uint32_t ka = sbase + pw * 4 +
                    (uint32_t)((np * 16 + (mat >> 1) * 8 + lr8) * 144 + ks * 32 + (mat & 1) * 16);
                ldsm4(kh, ka);
#pragma unroll
                for (int hh = 0; hh < 2; hh++)
                    mma_fp16(sacc[np * 2 + hh], qh[ks], &kh[hh * 2]);
            }
        }

        // causal mask (diagonal tile jb == qb only)
        if (jb == jbmax) {
#pragma unroll
            for (int nt = 0; nt < 16; nt++) {
                const int c = jb * KT + nt * 8 + ((lane & 3) << 1);
                if (c     > qrow0)     sacc[nt][0] = -INFINITY;
                if (c + 1 > qrow0)     sacc[nt][1] = -INFINITY;
                if (c     > qrow0 + 8) sacc[nt][2] = -INFINITY;
                if (c + 1 > qrow0 + 8) sacc[nt][3] = -INFINITY;
            }
        }

        // online softmax (rows r, r+8; reduce across 4 lanes)
        float mx0 = sacc[0][0], mx1 = sacc[0][2];
#pragma unroll
        for (int nt = 0; nt < 16; nt++) {
            mx0 = fmaxf(mx0, fmaxf(sacc[nt][0], sacc[nt][1]));
            mx1 = fmaxf(mx1, fmaxf(sacc[nt][2], sacc[nt][3]));
        }
        mx0 = fmaxf(mx0, __shfl_xor_sync(~0u, mx0, 1));
        mx0 = fmaxf(mx0, __shfl_xor_sync(~0u, mx0, 2));
        mx1 = fmaxf(mx1, __shfl_xor_sync(~0u, mx1, 1));
        mx1 = fmaxf(mx1, __shfl_xor_sync(~0u, mx1, 2));
        const float mn0 = fmaxf(m0r, mx0), mn1 = fmaxf(m1r, mx1);
        const float cr0 = __expf(m0r - mn0), cr1 = __expf(m1r - mn1);
        m0r = mn0; m1r = mn1;
        float rs0 = 0.f, rs1 = 0.f;
#pragma unroll
        for (int nt = 0; nt < 16; nt++) {
            sacc[nt][0] = __expf(sacc[nt][0] - mn0);
            sacc[nt][1] = __expf(sacc[nt][1] - mn0);
            sacc[nt][2] = __expf(sacc[nt][2] - mn1);
            sacc[nt][3] = __expf(sacc[nt][3] - mn1);
            rs0 += sacc[nt][0] + sacc[nt][1];
            rs1 += sacc[nt][2] + sacc[nt][3];
        }
        rs0 += __shfl_xor_sync(~0u, rs0, 1);
        rs0 += __shfl_xor_sync(~0u, rs0, 2);
        rs1 += __shfl_xor_sync(~0u, rs1, 1);
        rs1 += __shfl_xor_sync(~0u, rs1, 2);
        l0r = l0r * cr0 + rs0;
        l1r = l1r * cr1 + rs1;
#pragma unroll
        for (int nf = 0; nf < 8; nf++) {
            oacc[nf][0] *= cr0; oacc[nf][1] *= cr0;
            oacc[nf][2] *= cr1; oacc[nf][3] *= cr1;
        }

        // O += Ph Vh (128 rows of V) from parity pw
#pragma unroll
        for (int ks = 0; ks < 8; ks++) {
            uint32_t ph[4];
            ph[0] = cvt2h(sacc[2 * ks][0],     sacc[2 * ks][1]);
            ph[1] = cvt2h(sacc[2 * ks][2],     sacc[2 * ks][3]);
            ph[2] = cvt2h(sacc[2 * ks + 1][0], sacc[2 * ks + 1][1]);
            ph[3] = cvt2h(sacc[2 * ks + 1][2], sacc[2 * ks + 1][3]);
#pragma unroll
            for (int np = 0; np < 4; np++) {
                uint32_t vh[4];
                const uint32_t va = sbase + pw * 4 + (uint32_t)(ABUF * 4) +
                    (uint32_t)((ks * 16 + (mat & 1) * 8 + lr8) * 144 + np * 32 + (mat >> 1) * 16);
                ldsm4t(vh, va);
#pragma unroll
                for (int hh = 0; hh < 2; hh++)
                    mma_fp16(oacc[np * 2 + hh], ph, &vh[hh * 2]);
            }
        }

        __syncthreads();
    }

    // epilogue: normalize, write fp16 O [b, s, h*64 + d]
    const int b = bh >> 4, h = bh & 15;
    const float inv0 = 1.f / l0r, inv1 = 1.f / l1r;
#pragma unroll
    for (int nt = 0; nt < 8; nt++) {
        const int col = h * HDIM + nt * 8 + ((lane & 3) << 1);
        *(uint32_t*)(O + ((size_t)(b * SEQ) + qrow0) * EMB + col) =
            cvt2h(oacc[nt][0] * inv0, oacc[nt][1] * inv0);
        *(uint32_t*)(O + ((size_t)(b * SEQ) + qrow0 + 8) * EMB + col) =
            cvt2h(oacc[nt][2] * inv1, oacc[nt][3] * inv1);
    }
}

// ---------------------------------------------------------------------------
extern "C" void kernel_launch(void* const* d_in, const int* in_sizes, int n_in,
                              void* d_out, int out_size)
{
    (void)in_sizes; (void)n_in; (void)out_size;
    const float* x  = (const float*)d_in[0];
    // d_in[1] = mask (causal tril, implied — unused)
    const float* Wq = (const float*)d_in[2];
    const float* bq = (const float*)d_in[3];
    const float* Wk = (const float*)d_in[4];
    const float* bk = (const float*)d_in[5];
    const float* Wv = (const float*)d_in[6];
    const float* bv = (const float*)d_in[7];
    const float* Wo = (const float*)d_in[8];
    const float* bo = (const float*)d_in[9];
    float* out = (float*)d_out;

    __half *xh, *wh, *gq, *gk, *gv, *go;
    cudaGetSymbolAddress((void**)&xh, g_xh);
    cudaGetSymbolAddress((void**)&wh, g_wh);
    cudaGetSymbolAddress((void**)&gq, g_q);
    cudaGetSymbolAddress((void**)&gk, g_k);
    cudaGetSymbolAddress((void**)&gv, g_v);
    cudaGetSymbolAddress((void**)&go, g_o);

    cudaFuncSetAttribute(gemm_tc, cudaFuncAttributeMaxDynamicSharedMemorySize,
                         GEMM_SMEM_B);
    cudaFuncSetAttribute(attn_tc, cudaFuncAttributeMaxDynamicSharedMemorySize,
                         ATT_SMEM);

    // Convert x + all 4 weights to fp16 in ONE launch
    cvt_all<<<(TOT4 + 255) / 256, 256>>>(x, Wq, Wk, Wv, Wo, xh, wh);

    // Q, K, V projections in ONE launch (fp16 in, fp16 out; Q pre-scaled)
    const dim3 qkv_grid(EMB / 128, MTOT / 128, 3);  // (8, 32, 3)
    gemm_tc<<<qkv_grid, 256, GEMM_SMEM_B>>>(
        xh, wh + 0 * WN, wh + 1 * WN, wh + 2 * WN, bq, bk, bv,
        gq, gk, gv, nullptr, 1);

    const dim3 attn_grid(SEQ / QT, BATCH * NHEAD);  // (16, 32)
    attn_tc<<<attn_grid, 256, ATT_SMEM>>>(gq, gk, gv, go);

    // Output projection (fp16 in, fp32 out)
    const dim3 out_grid(EMB / 128, MTOT / 128, 1);
    gemm_tc<<<out_grid, 256, GEMM_SMEM_B>>>(
        go, wh + 3 * WN, wh + 3 * WN, wh + 3 * WN, bo, bo, bo,
        gq, gq, gq, out, 0);
}

// round 17
// speedup vs baseline: 2.4638x; 1.0324x over previous
#include <cuda_runtime.h>
#include <cuda_fp16.h>
#include <math.h>
#include <stddef.h>
#include <stdint.h>

// Problem constants
#define NHEAD 16
#define HDIM  64
#define SEQ   2048
#define BATCH 2
#define EMB   1024
#define MTOT  (BATCH * SEQ)   // 4096
#define WN    (EMB * EMB)

// Scratch (device globals: allocation-free, graph-capturable)
__device__ __half g_xh[MTOT * EMB];
__device__ __half g_wh[4 * WN];
__device__ __half g_q[BATCH * NHEAD * SEQ * HDIM];
__device__ __half g_k[BATCH * NHEAD * SEQ * HDIM];
__device__ __half g_v[BATCH * NHEAD * SEQ * HDIM];
__device__ __half g_o[MTOT * EMB];

// ===========================================================================
// mma.sync helpers
// ===========================================================================
__device__ __forceinline__ void mma_fp16(float* d, const uint32_t* a, const uint32_t* b) {
    asm volatile(
        "mma.sync.aligned.m16n8k16.row.col.f32.f16.f16.f32 "
        "{%0,%1,%2,%3}, {%4,%5,%6,%7}, {%8,%9}, {%0,%1,%2,%3};"
        : "+f"(d[0]), "+f"(d[1]), "+f"(d[2]), "+f"(d[3])
        : "r"(a[0]), "r"(a[1]), "r"(a[2]), "r"(a[3]), "r"(b[0]), "r"(b[1]));
}

__device__ __forceinline__ void ldsm4(uint32_t* r, uint32_t addr) {
    asm volatile("ldmatrix.sync.aligned.m8n8.x4.shared.b16 {%0,%1,%2,%3}, [%4];"
        : "=r"(r[0]), "=r"(r[1]), "=r"(r[2]), "=r"(r[3]) : "r"(addr));
}

__device__ __forceinline__ void ldsm4t(uint32_t* r, uint32_t addr) {
    asm volatile("ldmatrix.sync.aligned.m8n8.x4.trans.shared.b16 {%0,%1,%2,%3}, [%4];"
        : "=r"(r[0]), "=r"(r[1]), "=r"(r[2]), "=r"(r[3]) : "r"(addr));
}

__device__ __forceinline__ uint32_t smem_u32(const void* p) {
    uint32_t a;
    asm("{ .reg .u64 t; cvta.to.shared.u64 t, %1; cvt.u32.u64 %0, t; }"
        : "=r"(a) : "l"(p));
    return a;
}

__device__ __forceinline__ uint32_t cvt2h(float x, float y) {
    __half2 h = __floats2half2_rn(x, y);
    return *(uint32_t*)&h;
}

// ===========================================================================
// Fused fp32 -> fp16 conversion of x + 4 weights (ONE launch).
// ===========================================================================
#define X4   (MTOT * EMB / 4)   // 1048576
#define W4   (WN / 4)           // 262144
#define TOT4 (X4 + 4 * W4)      // 2097152

__global__ __launch_bounds__(256) void cvt_all(
    const float* __restrict__ x,
    const float* __restrict__ Wq, const float* __restrict__ Wk,
    const float* __restrict__ Wv, const float* __restrict__ Wo,
    __half* __restrict__ xh, __half* __restrict__ wh)
{
    const int i = blockIdx.x * blockDim.x + threadIdx.x;
    if (i >= TOT4) return;
    const float* src;
    __half* dst;
    if (i < X4) {
        src = x + (size_t)i * 4;
        dst = xh + (size_t)i * 4;
    } else {
        const int j = i - X4;
        const int seg = j / W4;          // 0..3
        const int off = j - seg * W4;
        const float* Ws = (seg == 0) ? Wq : (seg == 1) ? Wk : (seg == 2) ? Wv : Wo;
        src = Ws + (size_t)off * 4;
        dst = wh + (size_t)seg * WN + (size_t)off * 4;
    }
    const float4 v = *(const float4*)src;
    *(uint2*)dst = make_uint2(cvt2h(v.x, v.y), cvt2h(v.z, v.w));
}

// ===========================================================================
// Tensor-core GEMM, single-pass fp16, GBK=64: 4 MMA groups per chunk,
// barriers halved, STS + LDG prefetch each hidden under 2 MMA groups.
// 256 threads (8 warps 4x2, warp tile 32x64). Row stride 144B (conflict-
// free, 16B-aligned). grid.z selects W/bias/output.
// ===========================================================================
#define GBK 64
#define SROWB 144
#define SROWW (SROWB / 4)          // 36
#define TILE_U32 (128 * SROWW)     // 4608 words (18432 B)
#define BUFW (2 * TILE_U32)        // per-parity words
#define GEMM_SMEM_B (2 * BUFW * 4) // 73728 B
#define NCH (EMB / GBK)            // 16

__global__ __launch_bounds__(256, 1) void gemm_tc(
    const __half* __restrict__ A,
    const __half* __restrict__ W0, const __half* __restrict__ W1,
    const __half* __restrict__ W2,
    const float* __restrict__ bias0, const float* __restrict__ bias1,
    const float* __restrict__ bias2,
    __half* __restrict__ H0, __half* __restrict__ H1, __half* __restrict__ H2,
    float* __restrict__ Fout, int writeQKV)
{
    extern __shared__ uint32_t sh[];

    const int z = blockIdx.z;
    const __half* W = (z == 0) ? W0 : (z == 1) ? W1 : W2;
    const float* bias = (z == 0) ? bias0 : (z == 1) ? bias1 : bias2;
    __half* Hc = (z == 0) ? H0 : (z == 1) ? H1 : H2;

    const int tid = threadIdx.x;
    const int lane = tid & 31;
    const int wid = tid >> 5;          // 0..7
    const int wm = wid & 3;            // m-group (32 rows)
    const int wn = wid >> 2;           // n-group (64 cols)
    const int m0 = blockIdx.y * 128;
    const int n0 = blockIdx.x * 128;

    // staging: 128 rows x 128B per tile = 1024 uint4; 4 per thread per tile
    const int grow = tid >> 3;          // 0..31 (it adds 32)
    const int c16 = tid & 7;            // 16B chunk within 128B row

    const int mat = lane >> 3, lr8 = lane & 7;
    const uint32_t sbase = smem_u32(sh);
    const uint32_t a_off = (uint32_t)((wm * 32 + (mat & 1) * 8 + lr8) * SROWB + (mat >> 1) * 16);
    const uint32_t b_off = (uint32_t)((wn * 64 + (mat >> 1) * 8 + lr8) * SROWB + (mat & 1) * 16);

    float acc[2][8][4];
#pragma unroll
    for (int mf = 0; mf < 2; mf++)
#pragma unroll
        for (int nf = 0; nf < 8; nf++)
#pragma unroll
            for (int e = 0; e < 4; e++) acc[mf][nf][e] = 0.f;

    const __half* Ag = A + (size_t)m0 * EMB;
    const __half* Wg = W + (size_t)n0 * EMB;

    uint4 avr[4], wvr[4];

    // ---- prologue: chunk 0 -> parity 0; prefetch chunk 1 ----
#pragma unroll
    for (int it = 0; it < 4; it++) {
        const int row = grow + it * 32;
        avr[it] = *(const uint4*)(Ag + (size_t)row * EMB + c16 * 8);
        wvr[it] = *(const uint4*)(Wg + (size_t)row * EMB + c16 * 8);
    }
#pragma unroll
    for (int it = 0; it < 4; it++) {
        const int w0 = (grow + it * 32) * SROWW + c16 * 4;
        *(uint4*)(sh + w0) = avr[it];
        *(uint4*)(sh + TILE_U32 + w0) = wvr[it];
    }
#pragma unroll
    for (int it = 0; it < 4; it++) {
        const int row = grow + it * 32;
        avr[it] = *(const uint4*)(Ag + (size_t)row * EMB + GBK + c16 * 8);
        wvr[it] = *(const uint4*)(Wg + (size_t)row * EMB + GBK + c16 * 8);
    }
    __syncthreads();

    for (int kk = 0; kk < NCH; kk++) {
        const uint32_t pofs = (uint32_t)((kk & 1) * BUFW);
        const uint32_t nofs = (uint32_t)(((kk + 1) & 1) * BUFW);

        const uint32_t sA = sbase + pofs * 4 + a_off;
        const uint32_t sB = sbase + pofs * 4 + TILE_U32 * 4 + b_off;

        // ---- MMA groups ks = 0, 1 ----
#pragma unroll
        for (int ks = 0; ks < 2; ks++) {
            const uint32_t kadd = (uint32_t)ks * 32;
            uint32_t ah[2][4], bh[4][4];
#pragma unroll
            for (int mf = 0; mf < 2; mf++)
                ldsm4(ah[mf], sA + mf * 16 * SROWB + kadd);
#pragma unroll
            for (int np = 0; np < 4; np++)
                ldsm4(bh[np], sB + np * 16 * SROWB + kadd);
#pragma unroll
            for (int mf = 0; mf < 2; mf++)
#pragma unroll
                for (int nf = 0; nf < 8; nf++)
                    mma_fp16(acc[mf][nf], ah[mf], &bh[nf >> 1][(nf & 1) * 2]);
        }

        // ---- STS chunk kk+1 (pure copy, hidden under surrounding MMAs) ----
        if (kk + 1 < NCH) {
#pragma unroll
            for (int it = 0; it < 4; it++) {
                const int w0 = (grow + it * 32) * SROWW + c16 * 4;
                *(uint4*)(sh + nofs + w0) = avr[it];
                *(uint4*)(sh + nofs + TILE_U32 + w0) = wvr[it];
            }
        }

        // ---- MMA groups ks = 2, 3 ----
#pragma unroll
        for (int ks = 2; ks < 4; ks++) {
            const uint32_t kadd = (uint32_t)ks * 32;
            uint32_t ah[2][4], bh[4][4];
#pragma unroll
            for (int mf = 0; mf < 2; mf++)
                ldsm4(ah[mf], sA + mf * 16 * SROWB + kadd);
#pragma unroll
            for (int np = 0; np < 4; np++)
                ldsm4(bh[np], sB + np * 16 * SROWB + kadd);
#pragma unroll
            for (int mf = 0; mf < 2; mf++)
#pragma unroll
                for (int nf = 0; nf < 8; nf++)
                    mma_fp16(acc[mf][nf], ah[mf], &bh[nf >> 1][(nf & 1) * 2]);
        }

        // ---- prefetch chunk kk+2 ----
        if (kk + 2 < NCH) {
            const int kcol = (kk + 2) * GBK + c16 * 8;
#pragma unroll
            for (int it = 0; it < 4; it++) {
                const int row = grow + it * 32;
                avr[it] = *(const uint4*)(Ag + (size_t)row * EMB + kcol);
                wvr[it] = *(const uint4*)(Wg + (size_t)row * EMB + kcol);
            }
        }

        __syncthreads();   // single barrier per (64-wide) chunk
    }

    // Epilogue
    const float scl = (writeQKV && z == 0) ? 0.125f : 1.f;
#pragma unroll
    for (int mf = 0; mf < 2; mf++) {
#pragma unroll
        for (int half = 0; half < 2; half++) {
            const int m = m0 + wm * 32 + mf * 16 + (lane >> 2) + half * 8;
            const int b = m >> 11;
            const int s = m & (SEQ - 1);
#pragma unroll
            for (int nf = 0; nf < 8; nf++) {
                const int n = n0 + wn * 64 + nf * 8 + ((lane & 3) << 1);
                const float vx = (acc[mf][nf][half * 2 + 0] + bias[n]) * scl;
                const float vy = (acc[mf][nf][half * 2 + 1] + bias[n + 1]) * scl;
                if (writeQKV) {
                    const int h = n >> 6;
                    const int d = n & 63;
                    *(uint32_t*)(Hc + (((size_t)(b * NHEAD + h)) * SEQ + s) * HDIM + d)
                        = cvt2h(vx, vy);
                } else {
                    *(float2*)(Fout + (size_t)m * EMB + n) = make_float2(vx, vy);
                }
            }
        }
    }
}

// ===========================================================================
// Tensor-core causal flash attention, fp16 I/O, KT=128, double-buffered K/V
// (round-16 version, unchanged — passing).
// ===========================================================================
#define QT 128
#define KT 128
#define AROWW 36            // u32 words per smem row (144 B)
#define ABUF (128 * AROWW)  // 4608 words per region
#define ATT_SMEM (4 * ABUF * 4)   // 73728 B

__global__ __launch_bounds__(256, 1) void attn_tc(
    const __half* __restrict__ Q, const __half* __restrict__ K,
    const __half* __restrict__ V, __half* __restrict__ O)
{
    extern __shared__ uint32_t sm[];
    const int tid = threadIdx.x;
    const int lane = tid & 31;
    const int wid = tid >> 5;
    const int lr8 = lane & 7;
    const int mat = lane >> 3;
    const int qb = blockIdx.x;
    const int bh = blockIdx.y;

    const uint32_t sbase = smem_u32(sm);

    const __half* Qg = Q + ((size_t)bh * SEQ + (size_t)qb * QT) * HDIM;
    const __half* Kg = K + (size_t)bh * SEQ * HDIM;
    const __half* Vg = V + (size_t)bh * SEQ * HDIM;

    const int r16 = tid >> 4;             // 0..15
    const int hvo = (tid & 15) << 2;      // half offset within row
    const int kwo = (tid & 15) << 1;      // u32 word offset in smem row

#pragma unroll
    for (int u = 0; u < 8; u++) {
        const int row = r16 + u * 16;
        const uint2 qv = *(const uint2*)(Qg + (size_t)row * HDIM + hvo);
        *(uint2*)(sm + row * AROWW + kwo) = qv;
    }
    __syncthreads();

    uint32_t qh[4][4];
    {
        const uint32_t qa = sbase +
            (uint32_t)((wid * 16 + (mat & 1) * 8 + lr8) * 144 + (mat >> 1) * 16);
#pragma unroll
        for (int ks = 0; ks < 4; ks++)
            ldsm4(qh[ks], qa + ks * 32);
    }

    float oacc[8][4];
#pragma unroll
    for (int nf = 0; nf < 8; nf++)
#pragma unroll
        for (int e = 0; e < 4; e++) oacc[nf][e] = 0.f;
    float m0r = -INFINITY, m1r = -INFINITY, l0r = 0.f, l1r = 0.f;

    const int jbmax = qb;
    const int qrow0 = qb * QT + wid * 16 + (lane >> 2);

    uint2 kreg[8], vreg[8];
#pragma unroll
    for (int u = 0; u < 8; u++) {
        kreg[u] = *(const uint2*)(Kg + (size_t)(r16 + u * 16) * HDIM + hvo);
        vreg[u] = *(const uint2*)(Vg + (size_t)(r16 + u * 16) * HDIM + hvo);
    }
    __syncthreads();
#pragma unroll
    for (int u = 0; u < 8; u++) {
        const int w = (r16 + u * 16) * AROWW + kwo;
        *(uint2*)(sm + w) = kreg[u];
        *(uint2*)(sm + ABUF + w) = vreg[u];
    }
    if (jbmax >= 1) {
        const __half* Kt = Kg + (size_t)KT * HDIM;
        const __half* Vt = Vg + (size_t)KT * HDIM;
#pragma unroll
        for (int u = 0; u < 8; u++) {
            kreg[u] = *(const uint2*)(Kt + (size_t)(r16 + u * 16) * HDIM + hvo);
            vreg[u] = *(const uint2*)(Vt + (size_t)(r16 + u * 16) * HDIM + hvo);
        }
    }
    __syncthreads();

    for (int jb = 0; jb <= jbmax; jb++) {
        const uint32_t pw = (uint32_t)((jb & 1) * 2 * ABUF);
        const uint32_t nw = (uint32_t)(((jb + 1) & 1) * 2 * ABUF);

        if (jb < jbmax) {
#pragma unroll
            for (int u = 0; u < 8; u++) {
                const int w = (r16 + u * 16) * AROWW + kwo;
                *(uint2*)(sm + nw + w) = kreg[u];
                *(uint2*)(sm + nw + ABUF + w) = vreg[u];
            }
        }
        if (jb + 2 <= jbmax) {
            const __half* Kt = Kg + (size_t)(jb + 2) * KT * HDIM;
            const __half* Vt = Vg + (size_t)(jb + 2) * KT * HDIM;
#pragma unroll
            for (int u = 0; u < 8; u++) {
                kreg[u] = *(const uint2*)(Kt + (size_t)(r16 + u * 16) * HDIM + hvo);
                vreg[u] = *(const uint2*)(Vt + (size_t)(r16 + u * 16) * HDIM + hvo);
            }
        }

        float sacc[16][4];
#pragma unroll
        for (int nf = 0; nf < 16; nf++)
#pragma unroll
            for (int e = 0; e < 4; e++) sacc[nf][e] = 0.f;

#pragma unroll
        for (int ks = 0; ks < 4; ks++) {
#pragma unroll
            for (int np = 0; np < 8; np++) {
                uint32_t kh[4];
                const uint32_t ka = sbase + pw * 4 +
                    (uint32_t)((np * 16 + (mat >> 1) * 8 + lr8) * 144 + ks * 32 + (mat & 1) * 16);
                ldsm4(kh, ka);
#pragma unroll
                for (int hh = 0; hh < 2; hh++)
                    mma_fp16(sacc[np * 2 + hh], qh[ks], &kh[hh * 2]);
            }
        }

        if (jb == jbmax) {
#pragma unroll
            for (int nt = 0; nt < 16; nt++) {
                const int c = jb * KT + nt * 8 + ((lane & 3) << 1);
                if (c     > qrow0)     sacc[nt][0] = -INFINITY;
                if (c + 1 > qrow0)     sacc[nt][1] = -INFINITY;
                if (c     > qrow0 + 8) sacc[nt][2] = -INFINITY;
                if (c + 1 > qrow0 + 8) sacc[nt][3] = -INFINITY;
            }
        }

        float mx0 = sacc[0][0], mx1 = sacc[0][2];
#pragma unroll
        for (int nt = 0; nt < 16; nt++) {
            mx0 = fmaxf(mx0, fmaxf(sacc[nt][0], sacc[nt][1]));
            mx1 = fmaxf(mx1, fmaxf(sacc[nt][2], sacc[nt][3]));
        }
        mx0 = fmaxf(mx0, __shfl_xor_sync(~0u, mx0, 1));
        mx0 = fmaxf(mx0, __shfl_xor_sync(~0u, mx0, 2));
        mx1 = fmaxf(mx1, __shfl_xor_sync(~0u, mx1, 1));
        mx1 = fmaxf(mx1, __shfl_xor_sync(~0u, mx1, 2));
        const float mn0 = fmaxf(m0r, mx0), mn1 = fmaxf(m1r, mx1);
        const float cr0 = __expf(m0r - mn0), cr1 = __expf(m1r - mn1);
        m0r = mn0; m1r = mn1;
        float rs0 = 0.f, rs1 = 0.f;
#pragma unroll
        for (int nt = 0; nt < 16; nt++) {
            sacc[nt][0] = __expf(sacc[nt][0] - mn0);
            sacc[nt][1] = __expf(sacc[nt][1] - mn0);
            sacc[nt][2] = __expf(sacc[nt][2] - mn1);
            sacc[nt][3] = __expf(sacc[nt][3] - mn1);
            rs0 += sacc[nt][0] + sacc[nt][1];
            rs1 += sacc[nt][2] + sacc[nt][3];
        }
        rs0 += __shfl_xor_sync(~0u, rs0, 1);
        rs0 += __shfl_xor_sync(~0u, rs0, 2);
        rs1 += __shfl_xor_sync(~0u, rs1, 1);
        rs1 += __shfl_xor_sync(~0u, rs1, 2);
        l0r = l0r * cr0 + rs0;
        l1r = l1r * cr1 + rs1;
#pragma unroll
        for (int nf = 0; nf < 8; nf++) {
            oacc[nf][0] *= cr0; oacc[nf][1] *= cr0;
            oacc[nf][2] *= cr1; oacc[nf][3] *= cr1;
        }

#pragma unroll
        for (int ks = 0; ks < 8; ks++) {
            uint32_t ph[4];
            ph[0] = cvt2h(sacc[2 * ks][0],     sacc[2 * ks][1]);
            ph[1] = cvt2h(sacc[2 * ks][2],     sacc[2 * ks][3]);
            ph[2] = cvt2h(sacc[2 * ks + 1][0], sacc[2 * ks + 1][1]);
            ph[3] = cvt2h(sacc[2 * ks + 1][2], sacc[2 * ks + 1][3]);
#pragma unroll
            for (int np = 0; np < 4; np++) {
                uint32_t vh[4];
                const uint32_t va = sbase + pw * 4 + (uint32_t)(ABUF * 4) +
                    (uint32_t)((ks * 16 + (mat & 1) * 8 + lr8) * 144 + np * 32 + (mat >> 1) * 16);
                ldsm4t(vh, va);
#pragma unroll
                for (int hh = 0; hh < 2; hh++)
                    mma_fp16(oacc[np * 2 + hh], ph, &vh[hh * 2]);
            }
        }

        __syncthreads();
    }

    const int b = bh >> 4, h = bh & 15;
    const float inv0 = 1.f / l0r, inv1 = 1.f / l1r;
#pragma unroll
    for (int nt = 0; nt < 8; nt++) {
        const int col = h * HDIM + nt * 8 + ((lane & 3) << 1);
        *(uint32_t*)(O + ((size_t)(b * SEQ) + qrow0) * EMB + col) =
            cvt2h(oacc[nt][0] * inv0, oacc[nt][1] * inv0);
        *(uint32_t*)(O + ((size_t)(b * SEQ) + qrow0 + 8) * EMB + col) =
            cvt2h(oacc[nt][2] * inv1, oacc[nt][3] * inv1);
    }
}

// ---------------------------------------------------------------------------
extern "C" void kernel_launch(void* const* d_in, const int* in_sizes, int n_in,
                              void* d_out, int out_size)
{
    (void)in_sizes; (void)n_in; (void)out_size;
    const float* x  = (const float*)d_in[0];
    // d_in[1] = mask (causal tril, implied — unused)
    const float* Wq = (const float*)d_in[2];
    const float* bq = (const float*)d_in[3];
    const float* Wk = (const float*)d_in[4];
    const float* bk = (const float*)d_in[5];
    const float* Wv = (const float*)d_in[6];
    const float* bv = (const float*)d_in[7];
    const float* Wo = (const float*)d_in[8];
    const float* bo = (const float*)d_in[9];
    float* out = (float*)d_out;

    __half *xh, *wh, *gq, *gk, *gv, *go;
    cudaGetSymbolAddress((void**)&xh, g_xh);
    cudaGetSymbolAddress((void**)&wh, g_wh);
    cudaGetSymbolAddress((void**)&gq, g_q);
    cudaGetSymbolAddress((void**)&gk, g_k);
    cudaGetSymbolAddress((void**)&gv, g_v);
    cudaGetSymbolAddress((void**)&go, g_o);

    cudaFuncSetAttribute(gemm_tc, cudaFuncAttributeMaxDynamicSharedMemorySize,
                         GEMM_SMEM_B);
    cudaFuncSetAttribute(attn_tc, cudaFuncAttributeMaxDynamicSharedMemorySize,
                         ATT_SMEM);

    // Convert x + all 4 weights to fp16 in ONE launch
    cvt_all<<<(TOT4 + 255) / 256, 256>>>(x, Wq, Wk, Wv, Wo, xh, wh);

    // Q, K, V projections in ONE launch (fp16 in, fp16 out; Q pre-scaled)
    const dim3 qkv_grid(EMB / 128, MTOT / 128, 3);  // (8, 32, 3)
    gemm_tc<<<qkv_grid, 256, GEMM_SMEM_B>>>(
        xh, wh + 0 * WN, wh + 1 * WN, wh + 2 * WN, bq, bk, bv,
        gq, gk, gv, nullptr, 1);

    const dim3 attn_grid(SEQ / QT, BATCH * NHEAD);  // (16, 32)
    attn_tc<<<attn_grid, 256, ATT_SMEM>>>(gq, gk, gv, go);

    // Output projection (fp16 in, fp32 out)
    const dim3 out_grid(EMB / 128, MTOT / 128, 1);
    gemm_tc<<<out_grid, 256, GEMM_SMEM_B>>>(
        go, wh + 3 * WN, wh + 3 * WN, wh + 3 * WN, bo, bo, bo,
        gq, gq, gq, out, 0);
}